// round 1
// baseline (speedup 1.0000x reference)
#include <cuda_runtime.h>
#include <math.h>

#define H 128
#define F 64
#define NE_MAX 50000

// scratch (allocation-free rule: device globals)
__device__ float g_e  [NE_MAX * H];
__device__ float g_e2 [NE_MAX * H];
__device__ float g_agg[NE_MAX * H];
__device__ int   g_deg[NE_MAX];

__global__ void deg_kernel(const int* __restrict__ dst, int na, int* __restrict__ deg) {
    int i = blockIdx.x * blockDim.x + threadIdx.x;
    if (i < na) atomicAdd(&deg[dst[i]], 1);
}

// MODE: 0=encoder  1=msg(atomic segment-add)  2=self-msg(isolated only)
//       3=update   4=predictor(3-layer + sigmoid)
template <int MODE, int K1>
__global__ __launch_bounds__(256)
void mlp2_kernel(const float* __restrict__ A0,   // gather base, first half of concat
                 const float* __restrict__ B0,   // gather base, second half of concat
                 const float* __restrict__ W1, const float* __restrict__ b1,
                 const float* __restrict__ W2, const float* __restrict__ b2,
                 const float* __restrict__ W3, const float* __restrict__ b3,
                 const int* __restrict__ idx0, const int* __restrict__ idx1,
                 const int* __restrict__ deg,
                 float* __restrict__ outp,
                 int nrows, int logit_off)
{
    __shared__ float hid[64 * 132];   // hidden activations (also MODE1 output staging)
    __shared__ float ws [16 * 132];   // weight tile (also MODE4 reduction buffer)
    __shared__ float As [64 * 17];    // A tile (rows x k)
    __shared__ int   soff0[64];
    __shared__ int   soff1[64];
    __shared__ float sscale[64];
    __shared__ int   sdst[64];
    __shared__ int   sflag;

    const int tid  = threadIdx.x;
    const int row0 = blockIdx.x * 64;

    if (tid == 0) sflag = 0;
    __syncthreads();

    if (tid < 64) {
        int r = row0 + tid;
        bool valid = r < nrows;
        int rr = valid ? r : 0;
        float sc = 1.f;
        if (MODE == 0) {
            soff0[tid] = rr * F; soff1[tid] = 0;
        } else if (MODE == 1) {
            int i0 = idx0[rr], i1 = idx1[rr];
            soff0[tid] = i0 * H; soff1[tid] = i1 * H;
            sdst[tid] = i0;
        } else if (MODE == 2) {
            soff0[tid] = rr * H; soff1[tid] = rr * H;
            if (valid && deg[r] == 0) sflag = 1;
        } else if (MODE == 3) {
            soff0[tid] = rr * H; soff1[tid] = rr * H;
            int d = deg[rr];
            sc = 1.f / (d > 1 ? (float)d : 1.f);
        } else { // MODE 4
            int i0 = idx0[rr], i1 = idx1[rr];
            soff0[tid] = i0 * H; soff1[tid] = i1 * H;
        }
        sscale[tid] = sc;
    }
    __syncthreads();
    if (MODE == 2 && !sflag) return;   // no isolated nodes in this block (common case)

    const int tc = tid & 15;   // 16 col groups * 8 cols
    const int tr = tid >> 4;   // 16 row groups * 4 rows

    float acc[4][8];
#pragma unroll
    for (int i = 0; i < 4; i++)
#pragma unroll
        for (int j = 0; j < 8; j++) acc[i][j] = 0.f;

    // ---------------- stage 1: A[64 x K1] @ W1[K1 x 128] ----------------
    for (int k0 = 0; k0 < K1; k0 += 16) {
        {   // W tile: 16 x 128
            int kk = tid >> 5;
            int c  = (tid & 31) * 4;
            *(float4*)&ws[kk * 132 + c]       = *(const float4*)&W1[(k0 + kk) * H + c];
            *(float4*)&ws[(kk + 8) * 132 + c] = *(const float4*)&W1[(k0 + kk + 8) * H + c];
        }
        // A tile: 64 rows x 16 k (gathered)
#pragma unroll
        for (int p = 0; p < 4; p++) {
            int r  = p * 16 + (tid >> 4);
            int kk = tid & 15;
            int k  = k0 + kk;
            float v;
            if (K1 == 64 || k < H) v = __ldg(&A0[soff0[r] + k]);
            else                   v = __ldg(&B0[soff1[r] + (k - H)]) * sscale[r];
            As[r * 17 + kk] = v;
        }
        __syncthreads();
#pragma unroll
        for (int kk = 0; kk < 16; kk++) {
            float a[4];
#pragma unroll
            for (int i = 0; i < 4; i++) a[i] = As[(tr * 4 + i) * 17 + kk];
            float4 w0 = *(float4*)&ws[kk * 132 + tc * 8];
            float4 w1 = *(float4*)&ws[kk * 132 + tc * 8 + 4];
#pragma unroll
            for (int i = 0; i < 4; i++) {
                acc[i][0] += a[i] * w0.x; acc[i][1] += a[i] * w0.y;
                acc[i][2] += a[i] * w0.z; acc[i][3] += a[i] * w0.w;
                acc[i][4] += a[i] * w1.x; acc[i][5] += a[i] * w1.y;
                acc[i][6] += a[i] * w1.z; acc[i][7] += a[i] * w1.w;
            }
        }
        __syncthreads();
    }

    // bias + ReLU -> hidden
#pragma unroll
    for (int j = 0; j < 8; j++) {
        float bb = __ldg(&b1[tc * 8 + j]);
#pragma unroll
        for (int i = 0; i < 4; i++) {
            float v = acc[i][j] + bb;
            hid[(tr * 4 + i) * 132 + tc * 8 + j] = v > 0.f ? v : 0.f;
        }
    }
    __syncthreads();

    // ---------------- stage 2: hidden[64 x 128] @ W2[128 x 128] ----------------
#pragma unroll
    for (int i = 0; i < 4; i++)
#pragma unroll
        for (int j = 0; j < 8; j++) acc[i][j] = 0.f;

    for (int k0 = 0; k0 < H; k0 += 16) {
        {
            int kk = tid >> 5;
            int c  = (tid & 31) * 4;
            *(float4*)&ws[kk * 132 + c]       = *(const float4*)&W2[(k0 + kk) * H + c];
            *(float4*)&ws[(kk + 8) * 132 + c] = *(const float4*)&W2[(k0 + kk + 8) * H + c];
        }
        __syncthreads();
#pragma unroll
        for (int kk = 0; kk < 16; kk++) {
            int k = k0 + kk;
            float a[4];
#pragma unroll
            for (int i = 0; i < 4; i++) a[i] = hid[(tr * 4 + i) * 132 + k];
            float4 w0 = *(float4*)&ws[kk * 132 + tc * 8];
            float4 w1 = *(float4*)&ws[kk * 132 + tc * 8 + 4];
#pragma unroll
            for (int i = 0; i < 4; i++) {
                acc[i][0] += a[i] * w0.x; acc[i][1] += a[i] * w0.y;
                acc[i][2] += a[i] * w0.z; acc[i][3] += a[i] * w0.w;
                acc[i][4] += a[i] * w1.x; acc[i][5] += a[i] * w1.y;
                acc[i][6] += a[i] * w1.z; acc[i][7] += a[i] * w1.w;
            }
        }
        __syncthreads();
    }

    // ---------------- epilogue ----------------
    if (MODE == 4) {
        float p[4] = {0.f, 0.f, 0.f, 0.f};
#pragma unroll
        for (int j = 0; j < 8; j++) {
            float bb = __ldg(&b2[tc * 8 + j]);
            float w3 = __ldg(&W3[tc * 8 + j]);
#pragma unroll
            for (int i = 0; i < 4; i++) {
                float v = acc[i][j] + bb;
                v = v > 0.f ? v : 0.f;
                p[i] += v * w3;
            }
        }
        // reduce 16 col-groups per row (reuse ws)
#pragma unroll
        for (int i = 0; i < 4; i++) ws[(tr * 4 + i) * 16 + tc] = p[i];
        __syncthreads();
        if (tid < 64) {
            int r = row0 + tid;
            if (r < nrows) {
                float s = __ldg(&b3[0]);
#pragma unroll
                for (int t = 0; t < 16; t++) s += ws[tid * 16 + t];
                float prob = 1.f / (1.f + expf(-s));
                outp[r] = prob;
                if (logit_off > 0) outp[logit_off + r] = s;
            }
        }
        return;
    }

#pragma unroll
    for (int j = 0; j < 8; j++) {
        float bb = __ldg(&b2[tc * 8 + j]);
#pragma unroll
        for (int i = 0; i < 4; i++) {
            int r = row0 + tr * 4 + i;
            float v = acc[i][j] + bb;
            if (MODE == 3) v = v > 0.f ? v : 0.f;
            if (MODE == 0 || MODE == 3) {
                if (r < nrows) outp[(size_t)r * H + tc * 8 + j] = v;
            } else if (MODE == 2) {
                if (r < nrows && deg[r] == 0) outp[(size_t)r * H + tc * 8 + j] = v;
            } else { // MODE 1: stage to smem for segment reduce
                hid[(tr * 4 + i) * 132 + tc * 8 + j] = v;
            }
        }
    }

    if (MODE == 1) {
        __syncthreads();
        // adj_dst is sorted globally -> runs of equal dst inside the block.
        // Two teams of 128 threads, each owns 32 rows x 128 cols.
        int team = tid >> 7;
        int col  = tid & 127;
        int rbeg = team * 32, rend = rbeg + 32;
        float sum = 0.f;
        int cur = sdst[rbeg];
        for (int r = rbeg; r < rend; r++) {
            sum += hid[r * 132 + col];
            int nxt = (r + 1 < rend) ? sdst[r + 1] : -1;
            if (nxt != cur) {
                atomicAdd(&outp[(size_t)cur * H + col], sum);
                sum = 0.f;
                cur = nxt;
            }
        }
    }
}

extern "C" void kernel_launch(void* const* d_in, const int* in_sizes, int n_in,
                              void* d_out, int out_size) {
    const float* feat    = (const float*)d_in[0];
    const int*   adj_dst = (const int*)  d_in[1];
    const int*   adj_src = (const int*)  d_in[2];
    const int*   cand_i  = (const int*)  d_in[3];
    const int*   cand_j  = (const int*)  d_in[4];
    const float* enc_W1 = (const float*)d_in[5];
    const float* enc_b1 = (const float*)d_in[6];
    const float* enc_W2 = (const float*)d_in[7];
    const float* enc_b2 = (const float*)d_in[8];
    const float* msg_W1 = (const float*)d_in[9];
    const float* msg_b1 = (const float*)d_in[10];
    const float* msg_W2 = (const float*)d_in[11];
    const float* msg_b2 = (const float*)d_in[12];
    const float* upd_W1 = (const float*)d_in[13];
    const float* upd_b1 = (const float*)d_in[14];
    const float* upd_W2 = (const float*)d_in[15];
    const float* upd_b2 = (const float*)d_in[16];
    const float* pred_W1 = (const float*)d_in[17];
    const float* pred_b1 = (const float*)d_in[18];
    const float* pred_W2 = (const float*)d_in[19];
    const float* pred_b2 = (const float*)d_in[20];
    const float* pred_W3 = (const float*)d_in[21];
    const float* pred_b3 = (const float*)d_in[22];

    int NE = in_sizes[0] / F;
    int NA = in_sizes[1];
    int NC = in_sizes[3];
    if (NE > NE_MAX) NE = NE_MAX;

    float *e, *e2, *agg;
    int* deg;
    cudaGetSymbolAddress((void**)&e,   g_e);
    cudaGetSymbolAddress((void**)&e2,  g_e2);
    cudaGetSymbolAddress((void**)&agg, g_agg);
    cudaGetSymbolAddress((void**)&deg, g_deg);

    // degrees
    cudaMemsetAsync(deg, 0, (size_t)NE * sizeof(int));
    deg_kernel<<<(NA + 255) / 256, 256>>>(adj_dst, NA, deg);

    // encoder: feat -> e
    int gNE = (NE + 63) / 64;
    mlp2_kernel<0, 64><<<gNE, 256>>>(feat, feat, enc_W1, enc_b1, enc_W2, enc_b2,
                                     nullptr, nullptr, nullptr, nullptr, deg, e, NE, 0);

    float* cur = e;
    float* nxt = e2;
    int gNA = (NA + 63) / 64;
    for (int l = 0; l < 3; l++) {
        const float* mW1 = msg_W1 + (size_t)l * 2 * H * H;
        const float* mb1 = msg_b1 + (size_t)l * H;
        const float* mW2 = msg_W2 + (size_t)l * H * H;
        const float* mb2 = msg_b2 + (size_t)l * H;
        const float* uW1 = upd_W1 + (size_t)l * 2 * H * H;
        const float* ub1 = upd_b1 + (size_t)l * H;
        const float* uW2 = upd_W2 + (size_t)l * H * H;
        const float* ub2 = upd_b2 + (size_t)l * H;

        cudaMemsetAsync(agg, 0, (size_t)NE * H * sizeof(float));
        // per-pair messages, segment-summed into agg
        mlp2_kernel<1, 256><<<gNA, 256>>>(cur, cur, mW1, mb1, mW2, mb2,
                                          nullptr, nullptr, adj_dst, adj_src, deg, agg, NA, 0);
        // self message for isolated nodes (deg==0): written straight into agg
        mlp2_kernel<2, 256><<<gNE, 256>>>(cur, cur, mW1, mb1, mW2, mb2,
                                          nullptr, nullptr, nullptr, nullptr, deg, agg, NE, 0);
        // update: concat(e, agg*inv_deg) -> MLP -> ReLU -> nxt
        mlp2_kernel<3, 256><<<gNE, 256>>>(cur, agg, uW1, ub1, uW2, ub2,
                                          nullptr, nullptr, nullptr, nullptr, deg, nxt, NE, 0);
        float* t = cur; cur = nxt; nxt = t;
    }

    // predictor
    int gNC = (NC + 63) / 64;
    int logit_off = (out_size >= 2 * NC) ? NC : -1;
    mlp2_kernel<4, 256><<<gNC, 256>>>(cur, cur, pred_W1, pred_b1, pred_W2, pred_b2,
                                      pred_W3, pred_b3, cand_i, cand_j, deg,
                                      (float*)d_out, NC, logit_off);
}

// round 2
// speedup vs baseline: 4.2833x; 4.2833x over previous
#include <cuda_runtime.h>
#include <math.h>

#define H 128
#define F 64
#define NE_MAX 50000

// scratch (allocation-free rule: device globals)
__device__ float g_e  [NE_MAX * H];
__device__ float g_e2 [NE_MAX * H];
__device__ float g_agg[NE_MAX * H];
__device__ int   g_deg[NE_MAX];

__global__ void deg_kernel(const int* __restrict__ dst, int na, int* __restrict__ deg) {
    int i = blockIdx.x * blockDim.x + threadIdx.x;
    if (i < na) atomicAdd(&deg[dst[i]], 1);
}

__device__ __forceinline__ unsigned f2tf(float f) {
    unsigned u;
    asm("cvt.rna.tf32.f32 %0, %1;" : "=r"(u) : "f"(f));
    return u;
}
__device__ __forceinline__ float f2tf_f(float f) { return __uint_as_float(f2tf(f)); }

__device__ __forceinline__ void mma_tf32(float c[4],
                                         unsigned a0, unsigned a1, unsigned a2, unsigned a3,
                                         unsigned b0, unsigned b1) {
    asm volatile(
        "mma.sync.aligned.m16n8k8.row.col.f32.tf32.tf32.f32 "
        "{%0,%1,%2,%3}, {%4,%5,%6,%7}, {%8,%9}, {%0,%1,%2,%3};"
        : "+f"(c[0]), "+f"(c[1]), "+f"(c[2]), "+f"(c[3])
        : "r"(a0), "r"(a1), "r"(a2), "r"(a3), "r"(b0), "r"(b1));
}

// smem layout (dynamic):
//   Ws   : 32*136 floats   (weight k-tile, stride 136 -> conflict-free B frags)
//   hid  : 128*132 floats  (hidden acts; first part aliased as As with stride 36)
//   spred: 128 floats
//   soff0/soff1/sdst: 128 ints each; sscale: 128 floats
#define WS_ELEMS   (32 * 136)
#define HID_ELEMS  (128 * 132)
#define SMEM_FLOATS (WS_ELEMS + HID_ELEMS + 128 + 128 + 128 + 128 + 128)
#define SMEM_BYTES  (SMEM_FLOATS * 4)

// MODE: 0=encoder  1=msg(atomic segment-add)  2=self-msg(isolated only)
//       3=update   4=predictor(3-layer + sigmoid)
template <int MODE, int K1>
__global__ __launch_bounds__(256)
void mlp2_tc(const float* __restrict__ A0, const float* __restrict__ B0,
             const float* __restrict__ W1, const float* __restrict__ b1,
             const float* __restrict__ W2, const float* __restrict__ b2,
             const float* __restrict__ W3, const float* __restrict__ b3,
             const int* __restrict__ idx0, const int* __restrict__ idx1,
             const int* __restrict__ deg,
             float* __restrict__ outp,
             int nrows, int logit_off)
{
    extern __shared__ float sm[];
    float* Ws     = sm;                      // [32][136]
    float* hid    = sm + WS_ELEMS;           // [128][132]
    float* As     = hid;                     // alias, [128][36]
    float* spred  = hid + HID_ELEMS;         // [128]
    int*   soff0  = (int*)(spred + 128);
    int*   soff1  = soff0 + 128;
    int*   sdst   = soff1 + 128;
    float* sscale = (float*)(sdst + 128);

    const int tid  = threadIdx.x;
    const int lane = tid & 31;
    const int w    = tid >> 5;
    const int wm   = (w & 1) * 64;   // warp M base (2 M-warps)
    const int wn   = (w >> 1) * 32;  // warp N base (4 N-warps)
    const int row0 = blockIdx.x * 128;

    bool iso = false;
    if (tid < 128) {
        int r = row0 + tid;
        bool valid = r < nrows;
        int rr = valid ? r : 0;
        float sc = 1.f;
        if (MODE == 0) {
            soff0[tid] = rr * F; soff1[tid] = 0;
        } else if (MODE == 1) {
            int i0 = idx0[rr], i1 = idx1[rr];
            soff0[tid] = i0 * H; soff1[tid] = i1 * H;
            sdst[tid] = valid ? i0 : -1;
        } else if (MODE == 2) {
            soff0[tid] = rr * H; soff1[tid] = rr * H;
            iso = valid && (deg[r] == 0);
            sdst[tid] = iso ? 1 : 0;
        } else if (MODE == 3) {
            soff0[tid] = rr * H; soff1[tid] = rr * H;
            int d = deg[rr];
            sc = 1.f / (d > 1 ? (float)d : 1.f);
        } else {
            int i0 = idx0[rr], i1 = idx1[rr];
            soff0[tid] = i0 * H; soff1[tid] = i1 * H;
        }
        sscale[tid] = sc;
        if (MODE == 4) spred[tid] = 0.f;
    }
    int any = __syncthreads_or((MODE == 2) ? (int)iso : 1);
    if (MODE == 2 && !any) return;

    float acc[4][4][4];
#pragma unroll
    for (int mf = 0; mf < 4; mf++)
#pragma unroll
        for (int nf = 0; nf < 4; nf++)
#pragma unroll
            for (int q = 0; q < 4; q++) acc[mf][nf][q] = 0.f;

    // ================= stage 1: A[128 x K1] @ W1[K1 x 128] =================
    for (int k0 = 0; k0 < K1; k0 += 32) {
        // W tile 32x128
#pragma unroll
        for (int q = 0; q < 4; q++) {
            int i  = q * 256 + tid;
            int wr = i >> 5;
            int wc = (i & 31) * 4;
            float4 v = *(const float4*)&W1[(k0 + wr) * H + wc];
            float4 o;
            o.x = f2tf_f(v.x); o.y = f2tf_f(v.y); o.z = f2tf_f(v.z); o.w = f2tf_f(v.w);
            *(float4*)&Ws[wr * 136 + wc] = o;
        }
        // A tile 128x32 (gathered rows)
#pragma unroll
        for (int q = 0; q < 4; q++) {
            int i  = q * 256 + tid;
            int r  = i >> 3;
            int cg = (i & 7) * 4;
            float4 v;
            if (K1 == 64 || k0 < H) {
                v = *(const float4*)&A0[soff0[r] + k0 + cg];
            } else {
                v = *(const float4*)&B0[soff1[r] + (k0 - H) + cg];
                float sc = sscale[r];
                v.x *= sc; v.y *= sc; v.z *= sc; v.w *= sc;
            }
            float4 o;
            o.x = f2tf_f(v.x); o.y = f2tf_f(v.y); o.z = f2tf_f(v.z); o.w = f2tf_f(v.w);
            *(float4*)&As[r * 36 + cg] = o;
        }
        __syncthreads();
#pragma unroll
        for (int kk = 0; kk < 4; kk++) {
            int k = kk * 8;
            unsigned a[4][4], b[4][2];
#pragma unroll
            for (int mf = 0; mf < 4; mf++) {
                int ar = wm + mf * 16 + (lane >> 2);
                int ak = k + (lane & 3);
                a[mf][0] = __float_as_uint(As[ar * 36 + ak]);
                a[mf][1] = __float_as_uint(As[(ar + 8) * 36 + ak]);
                a[mf][2] = __float_as_uint(As[ar * 36 + ak + 4]);
                a[mf][3] = __float_as_uint(As[(ar + 8) * 36 + ak + 4]);
            }
#pragma unroll
            for (int nf = 0; nf < 4; nf++) {
                int bc = wn + nf * 8 + (lane >> 2);
                b[nf][0] = __float_as_uint(Ws[(k + (lane & 3)) * 136 + bc]);
                b[nf][1] = __float_as_uint(Ws[(k + 4 + (lane & 3)) * 136 + bc]);
            }
#pragma unroll
            for (int mf = 0; mf < 4; mf++)
#pragma unroll
                for (int nf = 0; nf < 4; nf++)
                    mma_tf32(acc[mf][nf], a[mf][0], a[mf][1], a[mf][2], a[mf][3],
                             b[nf][0], b[nf][1]);
        }
        __syncthreads();
    }

    // bias + ReLU -> hid (tf32-rounded, feeds stage-2 mma)
#pragma unroll
    for (int mf = 0; mf < 4; mf++)
#pragma unroll
        for (int nf = 0; nf < 4; nf++) {
            int row = wm + mf * 16 + (lane >> 2);
            int col = wn + nf * 8 + 2 * (lane & 3);
            float bb0 = __ldg(&b1[col]), bb1 = __ldg(&b1[col + 1]);
            hid[row * 132 + col]           = f2tf_f(fmaxf(acc[mf][nf][0] + bb0, 0.f));
            hid[row * 132 + col + 1]       = f2tf_f(fmaxf(acc[mf][nf][1] + bb1, 0.f));
            hid[(row + 8) * 132 + col]     = f2tf_f(fmaxf(acc[mf][nf][2] + bb0, 0.f));
            hid[(row + 8) * 132 + col + 1] = f2tf_f(fmaxf(acc[mf][nf][3] + bb1, 0.f));
        }

#pragma unroll
    for (int mf = 0; mf < 4; mf++)
#pragma unroll
        for (int nf = 0; nf < 4; nf++)
#pragma unroll
            for (int q = 0; q < 4; q++) acc[mf][nf][q] = 0.f;

    // ================= stage 2: hid[128 x 128] @ W2[128 x 128] =================
    for (int k0 = 0; k0 < H; k0 += 32) {
#pragma unroll
        for (int q = 0; q < 4; q++) {
            int i  = q * 256 + tid;
            int wr = i >> 5;
            int wc = (i & 31) * 4;
            float4 v = *(const float4*)&W2[(k0 + wr) * H + wc];
            float4 o;
            o.x = f2tf_f(v.x); o.y = f2tf_f(v.y); o.z = f2tf_f(v.z); o.w = f2tf_f(v.w);
            *(float4*)&Ws[wr * 136 + wc] = o;
        }
        __syncthreads();
#pragma unroll
        for (int kk = 0; kk < 4; kk++) {
            int k  = kk * 8;          // within Ws tile
            int ka = k0 + k;          // within hid
            unsigned a[4][4], b[4][2];
#pragma unroll
            for (int mf = 0; mf < 4; mf++) {
                int ar = wm + mf * 16 + (lane >> 2);
                int ak = ka + (lane & 3);
                a[mf][0] = __float_as_uint(hid[ar * 132 + ak]);
                a[mf][1] = __float_as_uint(hid[(ar + 8) * 132 + ak]);
                a[mf][2] = __float_as_uint(hid[ar * 132 + ak + 4]);
                a[mf][3] = __float_as_uint(hid[(ar + 8) * 132 + ak + 4]);
            }
#pragma unroll
            for (int nf = 0; nf < 4; nf++) {
                int bc = wn + nf * 8 + (lane >> 2);
                b[nf][0] = __float_as_uint(Ws[(k + (lane & 3)) * 136 + bc]);
                b[nf][1] = __float_as_uint(Ws[(k + 4 + (lane & 3)) * 136 + bc]);
            }
#pragma unroll
            for (int mf = 0; mf < 4; mf++)
#pragma unroll
                for (int nf = 0; nf < 4; nf++)
                    mma_tf32(acc[mf][nf], a[mf][0], a[mf][1], a[mf][2], a[mf][3],
                             b[nf][0], b[nf][1]);
        }
        __syncthreads();
    }

    // ================= epilogues =================
    if (MODE == 4) {
        float p[4][2];
#pragma unroll
        for (int mf = 0; mf < 4; mf++) { p[mf][0] = 0.f; p[mf][1] = 0.f; }
#pragma unroll
        for (int mf = 0; mf < 4; mf++)
#pragma unroll
            for (int nf = 0; nf < 4; nf++) {
                int col = wn + nf * 8 + 2 * (lane & 3);
                float bb0 = __ldg(&b2[col]), bb1 = __ldg(&b2[col + 1]);
                float w30 = __ldg(&W3[col]), w31 = __ldg(&W3[col + 1]);
                p[mf][0] += fmaxf(acc[mf][nf][0] + bb0, 0.f) * w30
                          + fmaxf(acc[mf][nf][1] + bb1, 0.f) * w31;
                p[mf][1] += fmaxf(acc[mf][nf][2] + bb0, 0.f) * w30
                          + fmaxf(acc[mf][nf][3] + bb1, 0.f) * w31;
            }
#pragma unroll
        for (int mf = 0; mf < 4; mf++)
#pragma unroll
            for (int h = 0; h < 2; h++) {
                float v = p[mf][h];
                v += __shfl_xor_sync(0xFFFFFFFFu, v, 1);
                v += __shfl_xor_sync(0xFFFFFFFFu, v, 2);
                if ((lane & 3) == 0)
                    atomicAdd(&spred[wm + mf * 16 + (lane >> 2) + 8 * h], v);
            }
        __syncthreads();
        if (tid < 128) {
            int r = row0 + tid;
            if (r < nrows) {
                float s = spred[tid] + __ldg(&b3[0]);
                outp[r] = 1.f / (1.f + expf(-s));
                if (logit_off > 0) outp[logit_off + r] = s;
            }
        }
        return;
    }

#pragma unroll
    for (int mf = 0; mf < 4; mf++)
#pragma unroll
        for (int nf = 0; nf < 4; nf++) {
            int row = wm + mf * 16 + (lane >> 2);
            int col = wn + nf * 8 + 2 * (lane & 3);
            float bb0 = __ldg(&b2[col]), bb1 = __ldg(&b2[col + 1]);
            float v0 = acc[mf][nf][0] + bb0, v1 = acc[mf][nf][1] + bb1;
            float v2 = acc[mf][nf][2] + bb0, v3 = acc[mf][nf][3] + bb1;
            if (MODE == 3) {
                v0 = fmaxf(v0, 0.f); v1 = fmaxf(v1, 0.f);
                v2 = fmaxf(v2, 0.f); v3 = fmaxf(v3, 0.f);
            }
            if (MODE == 0 || MODE == 3) {
                int g0 = row0 + row, g1 = row0 + row + 8;
                if (g0 < nrows) { outp[(size_t)g0 * H + col] = v0; outp[(size_t)g0 * H + col + 1] = v1; }
                if (g1 < nrows) { outp[(size_t)g1 * H + col] = v2; outp[(size_t)g1 * H + col + 1] = v3; }
            } else if (MODE == 2) {
                int g0 = row0 + row, g1 = row0 + row + 8;
                if (g0 < nrows && sdst[row])     { outp[(size_t)g0 * H + col] = v0; outp[(size_t)g0 * H + col + 1] = v1; }
                if (g1 < nrows && sdst[row + 8]) { outp[(size_t)g1 * H + col] = v2; outp[(size_t)g1 * H + col + 1] = v3; }
            } else {  // MODE 1: stage fp32 msgs to smem for segment reduce
                hid[row * 132 + col]           = v0;
                hid[row * 132 + col + 1]       = v1;
                hid[(row + 8) * 132 + col]     = v2;
                hid[(row + 8) * 132 + col + 1] = v3;
            }
        }

    if (MODE == 1) {
        __syncthreads();
        // adj_dst sorted -> runs of equal dst within the block. 2 teams x 128 cols.
        int team = tid >> 7;
        int col  = tid & 127;
        int rbeg = team * 64, rend = rbeg + 64;
        float sum = 0.f;
        int cur = sdst[rbeg];
        for (int r = rbeg; r < rend; r++) {
            sum += hid[r * 132 + col];
            int nxt = (r + 1 < rend) ? sdst[r + 1] : -2;
            if (nxt != cur) {
                if (cur >= 0) atomicAdd(&outp[(size_t)cur * H + col], sum);
                sum = 0.f;
                cur = nxt;
            }
        }
    }
}

extern "C" void kernel_launch(void* const* d_in, const int* in_sizes, int n_in,
                              void* d_out, int out_size) {
    const float* feat    = (const float*)d_in[0];
    const int*   adj_dst = (const int*)  d_in[1];
    const int*   adj_src = (const int*)  d_in[2];
    const int*   cand_i  = (const int*)  d_in[3];
    const int*   cand_j  = (const int*)  d_in[4];
    const float* enc_W1 = (const float*)d_in[5];
    const float* enc_b1 = (const float*)d_in[6];
    const float* enc_W2 = (const float*)d_in[7];
    const float* enc_b2 = (const float*)d_in[8];
    const float* msg_W1 = (const float*)d_in[9];
    const float* msg_b1 = (const float*)d_in[10];
    const float* msg_W2 = (const float*)d_in[11];
    const float* msg_b2 = (const float*)d_in[12];
    const float* upd_W1 = (const float*)d_in[13];
    const float* upd_b1 = (const float*)d_in[14];
    const float* upd_W2 = (const float*)d_in[15];
    const float* upd_b2 = (const float*)d_in[16];
    const float* pred_W1 = (const float*)d_in[17];
    const float* pred_b1 = (const float*)d_in[18];
    const float* pred_W2 = (const float*)d_in[19];
    const float* pred_b2 = (const float*)d_in[20];
    const float* pred_W3 = (const float*)d_in[21];
    const float* pred_b3 = (const float*)d_in[22];

    int NE = in_sizes[0] / F;
    int NA = in_sizes[1];
    int NC = in_sizes[3];
    if (NE > NE_MAX) NE = NE_MAX;

    float *e, *e2, *agg;
    int* deg;
    cudaGetSymbolAddress((void**)&e,   g_e);
    cudaGetSymbolAddress((void**)&e2,  g_e2);
    cudaGetSymbolAddress((void**)&agg, g_agg);
    cudaGetSymbolAddress((void**)&deg, g_deg);

    cudaFuncSetAttribute(mlp2_tc<0, 64>,  cudaFuncAttributeMaxDynamicSharedMemorySize, SMEM_BYTES);
    cudaFuncSetAttribute(mlp2_tc<1, 256>, cudaFuncAttributeMaxDynamicSharedMemorySize, SMEM_BYTES);
    cudaFuncSetAttribute(mlp2_tc<2, 256>, cudaFuncAttributeMaxDynamicSharedMemorySize, SMEM_BYTES);
    cudaFuncSetAttribute(mlp2_tc<3, 256>, cudaFuncAttributeMaxDynamicSharedMemorySize, SMEM_BYTES);
    cudaFuncSetAttribute(mlp2_tc<4, 256>, cudaFuncAttributeMaxDynamicSharedMemorySize, SMEM_BYTES);

    cudaMemsetAsync(deg, 0, (size_t)NE * sizeof(int));
    deg_kernel<<<(NA + 255) / 256, 256>>>(adj_dst, NA, deg);

    int gNE = (NE + 127) / 128;
    mlp2_tc<0, 64><<<gNE, 256, SMEM_BYTES>>>(feat, feat, enc_W1, enc_b1, enc_W2, enc_b2,
                                             nullptr, nullptr, nullptr, nullptr, deg, e, NE, 0);

    float* cur = e;
    float* nxt = e2;
    int gNA = (NA + 127) / 128;
    for (int l = 0; l < 3; l++) {
        const float* mW1 = msg_W1 + (size_t)l * 2 * H * H;
        const float* mb1 = msg_b1 + (size_t)l * H;
        const float* mW2 = msg_W2 + (size_t)l * H * H;
        const float* mb2 = msg_b2 + (size_t)l * H;
        const float* uW1 = upd_W1 + (size_t)l * 2 * H * H;
        const float* ub1 = upd_b1 + (size_t)l * H;
        const float* uW2 = upd_W2 + (size_t)l * H * H;
        const float* ub2 = upd_b2 + (size_t)l * H;

        cudaMemsetAsync(agg, 0, (size_t)NE * H * sizeof(float));
        mlp2_tc<1, 256><<<gNA, 256, SMEM_BYTES>>>(cur, cur, mW1, mb1, mW2, mb2,
                                                  nullptr, nullptr, adj_dst, adj_src, deg, agg, NA, 0);
        mlp2_tc<2, 256><<<gNE, 256, SMEM_BYTES>>>(cur, cur, mW1, mb1, mW2, mb2,
                                                  nullptr, nullptr, nullptr, nullptr, deg, agg, NE, 0);
        mlp2_tc<3, 256><<<gNE, 256, SMEM_BYTES>>>(cur, agg, uW1, ub1, uW2, ub2,
                                                  nullptr, nullptr, nullptr, nullptr, deg, nxt, NE, 0);
        float* t = cur; cur = nxt; nxt = t;
    }

    int gNC = (NC + 127) / 128;
    int logit_off = (out_size >= 2 * NC) ? NC : -1;
    mlp2_tc<4, 256><<<gNC, 256, SMEM_BYTES>>>(cur, cur, pred_W1, pred_b1, pred_W2, pred_b2,
                                              pred_W3, pred_b3, cand_i, cand_j, deg,
                                              (float*)d_out, NC, logit_off);
}

// round 3
// speedup vs baseline: 4.2901x; 1.0016x over previous
#include <cuda_runtime.h>
#include <math.h>

#define H 128
#define F 64
#define NE_MAX 50000

// scratch (allocation-free rule: device globals)
__device__ float g_e  [NE_MAX * H];
__device__ float g_e2 [NE_MAX * H];
__device__ float g_agg[NE_MAX * H];
__device__ int   g_deg[NE_MAX];

__global__ void deg_kernel(const int* __restrict__ dst, int na, int* __restrict__ deg) {
    int i = blockIdx.x * blockDim.x + threadIdx.x;
    if (i < na) atomicAdd(&deg[dst[i]], 1);
}

__device__ __forceinline__ unsigned f2tf(float f) {
    unsigned u;
    asm("cvt.rna.tf32.f32 %0, %1;" : "=r"(u) : "f"(f));
    return u;
}
__device__ __forceinline__ float f2tf_f(float f) { return __uint_as_float(f2tf(f)); }

__device__ __forceinline__ void mma_tf32(float c[4],
                                         unsigned a0, unsigned a1, unsigned a2, unsigned a3,
                                         unsigned b0, unsigned b1) {
    asm volatile(
        "mma.sync.aligned.m16n8k8.row.col.f32.tf32.tf32.f32 "
        "{%0,%1,%2,%3}, {%4,%5,%6,%7}, {%8,%9}, {%0,%1,%2,%3};"
        : "+f"(c[0]), "+f"(c[1]), "+f"(c[2]), "+f"(c[3])
        : "r"(a0), "r"(a1), "r"(a2), "r"(a3), "r"(b0), "r"(b1));
}

// smem layout (dynamic):
//   Ws   : 32*136 floats   (weight k-tile, stride 136 -> conflict-free B frags)
//   hid  : 128*132 floats  (hidden acts; first part aliased as As with stride 36)
//   spred: 128 floats
//   soff0/soff1/sdst: 128 ints each; sscale: 128 floats
#define WS_ELEMS   (32 * 136)
#define HID_ELEMS  (128 * 132)
#define SMEM_FLOATS (WS_ELEMS + HID_ELEMS + 128 + 128 + 128 + 128 + 128)
#define SMEM_BYTES  (SMEM_FLOATS * 4)

// MODE: 0=encoder  1=msg(atomic segment-add)  2=self-msg(isolated only)
//       3=update   4=predictor(3-layer + sigmoid)
template <int MODE, int K1>
__global__ __launch_bounds__(256)
void mlp2_tc(const float* __restrict__ A0, const float* __restrict__ B0,
             const float* __restrict__ W1, const float* __restrict__ b1,
             const float* __restrict__ W2, const float* __restrict__ b2,
             const float* __restrict__ W3, const float* __restrict__ b3,
             const int* __restrict__ idx0, const int* __restrict__ idx1,
             const int* __restrict__ deg,
             float* __restrict__ outp,
             int nrows, int logit_off)
{
    extern __shared__ float sm[];
    float* Ws     = sm;                      // [32][136]
    float* hid    = sm + WS_ELEMS;           // [128][132]
    float* As     = hid;                     // alias, [128][36]
    float* spred  = hid + HID_ELEMS;         // [128]
    int*   soff0  = (int*)(spred + 128);
    int*   soff1  = soff0 + 128;
    int*   sdst   = soff1 + 128;
    float* sscale = (float*)(sdst + 128);

    const int tid  = threadIdx.x;
    const int lane = tid & 31;
    const int w    = tid >> 5;
    const int wm   = (w & 1) * 64;   // warp M base (2 M-warps)
    const int wn   = (w >> 1) * 32;  // warp N base (4 N-warps)
    const int row0 = blockIdx.x * 128;

    bool iso = false;
    if (tid < 128) {
        int r = row0 + tid;
        bool valid = r < nrows;
        int rr = valid ? r : 0;
        float sc = 1.f;
        if (MODE == 0) {
            soff0[tid] = rr * F; soff1[tid] = 0;
        } else if (MODE == 1) {
            int i0 = idx0[rr], i1 = idx1[rr];
            soff0[tid] = i0 * H; soff1[tid] = i1 * H;
            sdst[tid] = valid ? i0 : -1;
        } else if (MODE == 2) {
            soff0[tid] = rr * H; soff1[tid] = rr * H;
            iso = valid && (deg[r] == 0);
            sdst[tid] = iso ? 1 : 0;
        } else if (MODE == 3) {
            soff0[tid] = rr * H; soff1[tid] = rr * H;
            int d = deg[rr];
            sc = 1.f / (d > 1 ? (float)d : 1.f);
        } else {
            int i0 = idx0[rr], i1 = idx1[rr];
            soff0[tid] = i0 * H; soff1[tid] = i1 * H;
        }
        sscale[tid] = sc;
        if (MODE == 4) spred[tid] = 0.f;
    }
    int any = __syncthreads_or((MODE == 2) ? (int)iso : 1);
    if (MODE == 2 && !any) return;

    float acc[4][4][4];
#pragma unroll
    for (int mf = 0; mf < 4; mf++)
#pragma unroll
        for (int nf = 0; nf < 4; nf++)
#pragma unroll
            for (int q = 0; q < 4; q++) acc[mf][nf][q] = 0.f;

    // ================= stage 1: A[128 x K1] @ W1[K1 x 128] =================
    for (int k0 = 0; k0 < K1; k0 += 32) {
        // W tile 32x128
#pragma unroll
        for (int q = 0; q < 4; q++) {
            int i  = q * 256 + tid;
            int wr = i >> 5;
            int wc = (i & 31) * 4;
            float4 v = *(const float4*)&W1[(k0 + wr) * H + wc];
            float4 o;
            o.x = f2tf_f(v.x); o.y = f2tf_f(v.y); o.z = f2tf_f(v.z); o.w = f2tf_f(v.w);
            *(float4*)&Ws[wr * 136 + wc] = o;
        }
        // A tile 128x32 (gathered rows)
#pragma unroll
        for (int q = 0; q < 4; q++) {
            int i  = q * 256 + tid;
            int r  = i >> 3;
            int cg = (i & 7) * 4;
            float4 v;
            if (K1 == 64 || k0 < H) {
                v = *(const float4*)&A0[soff0[r] + k0 + cg];
            } else {
                v = *(const float4*)&B0[soff1[r] + (k0 - H) + cg];
                float sc = sscale[r];
                v.x *= sc; v.y *= sc; v.z *= sc; v.w *= sc;
            }
            float4 o;
            o.x = f2tf_f(v.x); o.y = f2tf_f(v.y); o.z = f2tf_f(v.z); o.w = f2tf_f(v.w);
            *(float4*)&As[r * 36 + cg] = o;
        }
        __syncthreads();
#pragma unroll
        for (int kk = 0; kk < 4; kk++) {
            int k = kk * 8;
            unsigned a[4][4], b[4][2];
#pragma unroll
            for (int mf = 0; mf < 4; mf++) {
                int ar = wm + mf * 16 + (lane >> 2);
                int ak = k + (lane & 3);
                a[mf][0] = __float_as_uint(As[ar * 36 + ak]);
                a[mf][1] = __float_as_uint(As[(ar + 8) * 36 + ak]);
                a[mf][2] = __float_as_uint(As[ar * 36 + ak + 4]);
                a[mf][3] = __float_as_uint(As[(ar + 8) * 36 + ak + 4]);
            }
#pragma unroll
            for (int nf = 0; nf < 4; nf++) {
                int bc = wn + nf * 8 + (lane >> 2);
                b[nf][0] = __float_as_uint(Ws[(k + (lane & 3)) * 136 + bc]);
                b[nf][1] = __float_as_uint(Ws[(k + 4 + (lane & 3)) * 136 + bc]);
            }
#pragma unroll
            for (int mf = 0; mf < 4; mf++)
#pragma unroll
                for (int nf = 0; nf < 4; nf++)
                    mma_tf32(acc[mf][nf], a[mf][0], a[mf][1], a[mf][2], a[mf][3],
                             b[nf][0], b[nf][1]);
        }
        __syncthreads();
    }

    // bias + ReLU -> hid (tf32-rounded, feeds stage-2 mma)
#pragma unroll
    for (int mf = 0; mf < 4; mf++)
#pragma unroll
        for (int nf = 0; nf < 4; nf++) {
            int row = wm + mf * 16 + (lane >> 2);
            int col = wn + nf * 8 + 2 * (lane & 3);
            float bb0 = __ldg(&b1[col]), bb1 = __ldg(&b1[col + 1]);
            hid[row * 132 + col]           = f2tf_f(fmaxf(acc[mf][nf][0] + bb0, 0.f));
            hid[row * 132 + col + 1]       = f2tf_f(fmaxf(acc[mf][nf][1] + bb1, 0.f));
            hid[(row + 8) * 132 + col]     = f2tf_f(fmaxf(acc[mf][nf][2] + bb0, 0.f));
            hid[(row + 8) * 132 + col + 1] = f2tf_f(fmaxf(acc[mf][nf][3] + bb1, 0.f));
        }

#pragma unroll
    for (int mf = 0; mf < 4; mf++)
#pragma unroll
        for (int nf = 0; nf < 4; nf++)
#pragma unroll
            for (int q = 0; q < 4; q++) acc[mf][nf][q] = 0.f;

    // ================= stage 2: hid[128 x 128] @ W2[128 x 128] =================
    for (int k0 = 0; k0 < H; k0 += 32) {
#pragma unroll
        for (int q = 0; q < 4; q++) {
            int i  = q * 256 + tid;
            int wr = i >> 5;
            int wc = (i & 31) * 4;
            float4 v = *(const float4*)&W2[(k0 + wr) * H + wc];
            float4 o;
            o.x = f2tf_f(v.x); o.y = f2tf_f(v.y); o.z = f2tf_f(v.z); o.w = f2tf_f(v.w);
            *(float4*)&Ws[wr * 136 + wc] = o;
        }
        __syncthreads();
#pragma unroll
        for (int kk = 0; kk < 4; kk++) {
            int k  = kk * 8;          // within Ws tile
            int ka = k0 + k;          // within hid
            unsigned a[4][4], b[4][2];
#pragma unroll
            for (int mf = 0; mf < 4; mf++) {
                int ar = wm + mf * 16 + (lane >> 2);
                int ak = ka + (lane & 3);
                a[mf][0] = __float_as_uint(hid[ar * 132 + ak]);
                a[mf][1] = __float_as_uint(hid[(ar + 8) * 132 + ak]);
                a[mf][2] = __float_as_uint(hid[ar * 132 + ak + 4]);
                a[mf][3] = __float_as_uint(hid[(ar + 8) * 132 + ak + 4]);
            }
#pragma unroll
            for (int nf = 0; nf < 4; nf++) {
                int bc = wn + nf * 8 + (lane >> 2);
                b[nf][0] = __float_as_uint(Ws[(k + (lane & 3)) * 136 + bc]);
                b[nf][1] = __float_as_uint(Ws[(k + 4 + (lane & 3)) * 136 + bc]);
            }
#pragma unroll
            for (int mf = 0; mf < 4; mf++)
#pragma unroll
                for (int nf = 0; nf < 4; nf++)
                    mma_tf32(acc[mf][nf], a[mf][0], a[mf][1], a[mf][2], a[mf][3],
                             b[nf][0], b[nf][1]);
        }
        __syncthreads();
    }

    // ================= epilogues =================
    if (MODE == 4) {
        float p[4][2];
#pragma unroll
        for (int mf = 0; mf < 4; mf++) { p[mf][0] = 0.f; p[mf][1] = 0.f; }
#pragma unroll
        for (int mf = 0; mf < 4; mf++)
#pragma unroll
            for (int nf = 0; nf < 4; nf++) {
                int col = wn + nf * 8 + 2 * (lane & 3);
                float bb0 = __ldg(&b2[col]), bb1 = __ldg(&b2[col + 1]);
                float w30 = __ldg(&W3[col]), w31 = __ldg(&W3[col + 1]);
                p[mf][0] += fmaxf(acc[mf][nf][0] + bb0, 0.f) * w30
                          + fmaxf(acc[mf][nf][1] + bb1, 0.f) * w31;
                p[mf][1] += fmaxf(acc[mf][nf][2] + bb0, 0.f) * w30
                          + fmaxf(acc[mf][nf][3] + bb1, 0.f) * w31;
            }
#pragma unroll
        for (int mf = 0; mf < 4; mf++)
#pragma unroll
            for (int h = 0; h < 2; h++) {
                float v = p[mf][h];
                v += __shfl_xor_sync(0xFFFFFFFFu, v, 1);
                v += __shfl_xor_sync(0xFFFFFFFFu, v, 2);
                if ((lane & 3) == 0)
                    atomicAdd(&spred[wm + mf * 16 + (lane >> 2) + 8 * h], v);
            }
        __syncthreads();
        if (tid < 128) {
            int r = row0 + tid;
            if (r < nrows) {
                float s = spred[tid] + __ldg(&b3[0]);
                outp[r] = 1.f / (1.f + expf(-s));
                if (logit_off > 0) outp[logit_off + r] = s;
            }
        }
        return;
    }

#pragma unroll
    for (int mf = 0; mf < 4; mf++)
#pragma unroll
        for (int nf = 0; nf < 4; nf++) {
            int row = wm + mf * 16 + (lane >> 2);
            int col = wn + nf * 8 + 2 * (lane & 3);
            float bb0 = __ldg(&b2[col]), bb1 = __ldg(&b2[col + 1]);
            float v0 = acc[mf][nf][0] + bb0, v1 = acc[mf][nf][1] + bb1;
            float v2 = acc[mf][nf][2] + bb0, v3 = acc[mf][nf][3] + bb1;
            if (MODE == 3) {
                v0 = fmaxf(v0, 0.f); v1 = fmaxf(v1, 0.f);
                v2 = fmaxf(v2, 0.f); v3 = fmaxf(v3, 0.f);
            }
            if (MODE == 0 || MODE == 3) {
                int g0 = row0 + row, g1 = row0 + row + 8;
                if (g0 < nrows) { outp[(size_t)g0 * H + col] = v0; outp[(size_t)g0 * H + col + 1] = v1; }
                if (g1 < nrows) { outp[(size_t)g1 * H + col] = v2; outp[(size_t)g1 * H + col + 1] = v3; }
            } else if (MODE == 2) {
                int g0 = row0 + row, g1 = row0 + row + 8;
                if (g0 < nrows && sdst[row])     { outp[(size_t)g0 * H + col] = v0; outp[(size_t)g0 * H + col + 1] = v1; }
                if (g1 < nrows && sdst[row + 8]) { outp[(size_t)g1 * H + col] = v2; outp[(size_t)g1 * H + col + 1] = v3; }
            } else {  // MODE 1: stage fp32 msgs to smem for segment reduce
                hid[row * 132 + col]           = v0;
                hid[row * 132 + col + 1]       = v1;
                hid[(row + 8) * 132 + col]     = v2;
                hid[(row + 8) * 132 + col + 1] = v3;
            }
        }

    if (MODE == 1) {
        __syncthreads();
        // adj_dst sorted -> runs of equal dst within the block. 2 teams x 128 cols.
        int team = tid >> 7;
        int col  = tid & 127;
        int rbeg = team * 64, rend = rbeg + 64;
        float sum = 0.f;
        int cur = sdst[rbeg];
        for (int r = rbeg; r < rend; r++) {
            sum += hid[r * 132 + col];
            int nxt = (r + 1 < rend) ? sdst[r + 1] : -2;
            if (nxt != cur) {
                if (cur >= 0) atomicAdd(&outp[(size_t)cur * H + col], sum);
                sum = 0.f;
                cur = nxt;
            }
        }
    }
}

extern "C" void kernel_launch(void* const* d_in, const int* in_sizes, int n_in,
                              void* d_out, int out_size) {
    const float* feat    = (const float*)d_in[0];
    const int*   adj_dst = (const int*)  d_in[1];
    const int*   adj_src = (const int*)  d_in[2];
    const int*   cand_i  = (const int*)  d_in[3];
    const int*   cand_j  = (const int*)  d_in[4];
    const float* enc_W1 = (const float*)d_in[5];
    const float* enc_b1 = (const float*)d_in[6];
    const float* enc_W2 = (const float*)d_in[7];
    const float* enc_b2 = (const float*)d_in[8];
    const float* msg_W1 = (const float*)d_in[9];
    const float* msg_b1 = (const float*)d_in[10];
    const float* msg_W2 = (const float*)d_in[11];
    const float* msg_b2 = (const float*)d_in[12];
    const float* upd_W1 = (const float*)d_in[13];
    const float* upd_b1 = (const float*)d_in[14];
    const float* upd_W2 = (const float*)d_in[15];
    const float* upd_b2 = (const float*)d_in[16];
    const float* pred_W1 = (const float*)d_in[17];
    const float* pred_b1 = (const float*)d_in[18];
    const float* pred_W2 = (const float*)d_in[19];
    const float* pred_b2 = (const float*)d_in[20];
    const float* pred_W3 = (const float*)d_in[21];
    const float* pred_b3 = (const float*)d_in[22];

    int NE = in_sizes[0] / F;
    int NA = in_sizes[1];
    int NC = in_sizes[3];
    if (NE > NE_MAX) NE = NE_MAX;

    float *e, *e2, *agg;
    int* deg;
    cudaGetSymbolAddress((void**)&e,   g_e);
    cudaGetSymbolAddress((void**)&e2,  g_e2);
    cudaGetSymbolAddress((void**)&agg, g_agg);
    cudaGetSymbolAddress((void**)&deg, g_deg);

    cudaFuncSetAttribute(mlp2_tc<0, 64>,  cudaFuncAttributeMaxDynamicSharedMemorySize, SMEM_BYTES);
    cudaFuncSetAttribute(mlp2_tc<1, 256>, cudaFuncAttributeMaxDynamicSharedMemorySize, SMEM_BYTES);
    cudaFuncSetAttribute(mlp2_tc<2, 256>, cudaFuncAttributeMaxDynamicSharedMemorySize, SMEM_BYTES);
    cudaFuncSetAttribute(mlp2_tc<3, 256>, cudaFuncAttributeMaxDynamicSharedMemorySize, SMEM_BYTES);
    cudaFuncSetAttribute(mlp2_tc<4, 256>, cudaFuncAttributeMaxDynamicSharedMemorySize, SMEM_BYTES);

    cudaMemsetAsync(deg, 0, (size_t)NE * sizeof(int));
    deg_kernel<<<(NA + 255) / 256, 256>>>(adj_dst, NA, deg);

    int gNE = (NE + 127) / 128;
    mlp2_tc<0, 64><<<gNE, 256, SMEM_BYTES>>>(feat, feat, enc_W1, enc_b1, enc_W2, enc_b2,
                                             nullptr, nullptr, nullptr, nullptr, deg, e, NE, 0);

    float* cur = e;
    float* nxt = e2;
    int gNA = (NA + 127) / 128;
    for (int l = 0; l < 3; l++) {
        const float* mW1 = msg_W1 + (size_t)l * 2 * H * H;
        const float* mb1 = msg_b1 + (size_t)l * H;
        const float* mW2 = msg_W2 + (size_t)l * H * H;
        const float* mb2 = msg_b2 + (size_t)l * H;
        const float* uW1 = upd_W1 + (size_t)l * 2 * H * H;
        const float* ub1 = upd_b1 + (size_t)l * H;
        const float* uW2 = upd_W2 + (size_t)l * H * H;
        const float* ub2 = upd_b2 + (size_t)l * H;

        cudaMemsetAsync(agg, 0, (size_t)NE * H * sizeof(float));
        mlp2_tc<1, 256><<<gNA, 256, SMEM_BYTES>>>(cur, cur, mW1, mb1, mW2, mb2,
                                                  nullptr, nullptr, adj_dst, adj_src, deg, agg, NA, 0);
        mlp2_tc<2, 256><<<gNE, 256, SMEM_BYTES>>>(cur, cur, mW1, mb1, mW2, mb2,
                                                  nullptr, nullptr, nullptr, nullptr, deg, agg, NE, 0);
        mlp2_tc<3, 256><<<gNE, 256, SMEM_BYTES>>>(cur, agg, uW1, ub1, uW2, ub2,
                                                  nullptr, nullptr, nullptr, nullptr, deg, nxt, NE, 0);
        float* t = cur; cur = nxt; nxt = t;
    }

    int gNC = (NC + 127) / 128;
    int logit_off = (out_size >= 2 * NC) ? NC : -1;
    mlp2_tc<4, 256><<<gNC, 256, SMEM_BYTES>>>(cur, cur, pred_W1, pred_b1, pred_W2, pred_b2,
                                              pred_W3, pred_b3, cand_i, cand_j, deg,
                                              (float*)d_out, NC, logit_off);
}

// round 5
// speedup vs baseline: 4.5163x; 1.0527x over previous
#include <cuda_runtime.h>
#include <cuda_bf16.h>
#include <stdint.h>
#include <math.h>

#define H 128
#define NE_MAX 50000

typedef unsigned int uint;
typedef unsigned short u16;

// ---------------- device scratch (allocation-free rule) ----------------
__device__ u16   g_eh [NE_MAX * H];
__device__ u16   g_el [NE_MAX * H];
__device__ u16   g_e2h[NE_MAX * H];
__device__ u16   g_e2l[NE_MAX * H];
__device__ float g_P  [NE_MAX * H];
__device__ float g_Q  [NE_MAX * H];
__device__ float g_agg[NE_MAX * H];
__device__ int   g_deg[NE_MAX];
#define WSCRATCH 368640
__device__ u16 g_wh[WSCRATCH];
__device__ u16 g_wl[WSCRATCH];

// transposed/split weight offsets (elements)
#define OFF_ENC1 0
#define OFF_ENC2 8192
#define OFF_L(l)   (24576 + (l) * 98304)
#define OFF_W1T(l) (OFF_L(l))
#define OFF_W1B(l) (OFF_L(l) + 16384)
#define OFF_MW2(l) (OFF_L(l) + 32768)
#define OFF_U1T(l) (OFF_L(l) + 49152)
#define OFF_U1B(l) (OFF_L(l) + 65536)
#define OFF_UW2(l) (OFF_L(l) + 81920)
#define OFF_P1T 319488
#define OFF_P1B 335872
#define OFF_P2  352256

// smem word offsets (uint granularity); row stride 68 words = 136 u16
#define WROW 68
#define WH_W 0
#define WL_W 8704
#define AH_W 17408
#define AL_W 26112
#define CTRL_W 34816            // sdst[128] ints, then sp[256] floats
#define SMEM_WORDS 35200
#define SMEM_BYTES (SMEM_WORDS * 4)

// ---------------- helpers ----------------
__device__ __forceinline__ uint phi(float a, float b) {
    return (uint)__bfloat16_as_ushort(__float2bfloat16_rn(a))
         | ((uint)__bfloat16_as_ushort(__float2bfloat16_rn(b)) << 16);
}
__device__ __forceinline__ uint plo(float a, float b) {
    float ah = __bfloat162float(__float2bfloat16_rn(a));
    float bh = __bfloat162float(__float2bfloat16_rn(b));
    return phi(a - ah, b - bh);
}
__device__ __forceinline__ float bf2f(u16 v) {
    return __bfloat162float(__ushort_as_bfloat16(v));
}

__device__ __forceinline__ void mma_bf(float* c, uint a0, uint a1, uint a2, uint a3,
                                       uint b0, uint b1) {
    asm volatile(
        "mma.sync.aligned.m16n8k16.row.col.f32.bf16.bf16.f32 "
        "{%0,%1,%2,%3},{%4,%5,%6,%7},{%8,%9},{%0,%1,%2,%3};"
        : "+f"(c[0]), "+f"(c[1]), "+f"(c[2]), "+f"(c[3])
        : "r"(a0), "r"(a1), "r"(a2), "r"(a3), "r"(b0), "r"(b1));
}

// core: acc[2][8][4] (warp tile 32x64), A/W in smem (hi+lo), NK k16-steps
template <int NK>
__device__ __forceinline__ void gemm_core(const uint* sm, float acc[2][8][4],
                                          int wm, int wn, int lane) {
    const int lg = lane >> 2, lt = lane & 3;
#pragma unroll
    for (int ks = 0; ks < NK; ks++) {
        const int kw = ks * 8 + lt;
        uint ah[2][4], al[2][4];
#pragma unroll
        for (int mf = 0; mf < 2; mf++) {
            int base = (wm + mf * 16 + lg) * WROW + kw;
            ah[mf][0] = sm[AH_W + base];
            ah[mf][1] = sm[AH_W + base + 8 * WROW];
            ah[mf][2] = sm[AH_W + base + 4];
            ah[mf][3] = sm[AH_W + base + 8 * WROW + 4];
            al[mf][0] = sm[AL_W + base];
            al[mf][1] = sm[AL_W + base + 8 * WROW];
            al[mf][2] = sm[AL_W + base + 4];
            al[mf][3] = sm[AL_W + base + 8 * WROW + 4];
        }
#pragma unroll
        for (int nf = 0; nf < 8; nf++) {
            int bb = (wn + nf * 8 + lg) * WROW + kw;
            uint bh0 = sm[WH_W + bb], bh1 = sm[WH_W + bb + 4];
            uint bl0 = sm[WL_W + bb], bl1 = sm[WL_W + bb + 4];
#pragma unroll
            for (int mf = 0; mf < 2; mf++) {
                mma_bf(acc[mf][nf], ah[mf][0], ah[mf][1], ah[mf][2], ah[mf][3], bh0, bh1);
                mma_bf(acc[mf][nf], ah[mf][0], ah[mf][1], ah[mf][2], ah[mf][3], bl0, bl1);
                mma_bf(acc[mf][nf], al[mf][0], al[mf][1], al[mf][2], al[mf][3], bh0, bh1);
            }
        }
    }
}

template <int NK>
__device__ __forceinline__ void load_weights(uint* sm, const u16* Wth, const u16* Wtl,
                                             int tid) {
    const int nv = 128 * NK * 2;  // uint4 per array
    const uint4* sh = (const uint4*)Wth;
    const uint4* sl = (const uint4*)Wtl;
    for (int i = tid; i < nv; i += 256) {
        int n = i / (NK * 2), q = i % (NK * 2);
        *(uint4*)(sm + WH_W + n * WROW + q * 4) = sh[i];
        *(uint4*)(sm + WL_W + n * WROW + q * 4) = sl[i];
    }
}

// ---------------- small kernels ----------------
__global__ void deg_kernel(const int* __restrict__ dst, int na, int* __restrict__ deg) {
    int i = blockIdx.x * blockDim.x + threadIdx.x;
    if (i < na) atomicAdd(&deg[dst[i]], 1);
}

// transpose + bf16 hi/lo split:  out[n*K+k] = W[(rowoff+k)*128 + n]
__global__ void wprep(const float* __restrict__ W, int rowoff, int K, int off) {
    int i = blockIdx.x * 256 + threadIdx.x;
    if (i >= 128 * K) return;
    int n = i / K, k = i % K;
    float v = W[(size_t)(rowoff + k) * 128 + n];
    __nv_bfloat16 h = __float2bfloat16_rn(v);
    g_wh[off + i] = __bfloat16_as_ushort(h);
    g_wl[off + i] = __bfloat16_as_ushort(__float2bfloat16_rn(v - __bfloat162float(h)));
}

// isolated-node (deg==0) self message via P,Q: agg[n] = MLP2 hidden path
__global__ void selfmsg(const float* __restrict__ P, const float* __restrict__ Q,
                        const float* __restrict__ b1, const float* __restrict__ W2,
                        const float* __restrict__ b2, const int* __restrict__ deg,
                        float* __restrict__ agg, int ne) {
    int base = blockIdx.x * 256;
    int t = threadIdx.x;
    int idx = base + t;
    bool iso = (idx < ne) && (deg[idx] == 0);
    if (!__syncthreads_or((int)iso)) return;
    __shared__ float h[128];
    int lim = min(base + 256, ne);
    for (int n = base; n < lim; n++) {
        if (deg[n] != 0) continue;
        if (t < 128) h[t] = fmaxf(P[(size_t)n * H + t] + Q[(size_t)n * H + t] + b1[t], 0.f);
        __syncthreads();
        if (t < 128) {
            float o = b2[t];
            for (int k = 0; k < 128; k++) o += h[k] * W2[k * 128 + t];
            agg[(size_t)n * H + t] = o;
        }
        __syncthreads();
    }
}

// ---------------- plain GEMM: out = epi( A @ Wt ) ----------------
// AK: 0 = bf16 hi/lo arrays (identity rows), 1 = fp32 + inv_deg scale, 2 = fp32 plain
// EPI: 0 = fp32 raw out, 1 = bias+ReLU -> bf16 pair, 2 = bias -> bf16 pair
template <int AK, int NK, int EPI>
__global__ __launch_bounds__(256, 1)
void gk_plain(const float* __restrict__ Af,
              const u16* __restrict__ Aph, const u16* __restrict__ Apl,
              const u16* __restrict__ Wth, const u16* __restrict__ Wtl,
              const float* __restrict__ bias, const int* __restrict__ deg,
              float* __restrict__ outf, u16* __restrict__ obh, u16* __restrict__ obl,
              int nrows, int ntiles)
{
    extern __shared__ uint sm[];
    const int tid = threadIdx.x;
    const int lane = tid & 31, w = tid >> 5;
    const int wm = (w & 3) * 32, wn = (w >> 2) * 64;

    load_weights<NK>(sm, Wth, Wtl, tid);

    for (int t = blockIdx.x; t < ntiles; t += gridDim.x) {
        const int t0 = t * 128;
        // ---- A fill ----
        {
            int r = tid >> 1, hh = tid & 1;
            int gr = t0 + r;
            int rr = (gr < nrows) ? gr : 0;
            int base = r * WROW + hh * (NK * 4);   // words per half-row = NK*8/2
            if (AK == 0) {
                const uint4* s = (const uint4*)Aph + (size_t)rr * 16 + hh * 8;
                const uint4* sl = (const uint4*)Apl + (size_t)rr * 16 + hh * 8;
#pragma unroll
                for (int j = 0; j < 8; j++) {
                    *(uint4*)(sm + AH_W + base + j * 4) = s[j];
                    *(uint4*)(sm + AL_W + base + j * 4) = sl[j];
                }
            } else {
                const int NQ = NK * 2;             // float4 per half-row
                float sc = 1.f;
                if (AK == 1) { int d = deg[rr]; sc = 1.f / (d > 1 ? (float)d : 1.f); }
                const float4* s = (const float4*)(Af + (size_t)rr * (NK * 16) + hh * (NK * 8));
#pragma unroll
                for (int q = 0; q < NQ; q++) {
                    float4 v = s[q];
                    if (AK == 1) { v.x *= sc; v.y *= sc; v.z *= sc; v.w *= sc; }
                    *(uint2*)(sm + AH_W + base + 2 * q) = make_uint2(phi(v.x, v.y), phi(v.z, v.w));
                    *(uint2*)(sm + AL_W + base + 2 * q) = make_uint2(plo(v.x, v.y), plo(v.z, v.w));
                }
            }
        }
        __syncthreads();

        float acc[2][8][4];
#pragma unroll
        for (int mf = 0; mf < 2; mf++)
#pragma unroll
            for (int nf = 0; nf < 8; nf++)
#pragma unroll
                for (int q = 0; q < 4; q++) acc[mf][nf][q] = 0.f;
        gemm_core<NK>(sm, acc, wm, wn, lane);
        __syncthreads();

        // ---- epilogue ----
#pragma unroll
        for (int mf = 0; mf < 2; mf++)
#pragma unroll
            for (int nf = 0; nf < 8; nf++) {
                int row = wm + mf * 16 + (lane >> 2);
                int col = wn + nf * 8 + (lane & 3) * 2;
                int g0 = t0 + row, g1 = g0 + 8;
                if (EPI == 0) {
                    if (g0 < nrows)
                        *(float2*)&outf[(size_t)g0 * H + col] = make_float2(acc[mf][nf][0], acc[mf][nf][1]);
                    if (g1 < nrows)
                        *(float2*)&outf[(size_t)g1 * H + col] = make_float2(acc[mf][nf][2], acc[mf][nf][3]);
                } else {
                    float b0 = __ldg(&bias[col]), b1v = __ldg(&bias[col + 1]);
                    float v0 = acc[mf][nf][0] + b0, v1 = acc[mf][nf][1] + b1v;
                    float v2 = acc[mf][nf][2] + b0, v3 = acc[mf][nf][3] + b1v;
                    if (EPI == 1) {
                        v0 = fmaxf(v0, 0.f); v1 = fmaxf(v1, 0.f);
                        v2 = fmaxf(v2, 0.f); v3 = fmaxf(v3, 0.f);
                    }
                    int wi = col >> 1;
                    if (g0 < nrows) {
                        ((uint*)obh)[(size_t)g0 * 64 + wi] = phi(v0, v1);
                        ((uint*)obl)[(size_t)g0 * 64 + wi] = plo(v0, v1);
                    }
                    if (g1 < nrows) {
                        ((uint*)obh)[(size_t)g1 * 64 + wi] = phi(v2, v3);
                        ((uint*)obl)[(size_t)g1 * 64 + wi] = plo(v2, v3);
                    }
                }
            }
        __syncthreads();
    }
}

// ---------------- pairsum GEMM: hid = ReLU(X[i0]+Y[i1]+b1); out = epi(hid @ Wt) ----------------
// EPI: 0 = msg (b2 + segment-reduce atomics into agg), 1 = b2+ReLU -> bf16 pair, 2 = predictor
template <int EPI>
__global__ __launch_bounds__(256, 1)
void gk_pair(const float* __restrict__ X, const float* __restrict__ Y,
             const int* __restrict__ idx0, const int* __restrict__ idx1,
             const u16* __restrict__ Wth, const u16* __restrict__ Wtl,
             const float* __restrict__ b1, const float* __restrict__ b2,
             const float* __restrict__ W3, const float* __restrict__ b3,
             float* __restrict__ aggout, u16* __restrict__ obh, u16* __restrict__ obl,
             float* __restrict__ pout,
             int nrows, int ntiles, int logit_off)
{
    extern __shared__ uint sm[];
    int*   sdst = (int*)(sm + CTRL_W);
    float* sp   = (float*)(sm + CTRL_W + 128);
    float* stg  = (float*)(sm + AH_W);   // alias over A region (used post-GEMM)

    const int tid = threadIdx.x;
    const int lane = tid & 31, w = tid >> 5;
    const int wm = (w & 3) * 32, wn = (w >> 2) * 64;

    load_weights<8>(sm, Wth, Wtl, tid);

    for (int t = blockIdx.x; t < ntiles; t += gridDim.x) {
        const int t0 = t * 128;
        // ---- fill: hid = ReLU(X[i0] + Y[i1] + b1), split hi/lo ----
        {
            int r = tid >> 1, hh = tid & 1, ch = hh * 64;
            int gr = t0 + r;
            int rr = (gr < nrows) ? gr : 0;
            int i0 = idx0 ? __ldg(&idx0[rr]) : rr;
            int i1 = idx1 ? __ldg(&idx1[rr]) : rr;
            if (EPI == 0 && hh == 0) sdst[r] = (gr < nrows) ? i0 : -1;
            const float4* xp = (const float4*)(X + (size_t)i0 * H + ch);
            const float4* yp = (const float4*)(Y + (size_t)i1 * H + ch);
            int base = r * WROW + hh * 32;
#pragma unroll
            for (int q = 0; q < 16; q++) {
                float4 xv = xp[q], yv = yp[q];
                int c = ch + q * 4;
                float v0 = fmaxf(xv.x + yv.x + __ldg(&b1[c]),     0.f);
                float v1 = fmaxf(xv.y + yv.y + __ldg(&b1[c + 1]), 0.f);
                float v2 = fmaxf(xv.z + yv.z + __ldg(&b1[c + 2]), 0.f);
                float v3 = fmaxf(xv.w + yv.w + __ldg(&b1[c + 3]), 0.f);
                *(uint2*)(sm + AH_W + base + 2 * q) = make_uint2(phi(v0, v1), phi(v2, v3));
                *(uint2*)(sm + AL_W + base + 2 * q) = make_uint2(plo(v0, v1), plo(v2, v3));
            }
        }
        __syncthreads();

        float acc[2][8][4];
#pragma unroll
        for (int mf = 0; mf < 2; mf++)
#pragma unroll
            for (int nf = 0; nf < 8; nf++)
#pragma unroll
                for (int q = 0; q < 4; q++) acc[mf][nf][q] = 0.f;
        gemm_core<8>(sm, acc, wm, wn, lane);
        __syncthreads();

        if (EPI == 0) {
            // stage msgs (+b2) to smem, then sorted-dst segment reduce -> atomics
#pragma unroll
            for (int mf = 0; mf < 2; mf++)
#pragma unroll
                for (int nf = 0; nf < 8; nf++) {
                    int row = wm + mf * 16 + (lane >> 2);
                    int col = wn + nf * 8 + (lane & 3) * 2;
                    float b0 = __ldg(&b2[col]), b1v = __ldg(&b2[col + 1]);
                    stg[row * 132 + col]           = acc[mf][nf][0] + b0;
                    stg[row * 132 + col + 1]       = acc[mf][nf][1] + b1v;
                    stg[(row + 8) * 132 + col]     = acc[mf][nf][2] + b0;
                    stg[(row + 8) * 132 + col + 1] = acc[mf][nf][3] + b1v;
                }
            __syncthreads();
            int team = tid >> 7, col = tid & 127, rb = team * 64;
            float sum = 0.f;
            int cur = sdst[rb];
            for (int q = 0; q < 64; q++) {
                sum += stg[(rb + q) * 132 + col];
                int nxt = (q < 63) ? sdst[rb + q + 1] : -2;
                if (nxt != cur) {
                    if (cur >= 0) atomicAdd(&aggout[(size_t)cur * H + col], sum);
                    sum = 0.f;
                    cur = nxt;
                }
            }
        } else if (EPI == 1) {
#pragma unroll
            for (int mf = 0; mf < 2; mf++)
#pragma unroll
                for (int nf = 0; nf < 8; nf++) {
                    int row = wm + mf * 16 + (lane >> 2);
                    int col = wn + nf * 8 + (lane & 3) * 2;
                    int g0 = t0 + row, g1 = g0 + 8;
                    float b0 = __ldg(&b2[col]), b1v = __ldg(&b2[col + 1]);
                    float v0 = fmaxf(acc[mf][nf][0] + b0, 0.f);
                    float v1 = fmaxf(acc[mf][nf][1] + b1v, 0.f);
                    float v2 = fmaxf(acc[mf][nf][2] + b0, 0.f);
                    float v3 = fmaxf(acc[mf][nf][3] + b1v, 0.f);
                    int wi = col >> 1;
                    if (g0 < nrows) {
                        ((uint*)obh)[(size_t)g0 * 64 + wi] = phi(v0, v1);
                        ((uint*)obl)[(size_t)g0 * 64 + wi] = plo(v0, v1);
                    }
                    if (g1 < nrows) {
                        ((uint*)obh)[(size_t)g1 * 64 + wi] = phi(v2, v3);
                        ((uint*)obl)[(size_t)g1 * 64 + wi] = plo(v2, v3);
                    }
                }
        } else {
            float p[2][2] = {{0.f, 0.f}, {0.f, 0.f}};
#pragma unroll
            for (int mf = 0; mf < 2; mf++)
#pragma unroll
                for (int nf = 0; nf < 8; nf++) {
                    int col = wn + nf * 8 + (lane & 3) * 2;
                    float b0 = __ldg(&b2[col]), b1v = __ldg(&b2[col + 1]);
                    float w30 = __ldg(&W3[col]), w31 = __ldg(&W3[col + 1]);
                    p[mf][0] += fmaxf(acc[mf][nf][0] + b0, 0.f) * w30
                              + fmaxf(acc[mf][nf][1] + b1v, 0.f) * w31;
                    p[mf][1] += fmaxf(acc[mf][nf][2] + b0, 0.f) * w30
                              + fmaxf(acc[mf][nf][3] + b1v, 0.f) * w31;
                }
#pragma unroll
            for (int mf = 0; mf < 2; mf++)
#pragma unroll
                for (int hq = 0; hq < 2; hq++) {
                    float v = p[mf][hq];
                    v += __shfl_xor_sync(0xFFFFFFFFu, v, 1);
                    v += __shfl_xor_sync(0xFFFFFFFFu, v, 2);
                    if ((lane & 3) == 0) {
                        int row = wm + mf * 16 + (lane >> 2) + hq * 8;
                        sp[row + 128 * (wn >> 6)] = v;
                    }
                }
            __syncthreads();
            if (tid < 128) {
                int r = t0 + tid;
                if (r < nrows) {
                    float s = sp[tid] + sp[tid + 128] + __ldg(&b3[0]);
                    pout[r] = 1.f / (1.f + expf(-s));
                    if (logit_off > 0) pout[logit_off + r] = s;
                }
            }
        }
        __syncthreads();
    }
}

// ---------------- host ----------------
extern "C" void kernel_launch(void* const* d_in, const int* in_sizes, int n_in,
                              void* d_out, int out_size) {
    const float* feat    = (const float*)d_in[0];
    const int*   adj_dst = (const int*)  d_in[1];
    const int*   adj_src = (const int*)  d_in[2];
    const int*   cand_i  = (const int*)  d_in[3];
    const int*   cand_j  = (const int*)  d_in[4];
    const float* enc_W1 = (const float*)d_in[5];
    const float* enc_b1 = (const float*)d_in[6];
    const float* enc_W2 = (const float*)d_in[7];
    const float* enc_b2 = (const float*)d_in[8];
    const float* msg_W1 = (const float*)d_in[9];
    const float* msg_b1 = (const float*)d_in[10];
    const float* msg_W2 = (const float*)d_in[11];
    const float* msg_b2 = (const float*)d_in[12];
    const float* upd_W1 = (const float*)d_in[13];
    const float* upd_b1 = (const float*)d_in[14];
    const float* upd_W2 = (const float*)d_in[15];
    const float* upd_b2 = (const float*)d_in[16];
    const float* pred_W1 = (const float*)d_in[17];
    const float* pred_b1 = (const float*)d_in[18];
    const float* pred_W2 = (const float*)d_in[19];
    const float* pred_b2 = (const float*)d_in[20];
    const float* pred_W3 = (const float*)d_in[21];
    const float* pred_b3 = (const float*)d_in[22];

    int NE = in_sizes[0] / 64;
    int NA = in_sizes[1];
    int NC = in_sizes[3];
    if (NE > NE_MAX) NE = NE_MAX;

    float *P, *Q, *agg;
    int* deg;
    u16 *eh, *el, *e2h, *e2l, *wh, *wl;
    cudaGetSymbolAddress((void**)&P,   g_P);
    cudaGetSymbolAddress((void**)&Q,   g_Q);
    cudaGetSymbolAddress((void**)&agg, g_agg);
    cudaGetSymbolAddress((void**)&deg, g_deg);
    cudaGetSymbolAddress((void**)&eh,  g_eh);
    cudaGetSymbolAddress((void**)&el,  g_el);
    cudaGetSymbolAddress((void**)&e2h, g_e2h);
    cudaGetSymbolAddress((void**)&e2l, g_e2l);
    cudaGetSymbolAddress((void**)&wh,  g_wh);
    cudaGetSymbolAddress((void**)&wl,  g_wl);

    cudaFuncSetAttribute(gk_plain<2, 4, 1>, cudaFuncAttributeMaxDynamicSharedMemorySize, SMEM_BYTES);
    cudaFuncSetAttribute(gk_plain<0, 8, 2>, cudaFuncAttributeMaxDynamicSharedMemorySize, SMEM_BYTES);
    cudaFuncSetAttribute(gk_plain<0, 8, 0>, cudaFuncAttributeMaxDynamicSharedMemorySize, SMEM_BYTES);
    cudaFuncSetAttribute(gk_plain<1, 8, 0>, cudaFuncAttributeMaxDynamicSharedMemorySize, SMEM_BYTES);
    cudaFuncSetAttribute(gk_pair<0>, cudaFuncAttributeMaxDynamicSharedMemorySize, SMEM_BYTES);
    cudaFuncSetAttribute(gk_pair<1>, cudaFuncAttributeMaxDynamicSharedMemorySize, SMEM_BYTES);
    cudaFuncSetAttribute(gk_pair<2>, cudaFuncAttributeMaxDynamicSharedMemorySize, SMEM_BYTES);

    cudaMemsetAsync(deg, 0, (size_t)NE * sizeof(int));
    deg_kernel<<<(NA + 255) / 256, 256>>>(adj_dst, NA, deg);

    // weight prep
    wprep<<<32, 256>>>(enc_W1, 0, 64, OFF_ENC1);
    wprep<<<64, 256>>>(enc_W2, 0, 128, OFF_ENC2);
    for (int l = 0; l < 3; l++) {
        const float* mW1 = msg_W1 + (size_t)l * 2 * H * H;
        const float* mW2 = msg_W2 + (size_t)l * H * H;
        const float* uW1 = upd_W1 + (size_t)l * 2 * H * H;
        const float* uW2 = upd_W2 + (size_t)l * H * H;
        wprep<<<64, 256>>>(mW1, 0,   128, OFF_W1T(l));
        wprep<<<64, 256>>>(mW1, 128, 128, OFF_W1B(l));
        wprep<<<64, 256>>>(mW2, 0,   128, OFF_MW2(l));
        wprep<<<64, 256>>>(uW1, 0,   128, OFF_U1T(l));
        wprep<<<64, 256>>>(uW1, 128, 128, OFF_U1B(l));
        wprep<<<64, 256>>>(uW2, 0,   128, OFF_UW2(l));
    }
    wprep<<<64, 256>>>(pred_W1, 0,   128, OFF_P1T);
    wprep<<<64, 256>>>(pred_W1, 128, 128, OFF_P1B);
    wprep<<<64, 256>>>(pred_W2, 0,   128, OFF_P2);

    int gNE = (NE + 127) / 128;
    int gNA = (NA + 127) / 128;
    int gNC = (NC + 127) / 128;
    int gE = gNE < 148 ? gNE : 148;
    int gA = gNA < 148 ? gNA : 148;
    int gC = gNC < 148 ? gNC : 148;

    // encoder: feat -> ReLU(feat@W1+b1) [temp e2] -> @W2+b2 -> eh/el
    gk_plain<2, 4, 1><<<gE, 256, SMEM_BYTES>>>(
        feat, nullptr, nullptr, wh + OFF_ENC1, wl + OFF_ENC1,
        enc_b1, deg, nullptr, e2h, e2l, NE, gNE);
    gk_plain<0, 8, 2><<<gE, 256, SMEM_BYTES>>>(
        nullptr, e2h, e2l, wh + OFF_ENC2, wl + OFF_ENC2,
        enc_b2, deg, nullptr, eh, el, NE, gNE);

    u16 *ch = eh, *cl = el, *nh = e2h, *nl = e2l;
    for (int l = 0; l < 3; l++) {
        const float* mb1 = msg_b1 + (size_t)l * H;
        const float* mb2 = msg_b2 + (size_t)l * H;
        const float* ub1 = upd_b1 + (size_t)l * H;
        const float* ub2 = upd_b2 + (size_t)l * H;

        // P = e@W1top, Q = e@W1bot
        gk_plain<0, 8, 0><<<gE, 256, SMEM_BYTES>>>(
            nullptr, ch, cl, wh + OFF_W1T(l), wl + OFF_W1T(l),
            nullptr, deg, P, nullptr, nullptr, NE, gNE);
        gk_plain<0, 8, 0><<<gE, 256, SMEM_BYTES>>>(
            nullptr, ch, cl, wh + OFF_W1B(l), wl + OFF_W1B(l),
            nullptr, deg, Q, nullptr, nullptr, NE, gNE);

        // messages: ReLU(P[dst]+Q[src]+b1)@W2 + b2, segment-sum into agg
        cudaMemsetAsync(agg, 0, (size_t)NE * H * sizeof(float));
        gk_pair<0><<<gA, 256, SMEM_BYTES>>>(
            P, Q, adj_dst, adj_src, wh + OFF_MW2(l), wl + OFF_MW2(l),
            mb1, mb2, nullptr, nullptr, agg, nullptr, nullptr, nullptr, NA, gNA, 0);
        selfmsg<<<(NE + 255) / 256, 256>>>(
            P, Q, mb1, msg_W2 + (size_t)l * H * H, mb2, deg, agg, NE);

        // update: T = e@U1top; U = (agg*inv_deg)@U1bot; e' = ReLU(ReLU(T+U+b1)@U2+b2)
        gk_plain<0, 8, 0><<<gE, 256, SMEM_BYTES>>>(
            nullptr, ch, cl, wh + OFF_U1T(l), wl + OFF_U1T(l),
            nullptr, deg, P, nullptr, nullptr, NE, gNE);
        gk_plain<1, 8, 0><<<gE, 256, SMEM_BYTES>>>(
            agg, nullptr, nullptr, wh + OFF_U1B(l), wl + OFF_U1B(l),
            nullptr, deg, Q, nullptr, nullptr, NE, gNE);
        gk_pair<1><<<gE, 256, SMEM_BYTES>>>(
            P, Q, nullptr, nullptr, wh + OFF_UW2(l), wl + OFF_UW2(l),
            ub1, ub2, nullptr, nullptr, nullptr, nh, nl, nullptr, NE, gNE, 0);

        u16* t1 = ch; ch = nh; nh = t1;
        u16* t2 = cl; cl = nl; nl = t2;
    }

    // predictor: R = e@P1top, S = e@P1bot; out = sigmoid(ReLU(ReLU(R[i]+S[j]+b1)@P2+b2)@W3+b3)
    gk_plain<0, 8, 0><<<gE, 256, SMEM_BYTES>>>(
        nullptr, ch, cl, wh + OFF_P1T, wl + OFF_P1T,
        nullptr, deg, P, nullptr, nullptr, NE, gNE);
    gk_plain<0, 8, 0><<<gE, 256, SMEM_BYTES>>>(
        nullptr, ch, cl, wh + OFF_P1B, wl + OFF_P1B,
        nullptr, deg, Q, nullptr, nullptr, NE, gNE);
    int logit_off = (out_size >= 2 * NC) ? NC : -1;
    gk_pair<2><<<gC, 256, SMEM_BYTES>>>(
        P, Q, cand_i, cand_j, wh + OFF_P2, wl + OFF_P2,
        pred_b1, pred_b2, pred_W3, pred_b3,
        nullptr, nullptr, nullptr, (float*)d_out, NC, gNC, logit_off);
}

// round 7
// speedup vs baseline: 10.3864x; 2.2998x over previous
#include <cuda_runtime.h>
#include <cuda_bf16.h>
#include <stdint.h>
#include <math.h>

#define H 128
#define NE_MAX 50000

typedef unsigned int uint;
typedef unsigned short u16;

// ---------------- device scratch (allocation-free rule) ----------------
__device__ u16   g_eh [NE_MAX * H];
__device__ u16   g_el [NE_MAX * H];
__device__ u16   g_e2h[NE_MAX * H];
__device__ u16   g_e2l[NE_MAX * H];
__device__ float g_P  [NE_MAX * H];
__device__ float g_Q  [NE_MAX * H];
__device__ float g_agg[NE_MAX * H];     // Hagg
__device__ int   g_deg[NE_MAX];
__device__ float g_bc [3 * H];          // composite biases
#define WSCRATCH 368640
__device__ u16 g_wh[WSCRATCH];
__device__ u16 g_wl[WSCRATCH];

// transposed/split weight offsets (elements)
#define OFF_ENC1 0
#define OFF_ENC2 8192
#define OFF_L(l)   (24576 + (l) * 98304)
#define OFF_W1T(l) (OFF_L(l))
#define OFF_W1B(l) (OFF_L(l) + 16384)
#define OFF_WC(l)  (OFF_L(l) + 32768)   // composite W2@U1bot
#define OFF_U1T(l) (OFF_L(l) + 49152)
#define OFF_U1B(l) (OFF_L(l) + 65536)   // unused now (kept for layout)
#define OFF_UW2(l) (OFF_L(l) + 81920)
#define OFF_P1T 319488
#define OFF_P1B 335872
#define OFF_P2  352256

// smem word offsets (uint granularity); row stride 68 words = 136 u16
#define WROW 68
#define WH_W 0
#define WL_W 8704
#define AH_W 17408
#define AL_W 26112
#define CTRL_W 34816
#define SMEM_WORDS 35200
#define SMEM_BYTES (SMEM_WORDS * 4)

// ---------------- helpers ----------------
__device__ __forceinline__ uint phi(float a, float b) {
    return (uint)__bfloat16_as_ushort(__float2bfloat16_rn(a))
         | ((uint)__bfloat16_as_ushort(__float2bfloat16_rn(b)) << 16);
}
__device__ __forceinline__ uint plo(float a, float b) {
    float ah = __bfloat162float(__float2bfloat16_rn(a));
    float bh = __bfloat162float(__float2bfloat16_rn(b));
    return phi(a - ah, b - bh);
}

__device__ __forceinline__ void mma_bf(float* c, uint a0, uint a1, uint a2, uint a3,
                                       uint b0, uint b1) {
    asm volatile(
        "mma.sync.aligned.m16n8k16.row.col.f32.bf16.bf16.f32 "
        "{%0,%1,%2,%3},{%4,%5,%6,%7},{%8,%9},{%0,%1,%2,%3};"
        : "+f"(c[0]), "+f"(c[1]), "+f"(c[2]), "+f"(c[3])
        : "r"(a0), "r"(a1), "r"(a2), "r"(a3), "r"(b0), "r"(b1));
}

template <int NK>
__device__ __forceinline__ void gemm_core(const uint* sm, float acc[2][8][4],
                                          int wm, int wn, int lane) {
    const int lg = lane >> 2, lt = lane & 3;
#pragma unroll
    for (int ks = 0; ks < NK; ks++) {
        const int kw = ks * 8 + lt;
        uint ah[2][4], al[2][4];
#pragma unroll
        for (int mf = 0; mf < 2; mf++) {
            int base = (wm + mf * 16 + lg) * WROW + kw;
            ah[mf][0] = sm[AH_W + base];
            ah[mf][1] = sm[AH_W + base + 8 * WROW];
            ah[mf][2] = sm[AH_W + base + 4];
            ah[mf][3] = sm[AH_W + base + 8 * WROW + 4];
            al[mf][0] = sm[AL_W + base];
            al[mf][1] = sm[AL_W + base + 8 * WROW];
            al[mf][2] = sm[AL_W + base + 4];
            al[mf][3] = sm[AL_W + base + 8 * WROW + 4];
        }
#pragma unroll
        for (int nf = 0; nf < 8; nf++) {
            int bb = (wn + nf * 8 + lg) * WROW + kw;
            uint bh0 = sm[WH_W + bb], bh1 = sm[WH_W + bb + 4];
            uint bl0 = sm[WL_W + bb], bl1 = sm[WL_W + bb + 4];
#pragma unroll
            for (int mf = 0; mf < 2; mf++) {
                mma_bf(acc[mf][nf], ah[mf][0], ah[mf][1], ah[mf][2], ah[mf][3], bh0, bh1);
                mma_bf(acc[mf][nf], ah[mf][0], ah[mf][1], ah[mf][2], ah[mf][3], bl0, bl1);
                mma_bf(acc[mf][nf], al[mf][0], al[mf][1], al[mf][2], al[mf][3], bh0, bh1);
            }
        }
    }
}

template <int NK>
__device__ __forceinline__ void load_weights(uint* sm, const u16* Wth, const u16* Wtl,
                                             int tid) {
    const int nv = 128 * NK * 2;
    const uint4* sh = (const uint4*)Wth;
    const uint4* sl = (const uint4*)Wtl;
    for (int i = tid; i < nv; i += 256) {
        int n = i / (NK * 2), q = i % (NK * 2);
        *(uint4*)(sm + WH_W + n * WROW + q * 4) = sh[i];
        *(uint4*)(sm + WL_W + n * WROW + q * 4) = sl[i];
    }
}

// ---------------- small kernels ----------------
__global__ void deg_kernel(const int* __restrict__ dst, int na, int* __restrict__ deg) {
    int i = blockIdx.x * blockDim.x + threadIdx.x;
    if (i < na) atomicAdd(&deg[dst[i]], 1);
}

// one kernel prepping ALL weights (transpose + bf16 hi/lo split)
struct PJobs {
    const float* W[20];
    int rowoff[20], K[20], off[20], start[20];
    int njobs, total;
};
__global__ void prep_all(PJobs j) {
    int i = blockIdx.x * 256 + threadIdx.x;
    if (i >= j.total) return;
    int a = 0;
    while (a + 1 < j.njobs && i >= j.start[a + 1]) a++;
    int e = i - j.start[a];
    int K = j.K[a];
    int n = e / K, k = e % K;
    float v = j.W[a][(size_t)(j.rowoff[a] + k) * 128 + n];
    __nv_bfloat16 h = __float2bfloat16_rn(v);
    g_wh[j.off[a] + e] = __bfloat16_as_ushort(h);
    g_wl[j.off[a] + e] = __bfloat16_as_ushort(__float2bfloat16_rn(v - __bfloat162float(h)));
}

// composite weights: Wc = msg_W2 @ upd_W1_bot (fp32), bc = msg_b2 @ upd_W1_bot
__global__ void compprep(const float* __restrict__ upd_W1,
                         const float* __restrict__ msg_W2,
                         const float* __restrict__ msg_b2) {
    int b = blockIdx.x;
    if (b < 192) {
        int l = b >> 6;
        int i = (b & 63) * 256 + threadIdx.x;   // 0..16383
        int o = i & 127, h = i >> 7;
        const float* W2  = msg_W2 + (size_t)l * 16384;
        const float* U1b = upd_W1 + (size_t)l * 32768 + 16384;
        float s = 0.f;
        for (int a2 = 0; a2 < 128; a2++) s += W2[h * 128 + a2] * U1b[a2 * 128 + o];
        // wprep layout: element index = n*K + k with n=o (out col), k=h (in row)
        int li = OFF_WC(l) + o * 128 + h;
        __nv_bfloat16 hh = __float2bfloat16_rn(s);
        g_wh[li] = __bfloat16_as_ushort(hh);
        g_wl[li] = __bfloat16_as_ushort(__float2bfloat16_rn(s - __bfloat162float(hh)));
    } else if (b < 195) {
        int l = b - 192;
        int o = threadIdx.x;
        if (o < 128) {
            const float* U1b = upd_W1 + (size_t)l * 32768 + 16384;
            const float* b2  = msg_b2 + (size_t)l * 128;
            float s = 0.f;
            for (int a2 = 0; a2 < 128; a2++) s += b2[a2] * U1b[a2 * 128 + o];
            g_bc[l * 128 + o] = s;
        }
    }
}

// pair hidden aggregation: Hagg[dst] += ReLU(P[dst] + Q[src] + b1)
__global__ __launch_bounds__(256) void msum(const float* __restrict__ P,
                                            const float* __restrict__ Q,
                                            const float* __restrict__ b1,
                                            const int* __restrict__ dst,
                                            const int* __restrict__ src,
                                            float* __restrict__ Hagg, int na) {
    int team = threadIdx.x >> 7, col = threadIdx.x & 127;
    int p0 = blockIdx.x * 128 + team * 64;
    if (p0 >= na) return;
    float bias = __ldg(&b1[col]);
    float sum = 0.f, pv = 0.f;
    int cur = -1;
    for (int base = 0; base < 64; base += 8) {
        int dd[8], ss[8];
#pragma unroll
        for (int j = 0; j < 8; j++) {
            int a = p0 + base + j;
            bool v = a < na;
            dd[j] = v ? __ldg(&dst[a]) : -1;
            ss[j] = v ? __ldg(&src[a]) : 0;
        }
        float qv[8];
#pragma unroll
        for (int j = 0; j < 8; j++) qv[j] = __ldg(&Q[(size_t)ss[j] * H + col]);
#pragma unroll
        for (int j = 0; j < 8; j++) {
            if (dd[j] != cur) {
                if (cur >= 0) atomicAdd(&Hagg[(size_t)cur * H + col], sum);
                cur = dd[j];
                sum = 0.f;
                if (cur >= 0) pv = __ldg(&P[(size_t)cur * H + col]) + bias;
            }
            if (dd[j] >= 0) sum += fmaxf(pv + qv[j], 0.f);
        }
    }
    if (cur >= 0) atomicAdd(&Hagg[(size_t)cur * H + col], sum);
}

// isolated nodes (deg==0): Hagg[n] = ReLU(P[n]+Q[n]+b1)  (inv_deg=1 path then matches self-msg)
__global__ void fixup(const float* __restrict__ P, const float* __restrict__ Q,
                      const float* __restrict__ b1, const int* __restrict__ deg,
                      float* __restrict__ Hagg, int ne) {
    int n = blockIdx.x * 256 + threadIdx.x;
    if (n >= ne || deg[n] != 0) return;
    for (int c = 0; c < H; c++)
        Hagg[(size_t)n * H + c] = fmaxf(P[(size_t)n * H + c] + Q[(size_t)n * H + c] + b1[c], 0.f);
}

// ---------------- plain GEMM: out = epi( A @ Wt ) ----------------
// AK: 0 = bf16 hi/lo input, 1 = fp32 * inv_deg, 2 = fp32 plain
// EPI: 0 = fp32 raw, 1 = bias+ReLU -> bf16 pair, 2 = bias -> bf16 pair, 3 = fp32 + bias
template <int AK, int NK, int EPI>
__global__ __launch_bounds__(256, 1)
void gk_plain(const float* __restrict__ Af,
              const u16* __restrict__ Aph, const u16* __restrict__ Apl,
              const u16* __restrict__ Wth, const u16* __restrict__ Wtl,
              const float* __restrict__ bias, const int* __restrict__ deg,
              float* __restrict__ outf, u16* __restrict__ obh, u16* __restrict__ obl,
              int nrows, int ntiles)
{
    extern __shared__ uint sm[];
    const int tid = threadIdx.x;
    const int lane = tid & 31, w = tid >> 5;
    const int wm = (w & 3) * 32, wn = (w >> 2) * 64;

    load_weights<NK>(sm, Wth, Wtl, tid);

    for (int t = blockIdx.x; t < ntiles; t += gridDim.x) {
        const int t0 = t * 128;
        {
            int r = tid >> 1, hh = tid & 1;
            int gr = t0 + r;
            int rr = (gr < nrows) ? gr : 0;
            int base = r * WROW + hh * (NK * 4);
            if (AK == 0) {
                const uint4* s = (const uint4*)Aph + (size_t)rr * 16 + hh * 8;
                const uint4* sl = (const uint4*)Apl + (size_t)rr * 16 + hh * 8;
#pragma unroll
                for (int j = 0; j < 8; j++) {
                    *(uint4*)(sm + AH_W + base + j * 4) = s[j];
                    *(uint4*)(sm + AL_W + base + j * 4) = sl[j];
                }
            } else {
                const int NQ = NK * 2;
                float sc = 1.f;
                if (AK == 1) { int d = deg[rr]; sc = 1.f / (d > 1 ? (float)d : 1.f); }
                const float4* s = (const float4*)(Af + (size_t)rr * (NK * 16) + hh * (NK * 8));
#pragma unroll
                for (int q = 0; q < NQ; q++) {
                    float4 v = s[q];
                    if (AK == 1) { v.x *= sc; v.y *= sc; v.z *= sc; v.w *= sc; }
                    *(uint2*)(sm + AH_W + base + 2 * q) = make_uint2(phi(v.x, v.y), phi(v.z, v.w));
                    *(uint2*)(sm + AL_W + base + 2 * q) = make_uint2(plo(v.x, v.y), plo(v.z, v.w));
                }
            }
        }
        __syncthreads();

        float acc[2][8][4];
#pragma unroll
        for (int mf = 0; mf < 2; mf++)
#pragma unroll
            for (int nf = 0; nf < 8; nf++)
#pragma unroll
                for (int q = 0; q < 4; q++) acc[mf][nf][q] = 0.f;
        gemm_core<NK>(sm, acc, wm, wn, lane);
        __syncthreads();

#pragma unroll
        for (int mf = 0; mf < 2; mf++)
#pragma unroll
            for (int nf = 0; nf < 8; nf++) {
                int row = wm + mf * 16 + (lane >> 2);
                int col = wn + nf * 8 + (lane & 3) * 2;
                int g0 = t0 + row, g1 = g0 + 8;
                if (EPI == 0) {
                    if (g0 < nrows)
                        *(float2*)&outf[(size_t)g0 * H + col] = make_float2(acc[mf][nf][0], acc[mf][nf][1]);
                    if (g1 < nrows)
                        *(float2*)&outf[(size_t)g1 * H + col] = make_float2(acc[mf][nf][2], acc[mf][nf][3]);
                } else if (EPI == 3) {
                    float b0 = __ldg(&bias[col]), b1v = __ldg(&bias[col + 1]);
                    if (g0 < nrows)
                        *(float2*)&outf[(size_t)g0 * H + col] = make_float2(acc[mf][nf][0] + b0, acc[mf][nf][1] + b1v);
                    if (g1 < nrows)
                        *(float2*)&outf[(size_t)g1 * H + col] = make_float2(acc[mf][nf][2] + b0, acc[mf][nf][3] + b1v);
                } else {
                    float b0 = __ldg(&bias[col]), b1v = __ldg(&bias[col + 1]);
                    float v0 = acc[mf][nf][0] + b0, v1 = acc[mf][nf][1] + b1v;
                    float v2 = acc[mf][nf][2] + b0, v3 = acc[mf][nf][3] + b1v;
                    if (EPI == 1) {
                        v0 = fmaxf(v0, 0.f); v1 = fmaxf(v1, 0.f);
                        v2 = fmaxf(v2, 0.f); v3 = fmaxf(v3, 0.f);
                    }
                    int wi = col >> 1;
                    if (g0 < nrows) {
                        ((uint*)obh)[(size_t)g0 * 64 + wi] = phi(v0, v1);
                        ((uint*)obl)[(size_t)g0 * 64 + wi] = plo(v0, v1);
                    }
                    if (g1 < nrows) {
                        ((uint*)obh)[(size_t)g1 * 64 + wi] = phi(v2, v3);
                        ((uint*)obl)[(size_t)g1 * 64 + wi] = plo(v2, v3);
                    }
                }
            }
        __syncthreads();
    }
}

// ---------------- pairsum GEMM: hid = ReLU(X[i0]+Y[i1]+b1); out = epi(hid @ Wt) ----------------
// EPI: 1 = b2+ReLU -> bf16 pair (update), 2 = predictor (h@P2 -> ReLU -> @W3 -> sigmoid)
template <int EPI>
__global__ __launch_bounds__(256, 1)
void gk_pair(const float* __restrict__ X, const float* __restrict__ Y,
             const int* __restrict__ idx0, const int* __restrict__ idx1,
             const u16* __restrict__ Wth, const u16* __restrict__ Wtl,
             const float* __restrict__ b1, const float* __restrict__ b2,
             const float* __restrict__ W3, const float* __restrict__ b3,
             u16* __restrict__ obh, u16* __restrict__ obl,
             float* __restrict__ pout,
             int nrows, int ntiles, int logit_off)
{
    extern __shared__ uint sm[];
    float* sp = (float*)(sm + CTRL_W + 128);

    const int tid = threadIdx.x;
    const int lane = tid & 31, w = tid >> 5;
    const int wm = (w & 3) * 32, wn = (w >> 2) * 64;

    load_weights<8>(sm, Wth, Wtl, tid);

    for (int t = blockIdx.x; t < ntiles; t += gridDim.x) {
        const int t0 = t * 128;
        {
            int r = tid >> 1, hh = tid & 1, ch = hh * 64;
            int gr = t0 + r;
            int rr = (gr < nrows) ? gr : 0;
            int i0 = idx0 ? __ldg(&idx0[rr]) : rr;
            int i1 = idx1 ? __ldg(&idx1[rr]) : rr;
            const float4* xp = (const float4*)(X + (size_t)i0 * H + ch);
            const float4* yp = (const float4*)(Y + (size_t)i1 * H + ch);
            int base = r * WROW + hh * 32;
#pragma unroll
            for (int q = 0; q < 16; q++) {
                float4 xv = xp[q], yv = yp[q];
                int c = ch + q * 4;
                float v0 = fmaxf(xv.x + yv.x + __ldg(&b1[c]),     0.f);
                float v1 = fmaxf(xv.y + yv.y + __ldg(&b1[c + 1]), 0.f);
                float v2 = fmaxf(xv.z + yv.z + __ldg(&b1[c + 2]), 0.f);
                float v3 = fmaxf(xv.w + yv.w + __ldg(&b1[c + 3]), 0.f);
                *(uint2*)(sm + AH_W + base + 2 * q) = make_uint2(phi(v0, v1), phi(v2, v3));
                *(uint2*)(sm + AL_W + base + 2 * q) = make_uint2(plo(v0, v1), plo(v2, v3));
            }
        }
        __syncthreads();

        float acc[2][8][4];
#pragma unroll
        for (int mf = 0; mf < 2; mf++)
#pragma unroll
            for (int nf = 0; nf < 8; nf++)
#pragma unroll
                for (int q = 0; q < 4; q++) acc[mf][nf][q] = 0.f;
        gemm_core<8>(sm, acc, wm, wn, lane);
        __syncthreads();

        if (EPI == 1) {
#pragma unroll
            for (int mf = 0; mf < 2; mf++)
#pragma unroll
                for (int nf = 0; nf < 8; nf++) {
                    int row = wm + mf * 16 + (lane >> 2);
                    int col = wn + nf * 8 + (lane & 3) * 2;
                    int g0 = t0 + row, g1 = g0 + 8;
                    float b0 = __ldg(&b2[col]), b1v = __ldg(&b2[col + 1]);
                    float v0 = fmaxf(acc[mf][nf][0] + b0, 0.f);
                    float v1 = fmaxf(acc[mf][nf][1] + b1v, 0.f);
                    float v2 = fmaxf(acc[mf][nf][2] + b0, 0.f);
                    float v3 = fmaxf(acc[mf][nf][3] + b1v, 0.f);
                    int wi = col >> 1;
                    if (g0 < nrows) {
                        ((uint*)obh)[(size_t)g0 * 64 + wi] = phi(v0, v1);
                        ((uint*)obl)[(size_t)g0 * 64 + wi] = plo(v0, v1);
                    }
                    if (g1 < nrows) {
                        ((uint*)obh)[(size_t)g1 * 64 + wi] = phi(v2, v3);
                        ((uint*)obl)[(size_t)g1 * 64 + wi] = plo(v2, v3);
                    }
                }
        } else {
            float p[2][2] = {{0.f, 0.f}, {0.f, 0.f}};
#pragma unroll
            for (int mf = 0; mf < 2; mf++)
#pragma unroll
                for (int nf = 0; nf < 8; nf++) {
                    int col = wn + nf * 8 + (lane & 3) * 2;
                    float b0 = __ldg(&b2[col]), b1v = __ldg(&b2[col + 1]);
                    float w30 = __ldg(&W3[col]), w31 = __ldg(&W3[col + 1]);
                    p[mf][0] += fmaxf(acc[mf][nf][0] + b0, 0.f) * w30
                              + fmaxf(acc[mf][nf][1] + b1v, 0.f) * w31;
                    p[mf][1] += fmaxf(acc[mf][nf][2] + b0, 0.f) * w30
                              + fmaxf(acc[mf][nf][3] + b1v, 0.f) * w31;
                }
#pragma unroll
            for (int mf = 0; mf < 2; mf++)
#pragma unroll
                for (int hq = 0; hq < 2; hq++) {
                    float v = p[mf][hq];
                    v += __shfl_xor_sync(0xFFFFFFFFu, v, 1);
                    v += __shfl_xor_sync(0xFFFFFFFFu, v, 2);
                    if ((lane & 3) == 0) {
                        int row = wm + mf * 16 + (lane >> 2) + hq * 8;
                        sp[row + 128 * (wn >> 6)] = v;
                    }
                }
            __syncthreads();
            if (tid < 128) {
                int r = t0 + tid;
                if (r < nrows) {
                    float s = sp[tid] + sp[tid + 128] + __ldg(&b3[0]);
                    pout[r] = 1.f / (1.f + expf(-s));
                    if (logit_off > 0) pout[logit_off + r] = s;
                }
            }
        }
        __syncthreads();
    }
}

// ---------------- host ----------------
extern "C" void kernel_launch(void* const* d_in, const int* in_sizes, int n_in,
                              void* d_out, int out_size) {
    const float* feat    = (const float*)d_in[0];
    const int*   adj_dst = (const int*)  d_in[1];
    const int*   adj_src = (const int*)  d_in[2];
    const int*   cand_i  = (const int*)  d_in[3];
    const int*   cand_j  = (const int*)  d_in[4];
    const float* enc_W1 = (const float*)d_in[5];
    const float* enc_b1 = (const float*)d_in[6];
    const float* enc_W2 = (const float*)d_in[7];
    const float* enc_b2 = (const float*)d_in[8];
    const float* msg_W1 = (const float*)d_in[9];
    const float* msg_b1 = (const float*)d_in[10];
    const float* msg_W2 = (const float*)d_in[11];
    const float* msg_b2 = (const float*)d_in[12];
    const float* upd_W1 = (const float*)d_in[13];
    const float* upd_b1 = (const float*)d_in[14];
    const float* upd_W2 = (const float*)d_in[15];
    const float* upd_b2 = (const float*)d_in[16];
    const float* pred_W1 = (const float*)d_in[17];
    const float* pred_b1 = (const float*)d_in[18];
    const float* pred_W2 = (const float*)d_in[19];
    const float* pred_b2 = (const float*)d_in[20];
    const float* pred_W3 = (const float*)d_in[21];
    const float* pred_b3 = (const float*)d_in[22];

    int NE = in_sizes[0] / 64;
    int NA = in_sizes[1];
    int NC = in_sizes[3];
    if (NE > NE_MAX) NE = NE_MAX;

    float *P, *Q, *Hagg, *bc;
    int* deg;
    u16 *eh, *el, *e2h, *e2l, *wh, *wl;
    cudaGetSymbolAddress((void**)&P,    g_P);
    cudaGetSymbolAddress((void**)&Q,    g_Q);
    cudaGetSymbolAddress((void**)&Hagg, g_agg);
    cudaGetSymbolAddress((void**)&deg,  g_deg);
    cudaGetSymbolAddress((void**)&bc,   g_bc);
    cudaGetSymbolAddress((void**)&eh,   g_eh);
    cudaGetSymbolAddress((void**)&el,   g_el);
    cudaGetSymbolAddress((void**)&e2h,  g_e2h);
    cudaGetSymbolAddress((void**)&e2l,  g_e2l);
    cudaGetSymbolAddress((void**)&wh,   g_wh);
    cudaGetSymbolAddress((void**)&wl,   g_wl);

    cudaFuncSetAttribute(gk_plain<2, 4, 1>, cudaFuncAttributeMaxDynamicSharedMemorySize, SMEM_BYTES);
    cudaFuncSetAttribute(gk_plain<0, 8, 2>, cudaFuncAttributeMaxDynamicSharedMemorySize, SMEM_BYTES);
    cudaFuncSetAttribute(gk_plain<0, 8, 0>, cudaFuncAttributeMaxDynamicSharedMemorySize, SMEM_BYTES);
    cudaFuncSetAttribute(gk_plain<1, 8, 3>, cudaFuncAttributeMaxDynamicSharedMemorySize, SMEM_BYTES);
    cudaFuncSetAttribute(gk_pair<1>, cudaFuncAttributeMaxDynamicSharedMemorySize, SMEM_BYTES);
    cudaFuncSetAttribute(gk_pair<2>, cudaFuncAttributeMaxDynamicSharedMemorySize, SMEM_BYTES);

    cudaMemsetAsync(deg, 0, (size_t)NE * sizeof(int));
    deg_kernel<<<(NA + 255) / 256, 256>>>(adj_dst, NA, deg);

    // ---- weight prep: one kernel for all transposed splits ----
    PJobs pj;
    int cursor = 0, nj = 0;
    auto addjob = [&](const float* W, int ro, int K, int off) {
        pj.W[nj] = W; pj.rowoff[nj] = ro; pj.K[nj] = K; pj.off[nj] = off;
        pj.start[nj] = cursor; cursor += 128 * K; nj++;
    };
    addjob(enc_W1, 0, 64, OFF_ENC1);
    addjob(enc_W2, 0, 128, OFF_ENC2);
    for (int l = 0; l < 3; l++) {
        const float* mW1 = msg_W1 + (size_t)l * 2 * H * H;
        const float* uW1 = upd_W1 + (size_t)l * 2 * H * H;
        const float* uW2 = upd_W2 + (size_t)l * H * H;
        addjob(mW1, 0,   128, OFF_W1T(l));
        addjob(mW1, 128, 128, OFF_W1B(l));
        addjob(uW1, 0,   128, OFF_U1T(l));
        addjob(uW2, 0,   128, OFF_UW2(l));
    }
    addjob(pred_W1, 0,   128, OFF_P1T);
    addjob(pred_W1, 128, 128, OFF_P1B);
    addjob(pred_W2, 0,   128, OFF_P2);
    pj.njobs = nj; pj.total = cursor;
    prep_all<<<(cursor + 255) / 256, 256>>>(pj);
    compprep<<<195, 256>>>(upd_W1, msg_W2, msg_b2);

    int gNE = (NE + 127) / 128;
    int gNC = (NC + 127) / 128;
    int gE = gNE < 148 ? gNE : 148;
    int gC = gNC < 148 ? gNC : 148;

    // encoder
    gk_plain<2, 4, 1><<<gE, 256, SMEM_BYTES>>>(
        feat, nullptr, nullptr, wh + OFF_ENC1, wl + OFF_ENC1,
        enc_b1, deg, nullptr, e2h, e2l, NE, gNE);
    gk_plain<0, 8, 2><<<gE, 256, SMEM_BYTES>>>(
        nullptr, e2h, e2l, wh + OFF_ENC2, wl + OFF_ENC2,
        enc_b2, deg, nullptr, eh, el, NE, gNE);

    u16 *ch = eh, *cl = el, *nh = e2h, *nl = e2l;
    for (int l = 0; l < 3; l++) {
        const float* mb1 = msg_b1 + (size_t)l * H;
        const float* ub1 = upd_b1 + (size_t)l * H;
        const float* ub2 = upd_b2 + (size_t)l * H;

        // P = e@W1top, Q = e@W1bot (fp32, no bias; msum adds b1)
        gk_plain<0, 8, 0><<<gE, 256, SMEM_BYTES>>>(
            nullptr, ch, cl, wh + OFF_W1T(l), wl + OFF_W1T(l),
            nullptr, deg, P, nullptr, nullptr, NE, gNE);
        gk_plain<0, 8, 0><<<gE, 256, SMEM_BYTES>>>(
            nullptr, ch, cl, wh + OFF_W1B(l), wl + OFF_W1B(l),
            nullptr, deg, Q, nullptr, nullptr, NE, gNE);

        // Hagg = segment_sum(ReLU(P[dst]+Q[src]+b1)); iso fixup
        cudaMemsetAsync(Hagg, 0, (size_t)NE * H * sizeof(float));
        msum<<<(NA + 127) / 128, 256>>>(P, Q, mb1, adj_dst, adj_src, Hagg, NA);
        fixup<<<(NE + 255) / 256, 256>>>(P, Q, mb1, deg, Hagg, NE);

        // T = e@U1top -> P;  U = (Hagg*inv_deg)@Wcomp + bcomp -> Q
        gk_plain<0, 8, 0><<<gE, 256, SMEM_BYTES>>>(
            nullptr, ch, cl, wh + OFF_U1T(l), wl + OFF_U1T(l),
            nullptr, deg, P, nullptr, nullptr, NE, gNE);
        gk_plain<1, 8, 3><<<gE, 256, SMEM_BYTES>>>(
            Hagg, nullptr, nullptr, wh + OFF_WC(l), wl + OFF_WC(l),
            bc + l * H, deg, Q, nullptr, nullptr, NE, gNE);

        // e' = ReLU(ReLU(T+U+ub1)@U2+ub2)
        gk_pair<1><<<gE, 256, SMEM_BYTES>>>(
            P, Q, nullptr, nullptr, wh + OFF_UW2(l), wl + OFF_UW2(l),
            ub1, ub2, nullptr, nullptr, nh, nl, nullptr, NE, gNE, 0);

        u16* t1 = ch; ch = nh; nh = t1;
        u16* t2 = cl; cl = nl; nl = t2;
    }

    // predictor
    gk_plain<0, 8, 0><<<gE, 256, SMEM_BYTES>>>(
        nullptr, ch, cl, wh + OFF_P1T, wl + OFF_P1T,
        nullptr, deg, P, nullptr, nullptr, NE, gNE);
    gk_plain<0, 8, 0><<<gE, 256, SMEM_BYTES>>>(
        nullptr, ch, cl, wh + OFF_P1B, wl + OFF_P1B,
        nullptr, deg, Q, nullptr, nullptr, NE, gNE);
    int logit_off = (out_size >= 2 * NC) ? NC : -1;
    gk_pair<2><<<gC, 256, SMEM_BYTES>>>(
        P, Q, cand_i, cand_j, wh + OFF_P2, wl + OFF_P2,
        pred_b1, pred_b2, pred_W3, pred_b3,
        nullptr, nullptr, (float*)d_out, NC, gNC, logit_off);
}

// round 8
// speedup vs baseline: 10.5342x; 1.0142x over previous
#include <cuda_runtime.h>
#include <cuda_bf16.h>
#include <stdint.h>
#include <math.h>

#define H 128
#define NE_MAX 50000

typedef unsigned int uint;
typedef unsigned short u16;

// ---------------- device scratch (allocation-free rule) ----------------
__device__ u16   g_eh [NE_MAX * H];
__device__ u16   g_el [NE_MAX * H];
__device__ u16   g_e2h[NE_MAX * H];
__device__ u16   g_e2l[NE_MAX * H];
__device__ float g_P  [NE_MAX * H];
__device__ float g_Q  [NE_MAX * H];
__device__ float g_agg[NE_MAX * H];     // Hagg
__device__ int   g_deg[NE_MAX];
__device__ float g_bc [3 * H];          // composite biases
#define WSCRATCH 368640
__device__ u16 g_wh[WSCRATCH];
__device__ u16 g_wl[WSCRATCH];

// transposed/split weight offsets (elements)
#define OFF_ENC1 0
#define OFF_ENC2 8192
#define OFF_L(l)   (24576 + (l) * 98304)
#define OFF_W1T(l) (OFF_L(l))
#define OFF_W1B(l) (OFF_L(l) + 16384)
#define OFF_WC(l)  (OFF_L(l) + 32768)   // composite W2@U1bot
#define OFF_U1T(l) (OFF_L(l) + 49152)
#define OFF_UW2(l) (OFF_L(l) + 81920)
#define OFF_P1T 319488
#define OFF_P1B 335872
#define OFF_P2  352256

// smem word offsets; weight row stride 68 words (=136 u16), M-tile 64
#define WROW 68
#define WH_W 0
#define WL_W 8704
#define AH_W 17408
#define AL_W 21760
#define CTRL_W 26112
#define SMEM_WORDS 26400
#define SMEM_BYTES (SMEM_WORDS * 4)

// ---------------- helpers ----------------
__device__ __forceinline__ uint phi(float a, float b) {
    return (uint)__bfloat16_as_ushort(__float2bfloat16_rn(a))
         | ((uint)__bfloat16_as_ushort(__float2bfloat16_rn(b)) << 16);
}
__device__ __forceinline__ uint plo(float a, float b) {
    float ah = __bfloat162float(__float2bfloat16_rn(a));
    float bh = __bfloat162float(__float2bfloat16_rn(b));
    return phi(a - ah, b - bh);
}

__device__ __forceinline__ void mma_bf(float* c, uint a0, uint a1, uint a2, uint a3,
                                       uint b0, uint b1) {
    asm volatile(
        "mma.sync.aligned.m16n8k16.row.col.f32.bf16.bf16.f32 "
        "{%0,%1,%2,%3},{%4,%5,%6,%7},{%8,%9},{%0,%1,%2,%3};"
        : "+f"(c[0]), "+f"(c[1]), "+f"(c[2]), "+f"(c[3])
        : "r"(a0), "r"(a1), "r"(a2), "r"(a3), "r"(b0), "r"(b1));
}

// warp tile 32x32: acc[2][4][4]; 8 warps = 2 (M) x 4 (N); M-tile 64, N 128
template <int NK>
__device__ __forceinline__ void gemm_core(const uint* sm, float acc[2][4][4],
                                          int wm, int wn, int lane) {
    const int lg = lane >> 2, lt = lane & 3;
#pragma unroll
    for (int ks = 0; ks < NK; ks++) {
        const int kw = ks * 8 + lt;
        uint ah[2][4], al[2][4];
#pragma unroll
        for (int mf = 0; mf < 2; mf++) {
            int base = (wm + mf * 16 + lg) * WROW + kw;
            ah[mf][0] = sm[AH_W + base];
            ah[mf][1] = sm[AH_W + base + 8 * WROW];
            ah[mf][2] = sm[AH_W + base + 4];
            ah[mf][3] = sm[AH_W + base + 8 * WROW + 4];
            al[mf][0] = sm[AL_W + base];
            al[mf][1] = sm[AL_W + base + 8 * WROW];
            al[mf][2] = sm[AL_W + base + 4];
            al[mf][3] = sm[AL_W + base + 8 * WROW + 4];
        }
#pragma unroll
        for (int nf = 0; nf < 4; nf++) {
            int bb = (wn + nf * 8 + lg) * WROW + kw;
            uint bh0 = sm[WH_W + bb], bh1 = sm[WH_W + bb + 4];
            uint bl0 = sm[WL_W + bb], bl1 = sm[WL_W + bb + 4];
#pragma unroll
            for (int mf = 0; mf < 2; mf++) {
                mma_bf(acc[mf][nf], ah[mf][0], ah[mf][1], ah[mf][2], ah[mf][3], bh0, bh1);
                mma_bf(acc[mf][nf], ah[mf][0], ah[mf][1], ah[mf][2], ah[mf][3], bl0, bl1);
                mma_bf(acc[mf][nf], al[mf][0], al[mf][1], al[mf][2], al[mf][3], bh0, bh1);
            }
        }
    }
}

template <int NK>
__device__ __forceinline__ void load_weights(uint* sm, const u16* Wth, const u16* Wtl,
                                             int tid) {
    const int nv = 128 * NK * 2;
    const uint4* sh = (const uint4*)Wth;
    const uint4* sl = (const uint4*)Wtl;
    for (int i = tid; i < nv; i += 256) {
        int n = i / (NK * 2), q = i % (NK * 2);
        *(uint4*)(sm + WH_W + n * WROW + q * 4) = sh[i];
        *(uint4*)(sm + WL_W + n * WROW + q * 4) = sl[i];
    }
}

// ---------------- small kernels ----------------
__global__ void deg_kernel(const int* __restrict__ dst, int na, int* __restrict__ deg) {
    int i = blockIdx.x * blockDim.x + threadIdx.x;
    if (i < na) atomicAdd(&deg[dst[i]], 1);
}

struct PJobs {
    const float* W[20];
    int rowoff[20], K[20], off[20], start[20];
    int njobs, total;
};
__global__ void prep_all(PJobs j) {
    int i = blockIdx.x * 256 + threadIdx.x;
    if (i >= j.total) return;
    int a = 0;
    while (a + 1 < j.njobs && i >= j.start[a + 1]) a++;
    int e = i - j.start[a];
    int K = j.K[a];
    int n = e / K, k = e % K;
    float v = j.W[a][(size_t)(j.rowoff[a] + k) * 128 + n];
    __nv_bfloat16 h = __float2bfloat16_rn(v);
    g_wh[j.off[a] + e] = __bfloat16_as_ushort(h);
    g_wl[j.off[a] + e] = __bfloat16_as_ushort(__float2bfloat16_rn(v - __bfloat162float(h)));
}

__global__ void compprep(const float* __restrict__ upd_W1,
                         const float* __restrict__ msg_W2,
                         const float* __restrict__ msg_b2) {
    int b = blockIdx.x;
    if (b < 192) {
        int l = b >> 6;
        int i = (b & 63) * 256 + threadIdx.x;
        int o = i & 127, h = i >> 7;
        const float* W2  = msg_W2 + (size_t)l * 16384;
        const float* U1b = upd_W1 + (size_t)l * 32768 + 16384;
        float s = 0.f;
        for (int a2 = 0; a2 < 128; a2++) s += W2[h * 128 + a2] * U1b[a2 * 128 + o];
        int li = OFF_WC(l) + o * 128 + h;
        __nv_bfloat16 hh = __float2bfloat16_rn(s);
        g_wh[li] = __bfloat16_as_ushort(hh);
        g_wl[li] = __bfloat16_as_ushort(__float2bfloat16_rn(s - __bfloat162float(hh)));
    } else if (b < 195) {
        int l = b - 192;
        int o = threadIdx.x;
        if (o < 128) {
            const float* U1b = upd_W1 + (size_t)l * 32768 + 16384;
            const float* b2  = msg_b2 + (size_t)l * 128;
            float s = 0.f;
            for (int a2 = 0; a2 < 128; a2++) s += b2[a2] * U1b[a2 * 128 + o];
            g_bc[l * 128 + o] = s;
        }
    }
}

// pair hidden aggregation: Hagg[dst] += ReLU(P[dst] + Q[src] + b1)
__global__ __launch_bounds__(256) void msum(const float* __restrict__ P,
                                            const float* __restrict__ Q,
                                            const float* __restrict__ b1,
                                            const int* __restrict__ dst,
                                            const int* __restrict__ src,
                                            float* __restrict__ Hagg, int na) {
    int team = threadIdx.x >> 7, col = threadIdx.x & 127;
    int p0 = blockIdx.x * 128 + team * 64;
    if (p0 >= na) return;
    float bias = __ldg(&b1[col]);
    float sum = 0.f, pv = 0.f;
    int cur = -1;
    for (int base = 0; base < 64; base += 8) {
        int dd[8], ss[8];
#pragma unroll
        for (int j = 0; j < 8; j++) {
            int a = p0 + base + j;
            bool v = a < na;
            dd[j] = v ? __ldg(&dst[a]) : -1;
            ss[j] = v ? __ldg(&src[a]) : 0;
        }
        float qv[8];
#pragma unroll
        for (int j = 0; j < 8; j++) qv[j] = __ldg(&Q[(size_t)ss[j] * H + col]);
#pragma unroll
        for (int j = 0; j < 8; j++) {
            if (dd[j] != cur) {
                if (cur >= 0) atomicAdd(&Hagg[(size_t)cur * H + col], sum);
                cur = dd[j];
                sum = 0.f;
                if (cur >= 0) pv = __ldg(&P[(size_t)cur * H + col]) + bias;
            }
            if (dd[j] >= 0) sum += fmaxf(pv + qv[j], 0.f);
        }
    }
    if (cur >= 0) atomicAdd(&Hagg[(size_t)cur * H + col], sum);
}

__global__ void fixup(const float* __restrict__ P, const float* __restrict__ Q,
                      const float* __restrict__ b1, const int* __restrict__ deg,
                      float* __restrict__ Hagg, int ne) {
    int n = blockIdx.x * 256 + threadIdx.x;
    if (n >= ne || deg[n] != 0) return;
    for (int c = 0; c < H; c++)
        Hagg[(size_t)n * H + c] = fmaxf(P[(size_t)n * H + c] + Q[(size_t)n * H + c] + b1[c], 0.f);
}

// ---------------- plain GEMM (M-tile 64): out = epi( A @ Wt ) ----------------
// AK: 0 = bf16 hi/lo input, 1 = fp32 * inv_deg, 2 = fp32 plain
// EPI: 0 = fp32 raw, 1 = bias+ReLU -> bf16 pair, 2 = bias -> bf16 pair, 3 = fp32 + bias
template <int AK, int NK, int EPI>
__global__ __launch_bounds__(256, 2)
void gk_plain(const float* __restrict__ Af,
              const u16* __restrict__ Aph, const u16* __restrict__ Apl,
              const u16* __restrict__ Wth, const u16* __restrict__ Wtl,
              const float* __restrict__ bias, const int* __restrict__ deg,
              float* __restrict__ outf, u16* __restrict__ obh, u16* __restrict__ obl,
              int nrows, int ntiles)
{
    extern __shared__ uint sm[];
    const int tid = threadIdx.x;
    const int lane = tid & 31, w = tid >> 5;
    const int wm = (w & 1) * 32, wn = (w >> 1) * 32;

    load_weights<NK>(sm, Wth, Wtl, tid);

    for (int t = blockIdx.x; t < ntiles; t += gridDim.x) {
        const int t0 = t * 64;
        {
            int r = tid >> 2, q4 = tid & 3;
            int gr = t0 + r;
            int rr = (gr < nrows) ? gr : 0;
            int base = r * WROW + q4 * (NK * 2);
            if (AK == 0) {
                const uint4* s  = (const uint4*)Aph + (size_t)rr * (NK * 2) + q4 * (NK / 2);
                const uint4* sl = (const uint4*)Apl + (size_t)rr * (NK * 2) + q4 * (NK / 2);
#pragma unroll
                for (int j = 0; j < NK / 2; j++) {
                    *(uint4*)(sm + AH_W + base + j * 4) = s[j];
                    *(uint4*)(sm + AL_W + base + j * 4) = sl[j];
                }
            } else {
                float sc = 1.f;
                if (AK == 1) { int d = deg[rr]; sc = 1.f / (d > 1 ? (float)d : 1.f); }
                const float4* s = (const float4*)(Af + (size_t)rr * (NK * 16)) + q4 * NK;
#pragma unroll
                for (int q = 0; q < NK; q++) {
                    float4 v = s[q];
                    if (AK == 1) { v.x *= sc; v.y *= sc; v.z *= sc; v.w *= sc; }
                    *(uint2*)(sm + AH_W + base + 2 * q) = make_uint2(phi(v.x, v.y), phi(v.z, v.w));
                    *(uint2*)(sm + AL_W + base + 2 * q) = make_uint2(plo(v.x, v.y), plo(v.z, v.w));
                }
            }
        }
        __syncthreads();

        float acc[2][4][4];
#pragma unroll
        for (int mf = 0; mf < 2; mf++)
#pragma unroll
            for (int nf = 0; nf < 4; nf++)
#pragma unroll
                for (int q = 0; q < 4; q++) acc[mf][nf][q] = 0.f;
        gemm_core<NK>(sm, acc, wm, wn, lane);
        __syncthreads();

#pragma unroll
        for (int mf = 0; mf < 2; mf++)
#pragma unroll
            for (int nf = 0; nf < 4; nf++) {
                int row = wm + mf * 16 + (lane >> 2);
                int col = wn + nf * 8 + (lane & 3) * 2;
                int g0 = t0 + row, g1 = g0 + 8;
                if (EPI == 0) {
                    if (g0 < nrows)
                        *(float2*)&outf[(size_t)g0 * H + col] = make_float2(acc[mf][nf][0], acc[mf][nf][1]);
                    if (g1 < nrows)
                        *(float2*)&outf[(size_t)g1 * H + col] = make_float2(acc[mf][nf][2], acc[mf][nf][3]);
                } else if (EPI == 3) {
                    float b0 = __ldg(&bias[col]), b1v = __ldg(&bias[col + 1]);
                    if (g0 < nrows)
                        *(float2*)&outf[(size_t)g0 * H + col] = make_float2(acc[mf][nf][0] + b0, acc[mf][nf][1] + b1v);
                    if (g1 < nrows)
                        *(float2*)&outf[(size_t)g1 * H + col] = make_float2(acc[mf][nf][2] + b0, acc[mf][nf][3] + b1v);
                } else {
                    float b0 = __ldg(&bias[col]), b1v = __ldg(&bias[col + 1]);
                    float v0 = acc[mf][nf][0] + b0, v1 = acc[mf][nf][1] + b1v;
                    float v2 = acc[mf][nf][2] + b0, v3 = acc[mf][nf][3] + b1v;
                    if (EPI == 1) {
                        v0 = fmaxf(v0, 0.f); v1 = fmaxf(v1, 0.f);
                        v2 = fmaxf(v2, 0.f); v3 = fmaxf(v3, 0.f);
                    }
                    int wi = col >> 1;
                    if (g0 < nrows) {
                        ((uint*)obh)[(size_t)g0 * 64 + wi] = phi(v0, v1);
                        ((uint*)obl)[(size_t)g0 * 64 + wi] = plo(v0, v1);
                    }
                    if (g1 < nrows) {
                        ((uint*)obh)[(size_t)g1 * 64 + wi] = phi(v2, v3);
                        ((uint*)obl)[(size_t)g1 * 64 + wi] = plo(v2, v3);
                    }
                }
            }
        __syncthreads();
    }
}

// ---------------- pairsum GEMM (M-tile 64): hid = ReLU(X[i0]+Y[i1]+b1); out = epi(hid @ Wt) ----
// EPI: 1 = b2+ReLU -> bf16 pair (update), 2 = predictor
template <int EPI>
__global__ __launch_bounds__(256, 2)
void gk_pair(const float* __restrict__ X, const float* __restrict__ Y,
             const int* __restrict__ idx0, const int* __restrict__ idx1,
             const u16* __restrict__ Wth, const u16* __restrict__ Wtl,
             const float* __restrict__ b1, const float* __restrict__ b2,
             const float* __restrict__ W3, const float* __restrict__ b3,
             u16* __restrict__ obh, u16* __restrict__ obl,
             float* __restrict__ pout,
             int nrows, int ntiles, int logit_off)
{
    extern __shared__ uint sm[];
    float* sp = (float*)(sm + CTRL_W);

    const int tid = threadIdx.x;
    const int lane = tid & 31, w = tid >> 5;
    const int wm = (w & 1) * 32, wn = (w >> 1) * 32;

    load_weights<8>(sm, Wth, Wtl, tid);

    for (int t = blockIdx.x; t < ntiles; t += gridDim.x) {
        const int t0 = t * 64;
        {
            int r = tid >> 2, q4 = tid & 3, ch = q4 * 32;
            int gr = t0 + r;
            int rr = (gr < nrows) ? gr : 0;
            int i0 = idx0 ? __ldg(&idx0[rr]) : rr;
            int i1 = idx1 ? __ldg(&idx1[rr]) : rr;
            const float4* xp = (const float4*)(X + (size_t)i0 * H + ch);
            const float4* yp = (const float4*)(Y + (size_t)i1 * H + ch);
            int base = r * WROW + q4 * 16;
#pragma unroll
            for (int q = 0; q < 8; q++) {
                float4 xv = xp[q], yv = yp[q];
                int c = ch + q * 4;
                float v0 = fmaxf(xv.x + yv.x + __ldg(&b1[c]),     0.f);
                float v1 = fmaxf(xv.y + yv.y + __ldg(&b1[c + 1]), 0.f);
                float v2 = fmaxf(xv.z + yv.z + __ldg(&b1[c + 2]), 0.f);
                float v3 = fmaxf(xv.w + yv.w + __ldg(&b1[c + 3]), 0.f);
                *(uint2*)(sm + AH_W + base + 2 * q) = make_uint2(phi(v0, v1), phi(v2, v3));
                *(uint2*)(sm + AL_W + base + 2 * q) = make_uint2(plo(v0, v1), plo(v2, v3));
            }
        }
        __syncthreads();

        float acc[2][4][4];
#pragma unroll
        for (int mf = 0; mf < 2; mf++)
#pragma unroll
            for (int nf = 0; nf < 4; nf++)
#pragma unroll
                for (int q = 0; q < 4; q++) acc[mf][nf][q] = 0.f;
        gemm_core<8>(sm, acc, wm, wn, lane);
        __syncthreads();

        if (EPI == 1) {
#pragma unroll
            for (int mf = 0; mf < 2; mf++)
#pragma unroll
                for (int nf = 0; nf < 4; nf++) {
                    int row = wm + mf * 16 + (lane >> 2);
                    int col = wn + nf * 8 + (lane & 3) * 2;
                    int g0 = t0 + row, g1 = g0 + 8;
                    float b0 = __ldg(&b2[col]), b1v = __ldg(&b2[col + 1]);
                    float v0 = fmaxf(acc[mf][nf][0] + b0, 0.f);
                    float v1 = fmaxf(acc[mf][nf][1] + b1v, 0.f);
                    float v2 = fmaxf(acc[mf][nf][2] + b0, 0.f);
                    float v3 = fmaxf(acc[mf][nf][3] + b1v, 0.f);
                    int wi = col >> 1;
                    if (g0 < nrows) {
                        ((uint*)obh)[(size_t)g0 * 64 + wi] = phi(v0, v1);
                        ((uint*)obl)[(size_t)g0 * 64 + wi] = plo(v0, v1);
                    }
                    if (g1 < nrows) {
                        ((uint*)obh)[(size_t)g1 * 64 + wi] = phi(v2, v3);
                        ((uint*)obl)[(size_t)g1 * 64 + wi] = plo(v2, v3);
                    }
                }
        } else {
            float p[2][2] = {{0.f, 0.f}, {0.f, 0.f}};
#pragma unroll
            for (int mf = 0; mf < 2; mf++)
#pragma unroll
                for (int nf = 0; nf < 4; nf++) {
                    int col = wn + nf * 8 + (lane & 3) * 2;
                    float b0 = __ldg(&b2[col]), b1v = __ldg(&b2[col + 1]);
                    float w30 = __ldg(&W3[col]), w31 = __ldg(&W3[col + 1]);
                    p[mf][0] += fmaxf(acc[mf][nf][0] + b0, 0.f) * w30
                              + fmaxf(acc[mf][nf][1] + b1v, 0.f) * w31;
                    p[mf][1] += fmaxf(acc[mf][nf][2] + b0, 0.f) * w30
                              + fmaxf(acc[mf][nf][3] + b1v, 0.f) * w31;
                }
#pragma unroll
            for (int mf = 0; mf < 2; mf++)
#pragma unroll
                for (int hq = 0; hq < 2; hq++) {
                    float v = p[mf][hq];
                    v += __shfl_xor_sync(0xFFFFFFFFu, v, 1);
                    v += __shfl_xor_sync(0xFFFFFFFFu, v, 2);
                    if ((lane & 3) == 0) {
                        int row = wm + mf * 16 + (lane >> 2) + hq * 8;
                        sp[row + 64 * (wn >> 5)] = v;
                    }
                }
            __syncthreads();
            if (tid < 64) {
                int r = t0 + tid;
                if (r < nrows) {
                    float s = sp[tid] + sp[tid + 64] + sp[tid + 128] + sp[tid + 192] + __ldg(&b3[0]);
                    pout[r] = 1.f / (1.f + expf(-s));
                    if (logit_off > 0) pout[logit_off + r] = s;
                }
            }
        }
        __syncthreads();
    }
}

// ---------------- host ----------------
extern "C" void kernel_launch(void* const* d_in, const int* in_sizes, int n_in,
                              void* d_out, int out_size) {
    const float* feat    = (const float*)d_in[0];
    const int*   adj_dst = (const int*)  d_in[1];
    const int*   adj_src = (const int*)  d_in[2];
    const int*   cand_i  = (const int*)  d_in[3];
    const int*   cand_j  = (const int*)  d_in[4];
    const float* enc_W1 = (const float*)d_in[5];
    const float* enc_b1 = (const float*)d_in[6];
    const float* enc_W2 = (const float*)d_in[7];
    const float* enc_b2 = (const float*)d_in[8];
    const float* msg_W1 = (const float*)d_in[9];
    const float* msg_b1 = (const float*)d_in[10];
    const float* msg_W2 = (const float*)d_in[11];
    const float* msg_b2 = (const float*)d_in[12];
    const float* upd_W1 = (const float*)d_in[13];
    const float* upd_b1 = (const float*)d_in[14];
    const float* upd_W2 = (const float*)d_in[15];
    const float* upd_b2 = (const float*)d_in[16];
    const float* pred_W1 = (const float*)d_in[17];
    const float* pred_b1 = (const float*)d_in[18];
    const float* pred_W2 = (const float*)d_in[19];
    const float* pred_b2 = (const float*)d_in[20];
    const float* pred_W3 = (const float*)d_in[21];
    const float* pred_b3 = (const float*)d_in[22];

    int NE = in_sizes[0] / 64;
    int NA = in_sizes[1];
    int NC = in_sizes[3];
    if (NE > NE_MAX) NE = NE_MAX;

    float *P, *Q, *Hagg, *bc;
    int* deg;
    u16 *eh, *el, *e2h, *e2l, *wh, *wl;
    cudaGetSymbolAddress((void**)&P,    g_P);
    cudaGetSymbolAddress((void**)&Q,    g_Q);
    cudaGetSymbolAddress((void**)&Hagg, g_agg);
    cudaGetSymbolAddress((void**)&deg,  g_deg);
    cudaGetSymbolAddress((void**)&bc,   g_bc);
    cudaGetSymbolAddress((void**)&eh,   g_eh);
    cudaGetSymbolAddress((void**)&el,   g_el);
    cudaGetSymbolAddress((void**)&e2h,  g_e2h);
    cudaGetSymbolAddress((void**)&e2l,  g_e2l);
    cudaGetSymbolAddress((void**)&wh,   g_wh);
    cudaGetSymbolAddress((void**)&wl,   g_wl);

    cudaFuncSetAttribute(gk_plain<2, 4, 1>, cudaFuncAttributeMaxDynamicSharedMemorySize, SMEM_BYTES);
    cudaFuncSetAttribute(gk_plain<0, 8, 2>, cudaFuncAttributeMaxDynamicSharedMemorySize, SMEM_BYTES);
    cudaFuncSetAttribute(gk_plain<0, 8, 0>, cudaFuncAttributeMaxDynamicSharedMemorySize, SMEM_BYTES);
    cudaFuncSetAttribute(gk_plain<1, 8, 3>, cudaFuncAttributeMaxDynamicSharedMemorySize, SMEM_BYTES);
    cudaFuncSetAttribute(gk_pair<1>, cudaFuncAttributeMaxDynamicSharedMemorySize, SMEM_BYTES);
    cudaFuncSetAttribute(gk_pair<2>, cudaFuncAttributeMaxDynamicSharedMemorySize, SMEM_BYTES);

    cudaMemsetAsync(deg, 0, (size_t)NE * sizeof(int));
    deg_kernel<<<(NA + 255) / 256, 256>>>(adj_dst, NA, deg);

    // ---- weight prep ----
    PJobs pj;
    int cursor = 0, nj = 0;
    auto addjob = [&](const float* W, int ro, int K, int off) {
        pj.W[nj] = W; pj.rowoff[nj] = ro; pj.K[nj] = K; pj.off[nj] = off;
        pj.start[nj] = cursor; cursor += 128 * K; nj++;
    };
    addjob(enc_W1, 0, 64, OFF_ENC1);
    addjob(enc_W2, 0, 128, OFF_ENC2);
    for (int l = 0; l < 3; l++) {
        const float* mW1 = msg_W1 + (size_t)l * 2 * H * H;
        const float* uW1 = upd_W1 + (size_t)l * 2 * H * H;
        const float* uW2 = upd_W2 + (size_t)l * H * H;
        addjob(mW1, 0,   128, OFF_W1T(l));
        addjob(mW1, 128, 128, OFF_W1B(l));
        addjob(uW1, 0,   128, OFF_U1T(l));
        addjob(uW2, 0,   128, OFF_UW2(l));
    }
    addjob(pred_W1, 0,   128, OFF_P1T);
    addjob(pred_W1, 128, 128, OFF_P1B);
    addjob(pred_W2, 0,   128, OFF_P2);
    pj.njobs = nj; pj.total = cursor;
    prep_all<<<(cursor + 255) / 256, 256>>>(pj);
    compprep<<<195, 256>>>(upd_W1, msg_W2, msg_b2);

    int gNE = (NE + 63) / 64;
    int gNC = (NC + 63) / 64;
    int gE = gNE < 296 ? gNE : 296;
    int gC = gNC < 296 ? gNC : 296;

    // encoder
    gk_plain<2, 4, 1><<<gE, 256, SMEM_BYTES>>>(
        feat, nullptr, nullptr, wh + OFF_ENC1, wl + OFF_ENC1,
        enc_b1, deg, nullptr, e2h, e2l, NE, gNE);
    gk_plain<0, 8, 2><<<gE, 256, SMEM_BYTES>>>(
        nullptr, e2h, e2l, wh + OFF_ENC2, wl + OFF_ENC2,
        enc_b2, deg, nullptr, eh, el, NE, gNE);

    u16 *ch = eh, *cl = el, *nh = e2h, *nl = e2l;
    for (int l = 0; l < 3; l++) {
        const float* mb1 = msg_b1 + (size_t)l * H;
        const float* ub1 = upd_b1 + (size_t)l * H;
        const float* ub2 = upd_b2 + (size_t)l * H;

        gk_plain<0, 8, 0><<<gE, 256, SMEM_BYTES>>>(
            nullptr, ch, cl, wh + OFF_W1T(l), wl + OFF_W1T(l),
            nullptr, deg, P, nullptr, nullptr, NE, gNE);
        gk_plain<0, 8, 0><<<gE, 256, SMEM_BYTES>>>(
            nullptr, ch, cl, wh + OFF_W1B(l), wl + OFF_W1B(l),
            nullptr, deg, Q, nullptr, nullptr, NE, gNE);

        cudaMemsetAsync(Hagg, 0, (size_t)NE * H * sizeof(float));
        msum<<<(NA + 127) / 128, 256>>>(P, Q, mb1, adj_dst, adj_src, Hagg, NA);
        fixup<<<(NE + 255) / 256, 256>>>(P, Q, mb1, deg, Hagg, NE);

        gk_plain<0, 8, 0><<<gE, 256, SMEM_BYTES>>>(
            nullptr, ch, cl, wh + OFF_U1T(l), wl + OFF_U1T(l),
            nullptr, deg, P, nullptr, nullptr, NE, gNE);
        gk_plain<1, 8, 3><<<gE, 256, SMEM_BYTES>>>(
            Hagg, nullptr, nullptr, wh + OFF_WC(l), wl + OFF_WC(l),
            bc + l * H, deg, Q, nullptr, nullptr, NE, gNE);

        gk_pair<1><<<gE, 256, SMEM_BYTES>>>(
            P, Q, nullptr, nullptr, wh + OFF_UW2(l), wl + OFF_UW2(l),
            ub1, ub2, nullptr, nullptr, nh, nl, nullptr, NE, gNE, 0);

        u16* t1 = ch; ch = nh; nh = t1;
        u16* t2 = cl; cl = nl; nl = t2;
    }

    // predictor
    gk_plain<0, 8, 0><<<gE, 256, SMEM_BYTES>>>(
        nullptr, ch, cl, wh + OFF_P1T, wl + OFF_P1T,
        nullptr, deg, P, nullptr, nullptr, NE, gNE);
    gk_plain<0, 8, 0><<<gE, 256, SMEM_BYTES>>>(
        nullptr, ch, cl, wh + OFF_P1B, wl + OFF_P1B,
        nullptr, deg, Q, nullptr, nullptr, NE, gNE);
    int logit_off = (out_size >= 2 * NC) ? NC : -1;
    gk_pair<2><<<gC, 256, SMEM_BYTES>>>(
        P, Q, cand_i, cand_j, wh + OFF_P2, wl + OFF_P2,
        pred_b1, pred_b2, pred_W3, pred_b3,
        nullptr, nullptr, (float*)d_out, NC, gNC, logit_off);
}

// round 9
// speedup vs baseline: 11.6177x; 1.1028x over previous
#include <cuda_runtime.h>
#include <cuda_bf16.h>
#include <stdint.h>
#include <math.h>

#define H 128
#define NE_MAX 50000

typedef unsigned int uint;
typedef unsigned short u16;

// ---------------- device scratch (allocation-free rule) ----------------
__device__ u16   g_eh [NE_MAX * H];
__device__ u16   g_el [NE_MAX * H];
__device__ u16   g_e2h[NE_MAX * H];
__device__ u16   g_e2l[NE_MAX * H];
__device__ float g_P  [NE_MAX * H];
__device__ float g_Q  [NE_MAX * H];
__device__ float g_agg[NE_MAX * H];     // Hagg
__device__ int   g_deg[NE_MAX];
__device__ float g_bc [3 * H];          // composite biases
#define WSCRATCH 368640
__device__ u16 g_wh[WSCRATCH];
__device__ u16 g_wl[WSCRATCH];

// transposed/split weight offsets (elements)
#define OFF_ENC1 0
#define OFF_ENC2 8192
#define OFF_L(l)   (24576 + (l) * 98304)
#define OFF_W1T(l) (OFF_L(l))
#define OFF_W1B(l) (OFF_L(l) + 16384)
#define OFF_WC(l)  (OFF_L(l) + 32768)   // composite W2@U1bot
#define OFF_U1T(l) (OFF_L(l) + 49152)
#define OFF_UW2(l) (OFF_L(l) + 81920)
#define OFF_P1T 319488
#define OFF_P1B 335872
#define OFF_P2  352256

// smem word offsets; row stride 68 words (=136 u16)
// weights: WH 0..8703, WL 8704..17407
// A buffers: buf b at 17408 + b*8704 (hi 4352 words, lo 4352 words)
#define WROW 68
#define WH_W 0
#define WL_W 8704
#define ABASE 17408
#define ABUF  8704
#define AHALF 4352
#define CTRL_W 34816
#define SMEM_WORDS 35104
#define SMEM_BYTES (SMEM_WORDS * 4)

// ---------------- helpers ----------------
__device__ __forceinline__ uint phi(float a, float b) {
    return (uint)__bfloat16_as_ushort(__float2bfloat16_rn(a))
         | ((uint)__bfloat16_as_ushort(__float2bfloat16_rn(b)) << 16);
}
__device__ __forceinline__ uint plo(float a, float b) {
    float ah = __bfloat162float(__float2bfloat16_rn(a));
    float bh = __bfloat162float(__float2bfloat16_rn(b));
    return phi(a - ah, b - bh);
}
__device__ __forceinline__ uint smem_u32(const void* p) {
    uint a;
    asm("{ .reg .u64 t; cvta.to.shared.u64 t, %1; cvt.u32.u64 %0, t; }" : "=r"(a) : "l"(p));
    return a;
}
__device__ __forceinline__ void cpa16(uint dst, const void* src) {
    asm volatile("cp.async.cg.shared.global [%0], [%1], 16;" :: "r"(dst), "l"(src));
}
#define CPA_COMMIT() asm volatile("cp.async.commit_group;" ::: "memory")
#define CPA_WAIT(n)  asm volatile("cp.async.wait_group %0;" :: "n"(n) : "memory")

__device__ __forceinline__ void mma_bf(float* c, uint a0, uint a1, uint a2, uint a3,
                                       uint b0, uint b1) {
    asm volatile(
        "mma.sync.aligned.m16n8k16.row.col.f32.bf16.bf16.f32 "
        "{%0,%1,%2,%3},{%4,%5,%6,%7},{%8,%9},{%0,%1,%2,%3};"
        : "+f"(c[0]), "+f"(c[1]), "+f"(c[2]), "+f"(c[3])
        : "r"(a0), "r"(a1), "r"(a2), "r"(a3), "r"(b0), "r"(b1));
}

// warp tile 16x32: acc[4][4]; 16 warps = 4(M) x 4(N); M-tile 64, N 128
template <int NK>
__device__ __forceinline__ void gemm_core16(const uint* sm, int aH, int aL,
                                            float acc[4][4], int wm, int wn, int lane) {
    const int lg = lane >> 2, lt = lane & 3;
#pragma unroll
    for (int ks = 0; ks < NK; ks++) {
        const int kw = ks * 8 + lt;
        int base = (wm + lg) * WROW + kw;
        uint ah0 = sm[aH + base],     ah1 = sm[aH + base + 8 * WROW];
        uint ah2 = sm[aH + base + 4], ah3 = sm[aH + base + 8 * WROW + 4];
        uint al0 = sm[aL + base],     al1 = sm[aL + base + 8 * WROW];
        uint al2 = sm[aL + base + 4], al3 = sm[aL + base + 8 * WROW + 4];
#pragma unroll
        for (int nf = 0; nf < 4; nf++) {
            int bb = (wn + nf * 8 + lg) * WROW + kw;
            uint bh0 = sm[WH_W + bb], bh1 = sm[WH_W + bb + 4];
            uint bl0 = sm[WL_W + bb], bl1 = sm[WL_W + bb + 4];
            mma_bf(acc[nf], ah0, ah1, ah2, ah3, bh0, bh1);
            mma_bf(acc[nf], ah0, ah1, ah2, ah3, bl0, bl1);
            mma_bf(acc[nf], al0, al1, al2, al3, bh0, bh1);
        }
    }
}

template <int NK>
__device__ __forceinline__ void load_weights(uint* sm, const u16* Wth, const u16* Wtl,
                                             int tid) {
    const int nv = 128 * NK * 2;
    const uint4* sh = (const uint4*)Wth;
    const uint4* sl = (const uint4*)Wtl;
    for (int i = tid; i < nv; i += 512) {
        int n = i / (NK * 2), q = i % (NK * 2);
        *(uint4*)(sm + WH_W + n * WROW + q * 4) = sh[i];
        *(uint4*)(sm + WL_W + n * WROW + q * 4) = sl[i];
    }
}

// ---------------- small kernels ----------------
__global__ void deg_kernel(const int* __restrict__ dst, int na, int* __restrict__ deg) {
    int i = blockIdx.x * blockDim.x + threadIdx.x;
    if (i < na) atomicAdd(&deg[dst[i]], 1);
}

struct PJobs {
    const float* W[20];
    int rowoff[20], K[20], off[20], start[20];
    int njobs, total;
};
__global__ void prep_all(PJobs j) {
    int i = blockIdx.x * 256 + threadIdx.x;
    if (i >= j.total) return;
    int a = 0;
    while (a + 1 < j.njobs && i >= j.start[a + 1]) a++;
    int e = i - j.start[a];
    int K = j.K[a];
    int n = e / K, k = e % K;
    float v = j.W[a][(size_t)(j.rowoff[a] + k) * 128 + n];
    __nv_bfloat16 h = __float2bfloat16_rn(v);
    g_wh[j.off[a] + e] = __bfloat16_as_ushort(h);
    g_wl[j.off[a] + e] = __bfloat16_as_ushort(__float2bfloat16_rn(v - __bfloat162float(h)));
}

__global__ void compprep(const float* __restrict__ upd_W1,
                         const float* __restrict__ msg_W2,
                         const float* __restrict__ msg_b2) {
    int b = blockIdx.x;
    if (b < 192) {
        int l = b >> 6;
        int i = (b & 63) * 256 + threadIdx.x;
        int o = i & 127, h = i >> 7;
        const float* W2  = msg_W2 + (size_t)l * 16384;
        const float* U1b = upd_W1 + (size_t)l * 32768 + 16384;
        float s = 0.f;
        for (int a2 = 0; a2 < 128; a2++) s += W2[h * 128 + a2] * U1b[a2 * 128 + o];
        int li = OFF_WC(l) + o * 128 + h;
        __nv_bfloat16 hh = __float2bfloat16_rn(s);
        g_wh[li] = __bfloat16_as_ushort(hh);
        g_wl[li] = __bfloat16_as_ushort(__float2bfloat16_rn(s - __bfloat162float(hh)));
    } else if (b < 195) {
        int l = b - 192;
        int o = threadIdx.x;
        if (o < 128) {
            const float* U1b = upd_W1 + (size_t)l * 32768 + 16384;
            const float* b2  = msg_b2 + (size_t)l * 128;
            float s = 0.f;
            for (int a2 = 0; a2 < 128; a2++) s += b2[a2] * U1b[a2 * 128 + o];
            g_bc[l * 128 + o] = s;
        }
    }
}

// pair hidden aggregation: Hagg[dst] += ReLU(P[dst] + Q[src] + b1)
__global__ __launch_bounds__(256) void msum(const float* __restrict__ P,
                                            const float* __restrict__ Q,
                                            const float* __restrict__ b1,
                                            const int* __restrict__ dst,
                                            const int* __restrict__ src,
                                            float* __restrict__ Hagg, int na) {
    int team = threadIdx.x >> 7, col = threadIdx.x & 127;
    int p0 = blockIdx.x * 128 + team * 64;
    if (p0 >= na) return;
    float bias = __ldg(&b1[col]);
    float sum = 0.f, pv = 0.f;
    int cur = -1;
    for (int base = 0; base < 64; base += 8) {
        int dd[8], ss[8];
#pragma unroll
        for (int j = 0; j < 8; j++) {
            int a = p0 + base + j;
            bool v = a < na;
            dd[j] = v ? __ldg(&dst[a]) : -1;
            ss[j] = v ? __ldg(&src[a]) : 0;
        }
        float qv[8];
#pragma unroll
        for (int j = 0; j < 8; j++) qv[j] = __ldg(&Q[(size_t)ss[j] * H + col]);
#pragma unroll
        for (int j = 0; j < 8; j++) {
            if (dd[j] != cur) {
                if (cur >= 0) atomicAdd(&Hagg[(size_t)cur * H + col], sum);
                cur = dd[j];
                sum = 0.f;
                if (cur >= 0) pv = __ldg(&P[(size_t)cur * H + col]) + bias;
            }
            if (dd[j] >= 0) sum += fmaxf(pv + qv[j], 0.f);
        }
    }
    if (cur >= 0) atomicAdd(&Hagg[(size_t)cur * H + col], sum);
}

__global__ void fixup(const float* __restrict__ P, const float* __restrict__ Q,
                      const float* __restrict__ b1, const int* __restrict__ deg,
                      float* __restrict__ Hagg, int ne) {
    int n = blockIdx.x * 256 + threadIdx.x;
    if (n >= ne || deg[n] != 0) return;
    for (int c = 0; c < H; c++)
        Hagg[(size_t)n * H + c] = fmaxf(P[(size_t)n * H + c] + Q[(size_t)n * H + c] + b1[c], 0.f);
}

// ---------------- plain GEMM (M-tile 64, 512 thr, cp.async pipeline) ----------------
// AK: 0 = bf16 hi/lo input (cp.async double-buffer), 1 = fp32 * inv_deg, 2 = fp32 plain
// EPI: 0 = fp32 raw, 1 = bias+ReLU -> bf16 pair, 2 = bias -> bf16 pair, 3 = fp32 + bias
template <int AK, int NK, int EPI>
__global__ __launch_bounds__(512, 1)
void gk_plain(const float* __restrict__ Af,
              const u16* __restrict__ Aph, const u16* __restrict__ Apl,
              const u16* __restrict__ Wth, const u16* __restrict__ Wtl,
              const float* __restrict__ bias, const int* __restrict__ deg,
              float* __restrict__ outf, u16* __restrict__ obh, u16* __restrict__ obl,
              int nrows, int ntiles)
{
    extern __shared__ uint sm[];
    const int tid = threadIdx.x;
    const int lane = tid & 31, w = tid >> 5;
    const int wm = (w & 3) * 16, wn = (w >> 2) * 32;
    const uint sb = smem_u32(sm);

    load_weights<NK>(sm, Wth, Wtl, tid);

    const int r8 = tid >> 3, c8 = tid & 7;

    // async fill of a tile's A (AK==0 only): 4x 16B chunks per thread
    auto fill_async = [&](int t, int p) {
        int gr = t * 64 + r8;
        int rr = (gr < nrows) ? gr : 0;
        const char* shp = (const char*)(Aph + (size_t)rr * H) + c8 * 16;
        const char* slp = (const char*)(Apl + (size_t)rr * H) + c8 * 16;
        uint dh = sb + (ABASE + p * ABUF + r8 * WROW + c8 * 4) * 4;
        uint dl = dh + AHALF * 4;
        cpa16(dh, shp);        cpa16(dh + 128, shp + 128);
        cpa16(dl, slp);        cpa16(dl + 128, slp + 128);
        CPA_COMMIT();
    };

    // scalar fill for fp32 inputs (single buffer 0)
    auto fill_scalar = [&](int t) {
        int gr = t * 64 + r8;
        int rr = (gr < nrows) ? gr : 0;
        float sc = 1.f;
        if (AK == 1) { int d = deg[rr]; sc = 1.f / (d > 1 ? (float)d : 1.f); }
        const float4* s = (const float4*)(Af + (size_t)rr * (NK * 16)) + c8 * (NK / 2);
        int base = ABASE + r8 * WROW + c8 * NK;
#pragma unroll
        for (int q = 0; q < NK / 2; q++) {
            float4 v = s[q];
            if (AK == 1) { v.x *= sc; v.y *= sc; v.z *= sc; v.w *= sc; }
            *(uint2*)(sm + base + 2 * q)         = make_uint2(phi(v.x, v.y), phi(v.z, v.w));
            *(uint2*)(sm + base + AHALF + 2 * q) = make_uint2(plo(v.x, v.y), plo(v.z, v.w));
        }
    };

    int p = 0;
    if (AK == 0) fill_async(blockIdx.x < ntiles ? blockIdx.x : 0, 0);

    for (int t = blockIdx.x; t < ntiles; t += gridDim.x) {
        if (AK == 0) {
            __syncthreads();                       // all done computing from buf p^1
            int tn = t + gridDim.x;
            fill_async(tn < ntiles ? tn : t, p ^ 1);
            CPA_WAIT(1);                           // buf p ready
            __syncthreads();
        } else {
            __syncthreads();
            fill_scalar(t);
            __syncthreads();
        }

        float acc[4][4];
#pragma unroll
        for (int nf = 0; nf < 4; nf++)
#pragma unroll
            for (int q = 0; q < 4; q++) acc[nf][q] = 0.f;
        int aH = ABASE + (AK == 0 ? p * ABUF : 0);
        gemm_core16<NK>(sm, aH, aH + AHALF, acc, wm, wn, lane);

        const int t0 = t * 64;
        const int lg = lane >> 2, lt = lane & 3;
#pragma unroll
        for (int nf = 0; nf < 4; nf++) {
            int row = wm + lg;
            int col = wn + nf * 8 + lt * 2;
            int g0 = t0 + row, g1 = g0 + 8;
            if (EPI == 0) {
                if (g0 < nrows)
                    *(float2*)&outf[(size_t)g0 * H + col] = make_float2(acc[nf][0], acc[nf][1]);
                if (g1 < nrows)
                    *(float2*)&outf[(size_t)g1 * H + col] = make_float2(acc[nf][2], acc[nf][3]);
            } else if (EPI == 3) {
                float b0 = __ldg(&bias[col]), b1v = __ldg(&bias[col + 1]);
                if (g0 < nrows)
                    *(float2*)&outf[(size_t)g0 * H + col] = make_float2(acc[nf][0] + b0, acc[nf][1] + b1v);
                if (g1 < nrows)
                    *(float2*)&outf[(size_t)g1 * H + col] = make_float2(acc[nf][2] + b0, acc[nf][3] + b1v);
            } else {
                float b0 = __ldg(&bias[col]), b1v = __ldg(&bias[col + 1]);
                float v0 = acc[nf][0] + b0, v1 = acc[nf][1] + b1v;
                float v2 = acc[nf][2] + b0, v3 = acc[nf][3] + b1v;
                if (EPI == 1) {
                    v0 = fmaxf(v0, 0.f); v1 = fmaxf(v1, 0.f);
                    v2 = fmaxf(v2, 0.f); v3 = fmaxf(v3, 0.f);
                }
                int wi = col >> 1;
                if (g0 < nrows) {
                    ((uint*)obh)[(size_t)g0 * 64 + wi] = phi(v0, v1);
                    ((uint*)obl)[(size_t)g0 * 64 + wi] = plo(v0, v1);
                }
                if (g1 < nrows) {
                    ((uint*)obh)[(size_t)g1 * 64 + wi] = phi(v2, v3);
                    ((uint*)obl)[(size_t)g1 * 64 + wi] = plo(v2, v3);
                }
            }
        }
        p ^= 1;
    }
}

// ---------------- pairsum GEMM (M-tile 64, 512 thr): hid = ReLU(X[i0]+Y[i1]+b1); out = epi(hid@Wt)
// EPI: 1 = b2+ReLU -> bf16 pair (update), 2 = predictor
template <int EPI>
__global__ __launch_bounds__(512, 1)
void gk_pair(const float* __restrict__ X, const float* __restrict__ Y,
             const int* __restrict__ idx0, const int* __restrict__ idx1,
             const u16* __restrict__ Wth, const u16* __restrict__ Wtl,
             const float* __restrict__ b1, const float* __restrict__ b2,
             const float* __restrict__ W3, const float* __restrict__ b3,
             u16* __restrict__ obh, u16* __restrict__ obl,
             float* __restrict__ pout,
             int nrows, int ntiles, int logit_off)
{
    extern __shared__ uint sm[];
    float* sp = (float*)(sm + CTRL_W);

    const int tid = threadIdx.x;
    const int lane = tid & 31, w = tid >> 5;
    const int wm = (w & 3) * 16, wn = (w >> 2) * 32;

    load_weights<8>(sm, Wth, Wtl, tid);

    const int r8 = tid >> 3, c8 = tid & 7;

    for (int t = blockIdx.x; t < ntiles; t += gridDim.x) {
        const int t0 = t * 64;
        {
            int gr = t0 + r8;
            int rr = (gr < nrows) ? gr : 0;
            int i0 = idx0 ? __ldg(&idx0[rr]) : rr;
            int i1 = idx1 ? __ldg(&idx1[rr]) : rr;
            int ch = c8 * 16;
            const float4* xp = (const float4*)(X + (size_t)i0 * H + ch);
            const float4* yp = (const float4*)(Y + (size_t)i1 * H + ch);
            int base = ABASE + r8 * WROW + c8 * 8;
            __syncthreads();
#pragma unroll
            for (int q = 0; q < 4; q++) {
                float4 xv = xp[q], yv = yp[q];
                int c = ch + q * 4;
                float v0 = fmaxf(xv.x + yv.x + __ldg(&b1[c]),     0.f);
                float v1 = fmaxf(xv.y + yv.y + __ldg(&b1[c + 1]), 0.f);
                float v2 = fmaxf(xv.z + yv.z + __ldg(&b1[c + 2]), 0.f);
                float v3 = fmaxf(xv.w + yv.w + __ldg(&b1[c + 3]), 0.f);
                *(uint2*)(sm + base + 2 * q)         = make_uint2(phi(v0, v1), phi(v2, v3));
                *(uint2*)(sm + base + AHALF + 2 * q) = make_uint2(plo(v0, v1), plo(v2, v3));
            }
        }
        __syncthreads();

        float acc[4][4];
#pragma unroll
        for (int nf = 0; nf < 4; nf++)
#pragma unroll
            for (int q = 0; q < 4; q++) acc[nf][q] = 0.f;
        gemm_core16<8>(sm, ABASE, ABASE + AHALF, acc, wm, wn, lane);

        const int lg = lane >> 2, lt = lane & 3;
        if (EPI == 1) {
#pragma unroll
            for (int nf = 0; nf < 4; nf++) {
                int row = wm + lg;
                int col = wn + nf * 8 + lt * 2;
                int g0 = t0 + row, g1 = g0 + 8;
                float b0 = __ldg(&b2[col]), b1v = __ldg(&b2[col + 1]);
                float v0 = fmaxf(acc[nf][0] + b0, 0.f);
                float v1 = fmaxf(acc[nf][1] + b1v, 0.f);
                float v2 = fmaxf(acc[nf][2] + b0, 0.f);
                float v3 = fmaxf(acc[nf][3] + b1v, 0.f);
                int wi = col >> 1;
                if (g0 < nrows) {
                    ((uint*)obh)[(size_t)g0 * 64 + wi] = phi(v0, v1);
                    ((uint*)obl)[(size_t)g0 * 64 + wi] = plo(v0, v1);
                }
                if (g1 < nrows) {
                    ((uint*)obh)[(size_t)g1 * 64 + wi] = phi(v2, v3);
                    ((uint*)obl)[(size_t)g1 * 64 + wi] = plo(v2, v3);
                }
            }
        } else {
            float p0 = 0.f, p1 = 0.f;
#pragma unroll
            for (int nf = 0; nf < 4; nf++) {
                int col = wn + nf * 8 + lt * 2;
                float b0 = __ldg(&b2[col]), b1v = __ldg(&b2[col + 1]);
                float w30 = __ldg(&W3[col]), w31 = __ldg(&W3[col + 1]);
                p0 += fmaxf(acc[nf][0] + b0, 0.f) * w30
                    + fmaxf(acc[nf][1] + b1v, 0.f) * w31;
                p1 += fmaxf(acc[nf][2] + b0, 0.f) * w30
                    + fmaxf(acc[nf][3] + b1v, 0.f) * w31;
            }
            p0 += __shfl_xor_sync(0xFFFFFFFFu, p0, 1);
            p0 += __shfl_xor_sync(0xFFFFFFFFu, p0, 2);
            p1 += __shfl_xor_sync(0xFFFFFFFFu, p1, 1);
            p1 += __shfl_xor_sync(0xFFFFFFFFu, p1, 2);
            if (lt == 0) {
                sp[wm + lg +     64 * (wn >> 5)] = p0;
                sp[wm + lg + 8 + 64 * (wn >> 5)] = p1;
            }
            __syncthreads();
            if (tid < 64) {
                int r = t0 + tid;
                if (r < nrows) {
                    float s = sp[tid] + sp[tid + 64] + sp[tid + 128] + sp[tid + 192] + __ldg(&b3[0]);
                    pout[r] = 1.f / (1.f + expf(-s));
                    if (logit_off > 0) pout[logit_off + r] = s;
                }
            }
        }
    }
}

// ---------------- host ----------------
extern "C" void kernel_launch(void* const* d_in, const int* in_sizes, int n_in,
                              void* d_out, int out_size) {
    const float* feat    = (const float*)d_in[0];
    const int*   adj_dst = (const int*)  d_in[1];
    const int*   adj_src = (const int*)  d_in[2];
    const int*   cand_i  = (const int*)  d_in[3];
    const int*   cand_j  = (const int*)  d_in[4];
    const float* enc_W1 = (const float*)d_in[5];
    const float* enc_b1 = (const float*)d_in[6];
    const float* enc_W2 = (const float*)d_in[7];
    const float* enc_b2 = (const float*)d_in[8];
    const float* msg_W1 = (const float*)d_in[9];
    const float* msg_b1 = (const float*)d_in[10];
    const float* msg_W2 = (const float*)d_in[11];
    const float* msg_b2 = (const float*)d_in[12];
    const float* upd_W1 = (const float*)d_in[13];
    const float* upd_b1 = (const float*)d_in[14];
    const float* upd_W2 = (const float*)d_in[15];
    const float* upd_b2 = (const float*)d_in[16];
    const float* pred_W1 = (const float*)d_in[17];
    const float* pred_b1 = (const float*)d_in[18];
    const float* pred_W2 = (const float*)d_in[19];
    const float* pred_b2 = (const float*)d_in[20];
    const float* pred_W3 = (const float*)d_in[21];
    const float* pred_b3 = (const float*)d_in[22];

    int NE = in_sizes[0] / 64;
    int NA = in_sizes[1];
    int NC = in_sizes[3];
    if (NE > NE_MAX) NE = NE_MAX;

    float *P, *Q, *Hagg, *bc;
    int* deg;
    u16 *eh, *el, *e2h, *e2l, *wh, *wl;
    cudaGetSymbolAddress((void**)&P,    g_P);
    cudaGetSymbolAddress((void**)&Q,    g_Q);
    cudaGetSymbolAddress((void**)&Hagg, g_agg);
    cudaGetSymbolAddress((void**)&deg,  g_deg);
    cudaGetSymbolAddress((void**)&bc,   g_bc);
    cudaGetSymbolAddress((void**)&eh,   g_eh);
    cudaGetSymbolAddress((void**)&el,   g_el);
    cudaGetSymbolAddress((void**)&e2h,  g_e2h);
    cudaGetSymbolAddress((void**)&e2l,  g_e2l);
    cudaGetSymbolAddress((void**)&wh,   g_wh);
    cudaGetSymbolAddress((void**)&wl,   g_wl);

    cudaFuncSetAttribute(gk_plain<2, 4, 1>, cudaFuncAttributeMaxDynamicSharedMemorySize, SMEM_BYTES);
    cudaFuncSetAttribute(gk_plain<0, 8, 2>, cudaFuncAttributeMaxDynamicSharedMemorySize, SMEM_BYTES);
    cudaFuncSetAttribute(gk_plain<0, 8, 0>, cudaFuncAttributeMaxDynamicSharedMemorySize, SMEM_BYTES);
    cudaFuncSetAttribute(gk_plain<1, 8, 3>, cudaFuncAttributeMaxDynamicSharedMemorySize, SMEM_BYTES);
    cudaFuncSetAttribute(gk_pair<1>, cudaFuncAttributeMaxDynamicSharedMemorySize, SMEM_BYTES);
    cudaFuncSetAttribute(gk_pair<2>, cudaFuncAttributeMaxDynamicSharedMemorySize, SMEM_BYTES);

    cudaMemsetAsync(deg, 0, (size_t)NE * sizeof(int));
    deg_kernel<<<(NA + 255) / 256, 256>>>(adj_dst, NA, deg);

    // ---- weight prep ----
    PJobs pj;
    int cursor = 0, nj = 0;
    auto addjob = [&](const float* W, int ro, int K, int off) {
        pj.W[nj] = W; pj.rowoff[nj] = ro; pj.K[nj] = K; pj.off[nj] = off;
        pj.start[nj] = cursor; cursor += 128 * K; nj++;
    };
    addjob(enc_W1, 0, 64, OFF_ENC1);
    addjob(enc_W2, 0, 128, OFF_ENC2);
    for (int l = 0; l < 3; l++) {
        const float* mW1 = msg_W1 + (size_t)l * 2 * H * H;
        const float* uW1 = upd_W1 + (size_t)l * 2 * H * H;
        const float* uW2 = upd_W2 + (size_t)l * H * H;
        addjob(mW1, 0,   128, OFF_W1T(l));
        addjob(mW1, 128, 128, OFF_W1B(l));
        addjob(uW1, 0,   128, OFF_U1T(l));
        addjob(uW2, 0,   128, OFF_UW2(l));
    }
    addjob(pred_W1, 0,   128, OFF_P1T);
    addjob(pred_W1, 128, 128, OFF_P1B);
    addjob(pred_W2, 0,   128, OFF_P2);
    pj.njobs = nj; pj.total = cursor;
    prep_all<<<(cursor + 255) / 256, 256>>>(pj);
    compprep<<<195, 256>>>(upd_W1, msg_W2, msg_b2);

    int gNE = (NE + 63) / 64;
    int gNC = (NC + 63) / 64;
    int gE = gNE < 148 ? gNE : 148;
    int gC = gNC < 148 ? gNC : 148;

    // encoder
    gk_plain<2, 4, 1><<<gE, 512, SMEM_BYTES>>>(
        feat, nullptr, nullptr, wh + OFF_ENC1, wl + OFF_ENC1,
        enc_b1, deg, nullptr, e2h, e2l, NE, gNE);
    gk_plain<0, 8, 2><<<gE, 512, SMEM_BYTES>>>(
        nullptr, e2h, e2l, wh + OFF_ENC2, wl + OFF_ENC2,
        enc_b2, deg, nullptr, eh, el, NE, gNE);

    u16 *ch = eh, *cl = el, *nh = e2h, *nl = e2l;
    for (int l = 0; l < 3; l++) {
        const float* mb1 = msg_b1 + (size_t)l * H;
        const float* ub1 = upd_b1 + (size_t)l * H;
        const float* ub2 = upd_b2 + (size_t)l * H;

        gk_plain<0, 8, 0><<<gE, 512, SMEM_BYTES>>>(
            nullptr, ch, cl, wh + OFF_W1T(l), wl + OFF_W1T(l),
            nullptr, deg, P, nullptr, nullptr, NE, gNE);
        gk_plain<0, 8, 0><<<gE, 512, SMEM_BYTES>>>(
            nullptr, ch, cl, wh + OFF_W1B(l), wl + OFF_W1B(l),
            nullptr, deg, Q, nullptr, nullptr, NE, gNE);

        cudaMemsetAsync(Hagg, 0, (size_t)NE * H * sizeof(float));
        msum<<<(NA + 127) / 128, 256>>>(P, Q, mb1, adj_dst, adj_src, Hagg, NA);
        fixup<<<(NE + 255) / 256, 256>>>(P, Q, mb1, deg, Hagg, NE);

        gk_plain<0, 8, 0><<<gE, 512, SMEM_BYTES>>>(
            nullptr, ch, cl, wh + OFF_U1T(l), wl + OFF_U1T(l),
            nullptr, deg, P, nullptr, nullptr, NE, gNE);
        gk_plain<1, 8, 3><<<gE, 512, SMEM_BYTES>>>(
            Hagg, nullptr, nullptr, wh + OFF_WC(l), wl + OFF_WC(l),
            bc + l * H, deg, Q, nullptr, nullptr, NE, gNE);

        gk_pair<1><<<gE, 512, SMEM_BYTES>>>(
            P, Q, nullptr, nullptr, wh + OFF_UW2(l), wl + OFF_UW2(l),
            ub1, ub2, nullptr, nullptr, nh, nl, nullptr, NE, gNE, 0);

        u16* t1 = ch; ch = nh; nh = t1;
        u16* t2 = cl; cl = nl; nl = t2;
    }

    // predictor
    gk_plain<0, 8, 0><<<gE, 512, SMEM_BYTES>>>(
        nullptr, ch, cl, wh + OFF_P1T, wl + OFF_P1T,
        nullptr, deg, P, nullptr, nullptr, NE, gNE);
    gk_plain<0, 8, 0><<<gE, 512, SMEM_BYTES>>>(
        nullptr, ch, cl, wh + OFF_P1B, wl + OFF_P1B,
        nullptr, deg, Q, nullptr, nullptr, NE, gNE);
    int logit_off = (out_size >= 2 * NC) ? NC : -1;
    gk_pair<2><<<gC, 512, SMEM_BYTES>>>(
        P, Q, cand_i, cand_j, wh + OFF_P2, wl + OFF_P2,
        pred_b1, pred_b2, pred_W3, pred_b3,
        nullptr, nullptr, (float*)d_out, NC, gNC, logit_off);
}

// round 11
// speedup vs baseline: 12.7107x; 1.0941x over previous
#include <cuda_runtime.h>
#include <cuda_bf16.h>
#include <stdint.h>
#include <math.h>

#define H 128
#define NE_MAX 50000

typedef unsigned int uint;
typedef unsigned short u16;

// ---------------- device scratch (allocation-free rule) ----------------
__device__ u16   g_eh [NE_MAX * H];
__device__ u16   g_el [NE_MAX * H];
__device__ u16   g_e2h[NE_MAX * H];
__device__ u16   g_e2l[NE_MAX * H];
__device__ u16   g_hh [NE_MAX * H];      // hid bf16 hi
__device__ u16   g_hl [NE_MAX * H];      // hid bf16 lo
__device__ float g_P  [NE_MAX * H];
__device__ float g_Q  [NE_MAX * H];
__device__ float g_agg[NE_MAX * H];      // Hagg
__device__ int   g_deg[NE_MAX];
__device__ float g_bc [3 * H];           // combined update bias (b2@U1bot + upd_b1)
#define WSCRATCH 368640
__device__ u16 g_wh[WSCRATCH];
__device__ u16 g_wl[WSCRATCH];

// transposed/split weight offsets (elements)
#define OFF_ENC1 0
#define OFF_ENC2 8192
#define OFF_L(l)   (24576 + (l) * 98304)
#define OFF_W1T(l) (OFF_L(l))
#define OFF_W1B(l) (OFF_L(l) + 16384)
#define OFF_WC(l)  (OFF_L(l) + 32768)   // composite W2@U1bot
#define OFF_U1T(l) (OFF_L(l) + 49152)
#define OFF_UW2(l) (OFF_L(l) + 81920)
#define OFF_P1T 319488
#define OFF_P1B 335872
#define OFF_P2  352256

// ---- single-GEMM smem layout (gk_plain / gk_pair) ----
#define WROW 68
#define WH_W 0
#define WL_W 8704
#define ABASE 17408
#define ABUF  8704
#define AHALF 4352
#define CTRL_W 34816
#define SMEM_WORDS 35104
#define SMEM_BYTES (SMEM_WORDS * 4)

// ---- dual-GEMM smem layout (gk_dual / gk_upd) ----
#define D_W1H 0
#define D_W1L 8704
#define D_W2H 17408
#define D_W2L 26112
#define D_ABASE 34816
#define D_ABUF  8704
#define D_AHALF 4352
#define D_SMEM_WORDS 52224
#define D_SMEM_BYTES (D_SMEM_WORDS * 4)

// ---------------- helpers ----------------
__device__ __forceinline__ uint phi(float a, float b) {
    return (uint)__bfloat16_as_ushort(__float2bfloat16_rn(a))
         | ((uint)__bfloat16_as_ushort(__float2bfloat16_rn(b)) << 16);
}
__device__ __forceinline__ uint plo(float a, float b) {
    float ah = __bfloat162float(__float2bfloat16_rn(a));
    float bh = __bfloat162float(__float2bfloat16_rn(b));
    return phi(a - ah, b - bh);
}
__device__ __forceinline__ uint smem_u32(const void* p) {
    uint a;
    asm("{ .reg .u64 t; cvta.to.shared.u64 t, %1; cvt.u32.u64 %0, t; }" : "=r"(a) : "l"(p));
    return a;
}
__device__ __forceinline__ void cpa16(uint dst, const void* src) {
    asm volatile("cp.async.cg.shared.global [%0], [%1], 16;" :: "r"(dst), "l"(src));
}
#define CPA_COMMIT() asm volatile("cp.async.commit_group;" ::: "memory")
#define CPA_WAIT(n)  asm volatile("cp.async.wait_group %0;" :: "n"(n) : "memory")

__device__ __forceinline__ void mma_bf(float* c, uint a0, uint a1, uint a2, uint a3,
                                       uint b0, uint b1) {
    asm volatile(
        "mma.sync.aligned.m16n8k16.row.col.f32.bf16.bf16.f32 "
        "{%0,%1,%2,%3},{%4,%5,%6,%7},{%8,%9},{%0,%1,%2,%3};"
        : "+f"(c[0]), "+f"(c[1]), "+f"(c[2]), "+f"(c[3])
        : "r"(a0), "r"(a1), "r"(a2), "r"(a3), "r"(b0), "r"(b1));
}

// warp tile 16x32: acc[4][4]; 16 warps = 4(M) x 4(N); M-tile 64, N 128
template <int NK>
__device__ __forceinline__ void gemm_core16(const uint* sm, int aH, int aL,
                                            int wH, int wL,
                                            float acc[4][4], int wm, int wn, int lane) {
    const int lg = lane >> 2, lt = lane & 3;
#pragma unroll
    for (int ks = 0; ks < NK; ks++) {
        const int kw = ks * 8 + lt;
        int base = (wm + lg) * WROW + kw;
        uint ah0 = sm[aH + base],     ah1 = sm[aH + base + 8 * WROW];
        uint ah2 = sm[aH + base + 4], ah3 = sm[aH + base + 8 * WROW + 4];
        uint al0 = sm[aL + base],     al1 = sm[aL + base + 8 * WROW];
        uint al2 = sm[aL + base + 4], al3 = sm[aL + base + 8 * WROW + 4];
#pragma unroll
        for (int nf = 0; nf < 4; nf++) {
            int bb = (wn + nf * 8 + lg) * WROW + kw;
            uint bh0 = sm[wH + bb], bh1 = sm[wH + bb + 4];
            uint bl0 = sm[wL + bb], bl1 = sm[wL + bb + 4];
            mma_bf(acc[nf], ah0, ah1, ah2, ah3, bh0, bh1);
            mma_bf(acc[nf], ah0, ah1, ah2, ah3, bl0, bl1);
            mma_bf(acc[nf], al0, al1, al2, al3, bh0, bh1);
        }
    }
}

template <int NK>
__device__ __forceinline__ void load_weights(uint* sm, int dH, int dL,
                                             const u16* Wth, const u16* Wtl, int tid) {
    const int nv = 128 * NK * 2;
    const uint4* sh = (const uint4*)Wth;
    const uint4* sl = (const uint4*)Wtl;
    for (int i = tid; i < nv; i += 512) {
        int n = i / (NK * 2), q = i % (NK * 2);
        *(uint4*)(sm + dH + n * WROW + q * 4) = sh[i];
        *(uint4*)(sm + dL + n * WROW + q * 4) = sl[i];
    }
}

// ---------------- small kernels ----------------
__global__ void deg_kernel(const int* __restrict__ dst, int na, int* __restrict__ deg) {
    int i = blockIdx.x * blockDim.x + threadIdx.x;
    if (i < na) atomicAdd(&deg[dst[i]], 1);
}

struct PJobs {
    const float* W[20];
    int rowoff[20], K[20], off[20], start[20];
    int njobs, total;
};
__global__ void prep_all(PJobs j) {
    int i = blockIdx.x * 256 + threadIdx.x;
    if (i >= j.total) return;
    int a = 0;
    while (a + 1 < j.njobs && i >= j.start[a + 1]) a++;
    int e = i - j.start[a];
    int K = j.K[a];
    int n = e / K, k = e % K;
    float v = j.W[a][(size_t)(j.rowoff[a] + k) * 128 + n];
    __nv_bfloat16 h = __float2bfloat16_rn(v);
    g_wh[j.off[a] + e] = __bfloat16_as_ushort(h);
    g_wl[j.off[a] + e] = __bfloat16_as_ushort(__float2bfloat16_rn(v - __bfloat162float(h)));
}

// composite: Wc = msg_W2 @ U1bot;  bc = msg_b2 @ U1bot + upd_b1
__global__ void compprep(const float* __restrict__ upd_W1,
                         const float* __restrict__ msg_W2,
                         const float* __restrict__ msg_b2,
                         const float* __restrict__ upd_b1) {
    int b = blockIdx.x;
    if (b < 192) {
        int l = b >> 6;
        int i = (b & 63) * 256 + threadIdx.x;
        int o = i & 127, h = i >> 7;
        const float* W2  = msg_W2 + (size_t)l * 16384;
        const float* U1b = upd_W1 + (size_t)l * 32768 + 16384;
        float s = 0.f;
        for (int a2 = 0; a2 < 128; a2++) s += W2[h * 128 + a2] * U1b[a2 * 128 + o];
        int li = OFF_WC(l) + o * 128 + h;
        __nv_bfloat16 hh = __float2bfloat16_rn(s);
        g_wh[li] = __bfloat16_as_ushort(hh);
        g_wl[li] = __bfloat16_as_ushort(__float2bfloat16_rn(s - __bfloat162float(hh)));
    } else if (b < 195) {
        int l = b - 192;
        int o = threadIdx.x;
        if (o < 128) {
            const float* U1b = upd_W1 + (size_t)l * 32768 + 16384;
            const float* b2  = msg_b2 + (size_t)l * 128;
            float s = upd_b1[l * 128 + o];
            for (int a2 = 0; a2 < 128; a2++) s += b2[a2] * U1b[a2 * 128 + o];
            g_bc[l * 128 + o] = s;
        }
    }
}

// pair hidden aggregation: Hagg[dst] += ReLU(P[dst] + Q[src] + b1)
__global__ __launch_bounds__(256) void msum(const float* __restrict__ P,
                                            const float* __restrict__ Q,
                                            const float* __restrict__ b1,
                                            const int* __restrict__ dst,
                                            const int* __restrict__ src,
                                            float* __restrict__ Hagg, int na) {
    int team = threadIdx.x >> 7, col = threadIdx.x & 127;
    int p0 = blockIdx.x * 128 + team * 64;
    if (p0 >= na) return;
    float bias = __ldg(&b1[col]);
    float sum = 0.f, pv = 0.f;
    int cur = -1;
    for (int base = 0; base < 64; base += 8) {
        int dd[8], ss[8];
#pragma unroll
        for (int j = 0; j < 8; j++) {
            int a = p0 + base + j;
            bool v = a < na;
            dd[j] = v ? __ldg(&dst[a]) : -1;
            ss[j] = v ? __ldg(&src[a]) : 0;
        }
        float qv[8];
#pragma unroll
        for (int j = 0; j < 8; j++) qv[j] = __ldg(&Q[(size_t)ss[j] * H + col]);
#pragma unroll
        for (int j = 0; j < 8; j++) {
            if (dd[j] != cur) {
                if (cur >= 0) atomicAdd(&Hagg[(size_t)cur * H + col], sum);
                cur = dd[j];
                sum = 0.f;
                if (cur >= 0) pv = __ldg(&P[(size_t)cur * H + col]) + bias;
            }
            if (dd[j] >= 0) sum += fmaxf(pv + qv[j], 0.f);
        }
    }
    if (cur >= 0) atomicAdd(&Hagg[(size_t)cur * H + col], sum);
}

__global__ void fixup(const float* __restrict__ P, const float* __restrict__ Q,
                      const float* __restrict__ b1, const int* __restrict__ deg,
                      float* __restrict__ Hagg, int ne) {
    int n = blockIdx.x * 256 + threadIdx.x;
    if (n >= ne || deg[n] != 0) return;
    for (int c = 0; c < H; c++)
        Hagg[(size_t)n * H + c] = fmaxf(P[(size_t)n * H + c] + Q[(size_t)n * H + c] + b1[c], 0.f);
}

// ---------------- single GEMM (M-tile 64, 512 thr, cp.async pipeline) ----------------
// AK: 0 = bf16 hi/lo input (cp.async double-buffer), 2 = fp32 plain
// EPI: 1 = bias+ReLU -> bf16 pair, 2 = bias -> bf16 pair
template <int AK, int NK, int EPI>
__global__ __launch_bounds__(512, 1)
void gk_plain(const float* __restrict__ Af,
              const u16* __restrict__ Aph, const u16* __restrict__ Apl,
              const u16* __restrict__ Wth, const u16* __restrict__ Wtl,
              const float* __restrict__ bias,
              u16* __restrict__ obh, u16* __restrict__ obl,
              int nrows, int ntiles)
{
    extern __shared__ uint sm[];
    const int tid = threadIdx.x;
    const int lane = tid & 31, w = tid >> 5;
    const int wm = (w & 3) * 16, wn = (w >> 2) * 32;
    const uint sb = smem_u32(sm);

    load_weights<NK>(sm, WH_W, WL_W, Wth, Wtl, tid);

    const int r8 = tid >> 3, c8 = tid & 7;

    auto fill_async = [&](int t, int p) {
        int gr = t * 64 + r8;
        int rr = (gr < nrows) ? gr : 0;
        const char* shp = (const char*)(Aph + (size_t)rr * H) + c8 * 16;
        const char* slp = (const char*)(Apl + (size_t)rr * H) + c8 * 16;
        uint dh = sb + (ABASE + p * ABUF + r8 * WROW + c8 * 4) * 4;
        uint dl = dh + AHALF * 4;
        cpa16(dh, shp);        cpa16(dh + 128, shp + 128);
        cpa16(dl, slp);        cpa16(dl + 128, slp + 128);
        CPA_COMMIT();
    };
    auto fill_scalar = [&](int t) {
        int gr = t * 64 + r8;
        int rr = (gr < nrows) ? gr : 0;
        const float4* s = (const float4*)(Af + (size_t)rr * (NK * 16)) + c8 * (NK / 2);
        int base = ABASE + r8 * WROW + c8 * NK;
#pragma unroll
        for (int q = 0; q < NK / 2; q++) {
            float4 v = s[q];
            *(uint2*)(sm + base + 2 * q)         = make_uint2(phi(v.x, v.y), phi(v.z, v.w));
            *(uint2*)(sm + base + AHALF + 2 * q) = make_uint2(plo(v.x, v.y), plo(v.z, v.w));
        }
    };

    int p = 0;
    if (AK == 0) fill_async(blockIdx.x < ntiles ? blockIdx.x : 0, 0);

    for (int t = blockIdx.x; t < ntiles; t += gridDim.x) {
        if (AK == 0) {
            __syncthreads();
            int tn = t + gridDim.x;
            fill_async(tn < ntiles ? tn : t, p ^ 1);
            CPA_WAIT(1);
            __syncthreads();
        } else {
            __syncthreads();
            fill_scalar(t);
            __syncthreads();
        }

        float acc[4][4];
#pragma unroll
        for (int nf = 0; nf < 4; nf++)
#pragma unroll
            for (int q = 0; q < 4; q++) acc[nf][q] = 0.f;
        int aH = ABASE + (AK == 0 ? p * ABUF : 0);
        gemm_core16<NK>(sm, aH, aH + AHALF, WH_W, WL_W, acc, wm, wn, lane);

        const int t0 = t * 64;
        const int lg = lane >> 2, lt = lane & 3;
#pragma unroll
        for (int nf = 0; nf < 4; nf++) {
            int row = wm + lg;
            int col = wn + nf * 8 + lt * 2;
            int g0 = t0 + row, g1 = g0 + 8;
            float b0 = __ldg(&bias[col]), b1v = __ldg(&bias[col + 1]);
            float v0 = acc[nf][0] + b0, v1 = acc[nf][1] + b1v;
            float v2 = acc[nf][2] + b0, v3 = acc[nf][3] + b1v;
            if (EPI == 1) {
                v0 = fmaxf(v0, 0.f); v1 = fmaxf(v1, 0.f);
                v2 = fmaxf(v2, 0.f); v3 = fmaxf(v3, 0.f);
            }
            int wi = col >> 1;
            if (g0 < nrows) {
                ((uint*)obh)[(size_t)g0 * 64 + wi] = phi(v0, v1);
                ((uint*)obl)[(size_t)g0 * 64 + wi] = plo(v0, v1);
            }
            if (g1 < nrows) {
                ((uint*)obh)[(size_t)g1 * 64 + wi] = phi(v2, v3);
                ((uint*)obl)[(size_t)g1 * 64 + wi] = plo(v2, v3);
            }
        }
        p ^= 1;
    }
}

// ---------------- dual GEMM, shared A: out1 = A@W1, out2 = A@W2 (fp32 raw) ----------------
__global__ __launch_bounds__(512, 1)
void gk_dual(const u16* __restrict__ Aph, const u16* __restrict__ Apl,
             const u16* __restrict__ W1h_, const u16* __restrict__ W1l_,
             const u16* __restrict__ W2h_, const u16* __restrict__ W2l_,
             float* __restrict__ out1, float* __restrict__ out2,
             int nrows, int ntiles)
{
    extern __shared__ uint sm[];
    const int tid = threadIdx.x;
    const int lane = tid & 31, w = tid >> 5;
    const int wm = (w & 3) * 16, wn = (w >> 2) * 32;
    const uint sb = smem_u32(sm);

    load_weights<8>(sm, D_W1H, D_W1L, W1h_, W1l_, tid);
    load_weights<8>(sm, D_W2H, D_W2L, W2h_, W2l_, tid);

    const int r8 = tid >> 3, c8 = tid & 7;
    auto fill_async = [&](int t, int p) {
        int gr = t * 64 + r8;
        int rr = (gr < nrows) ? gr : 0;
        const char* shp = (const char*)(Aph + (size_t)rr * H) + c8 * 16;
        const char* slp = (const char*)(Apl + (size_t)rr * H) + c8 * 16;
        uint dh = sb + (D_ABASE + p * D_ABUF + r8 * WROW + c8 * 4) * 4;
        uint dl = dh + D_AHALF * 4;
        cpa16(dh, shp);        cpa16(dh + 128, shp + 128);
        cpa16(dl, slp);        cpa16(dl + 128, slp + 128);
        CPA_COMMIT();
    };

    int p = 0;
    fill_async(blockIdx.x < ntiles ? blockIdx.x : 0, 0);

    for (int t = blockIdx.x; t < ntiles; t += gridDim.x) {
        __syncthreads();
        int tn = t + gridDim.x;
        fill_async(tn < ntiles ? tn : t, p ^ 1);
        CPA_WAIT(1);
        __syncthreads();

        int aH = D_ABASE + p * D_ABUF;
        float acc1[4][4], acc2[4][4];
#pragma unroll
        for (int nf = 0; nf < 4; nf++)
#pragma unroll
            for (int q = 0; q < 4; q++) { acc1[nf][q] = 0.f; acc2[nf][q] = 0.f; }
        gemm_core16<8>(sm, aH, aH + D_AHALF, D_W1H, D_W1L, acc1, wm, wn, lane);
        gemm_core16<8>(sm, aH, aH + D_AHALF, D_W2H, D_W2L, acc2, wm, wn, lane);

        const int t0 = t * 64;
        const int lg = lane >> 2, lt = lane & 3;
#pragma unroll
        for (int nf = 0; nf < 4; nf++) {
            int row = wm + lg;
            int col = wn + nf * 8 + lt * 2;
            int g0 = t0 + row, g1 = g0 + 8;
            if (g0 < nrows) {
                *(float2*)&out1[(size_t)g0 * H + col] = make_float2(acc1[nf][0], acc1[nf][1]);
                *(float2*)&out2[(size_t)g0 * H + col] = make_float2(acc2[nf][0], acc2[nf][1]);
            }
            if (g1 < nrows) {
                *(float2*)&out1[(size_t)g1 * H + col] = make_float2(acc1[nf][2], acc1[nf][3]);
                *(float2*)&out2[(size_t)g1 * H + col] = make_float2(acc2[nf][2], acc2[nf][3]);
            }
        }
        p ^= 1;
    }
}

// ---------------- update fused: hid = ReLU(e@U1T + (Hagg*inv_deg)@WC + bias) -> bf16 ----------------
__global__ __launch_bounds__(512, 1)
void gk_upd(const u16* __restrict__ Aph, const u16* __restrict__ Apl,
            const float* __restrict__ Hagg,
            const u16* __restrict__ W1h_, const u16* __restrict__ W1l_,
            const u16* __restrict__ W2h_, const u16* __restrict__ W2l_,
            const float* __restrict__ bias, const int* __restrict__ deg,
            u16* __restrict__ obh, u16* __restrict__ obl,
            int nrows, int ntiles)
{
    extern __shared__ uint sm[];
    const int tid = threadIdx.x;
    const int lane = tid & 31, w = tid >> 5;
    const int wm = (w & 3) * 16, wn = (w >> 2) * 32;
    const uint sb = smem_u32(sm);

    load_weights<8>(sm, D_W1H, D_W1L, W1h_, W1l_, tid);
    load_weights<8>(sm, D_W2H, D_W2L, W2h_, W2l_, tid);

    const int r8 = tid >> 3, c8 = tid & 7;

    for (int t = blockIdx.x; t < ntiles; t += gridDim.x) {
        const int t0 = t * 64;
        int gr = t0 + r8;
        int rr = (gr < nrows) ? gr : 0;
        __syncthreads();
        {   // A1: e (bf16 hi/lo) via cp.async
            const char* shp = (const char*)(Aph + (size_t)rr * H) + c8 * 16;
            const char* slp = (const char*)(Apl + (size_t)rr * H) + c8 * 16;
            uint dh = sb + (D_ABASE + r8 * WROW + c8 * 4) * 4;
            uint dl = dh + D_AHALF * 4;
            cpa16(dh, shp);        cpa16(dh + 128, shp + 128);
            cpa16(dl, slp);        cpa16(dl + 128, slp + 128);
            CPA_COMMIT();
        }
        {   // A2: Hagg * inv_deg, scalar convert
            int d = deg[rr];
            float sc = 1.f / (d > 1 ? (float)d : 1.f);
            const float4* s = (const float4*)(Hagg + (size_t)rr * H) + c8 * 4;
            int base = D_ABASE + D_ABUF + r8 * WROW + c8 * 8;
#pragma unroll
            for (int q = 0; q < 4; q++) {
                float4 v = s[q];
                v.x *= sc; v.y *= sc; v.z *= sc; v.w *= sc;
                *(uint2*)(sm + base + 2 * q)           = make_uint2(phi(v.x, v.y), phi(v.z, v.w));
                *(uint2*)(sm + base + D_AHALF + 2 * q) = make_uint2(plo(v.x, v.y), plo(v.z, v.w));
            }
        }
        CPA_WAIT(0);
        __syncthreads();

        float acc[4][4];
#pragma unroll
        for (int nf = 0; nf < 4; nf++)
#pragma unroll
            for (int q = 0; q < 4; q++) acc[nf][q] = 0.f;
        gemm_core16<8>(sm, D_ABASE, D_ABASE + D_AHALF, D_W1H, D_W1L, acc, wm, wn, lane);
        gemm_core16<8>(sm, D_ABASE + D_ABUF, D_ABASE + D_ABUF + D_AHALF, D_W2H, D_W2L, acc, wm, wn, lane);

        const int lg = lane >> 2, lt = lane & 3;
#pragma unroll
        for (int nf = 0; nf < 4; nf++) {
            int row = wm + lg;
            int col = wn + nf * 8 + lt * 2;
            int g0 = t0 + row, g1 = g0 + 8;
            float b0 = __ldg(&bias[col]), b1v = __ldg(&bias[col + 1]);
            float v0 = fmaxf(acc[nf][0] + b0, 0.f);
            float v1 = fmaxf(acc[nf][1] + b1v, 0.f);
            float v2 = fmaxf(acc[nf][2] + b0, 0.f);
            float v3 = fmaxf(acc[nf][3] + b1v, 0.f);
            int wi = col >> 1;
            if (g0 < nrows) {
                ((uint*)obh)[(size_t)g0 * 64 + wi] = phi(v0, v1);
                ((uint*)obl)[(size_t)g0 * 64 + wi] = plo(v0, v1);
            }
            if (g1 < nrows) {
                ((uint*)obh)[(size_t)g1 * 64 + wi] = phi(v2, v3);
                ((uint*)obl)[(size_t)g1 * 64 + wi] = plo(v2, v3);
            }
        }
    }
}

// ---------------- pairsum GEMM: hid = ReLU(X[i0]+Y[i1]+b1); out = predictor epilogue ----------------
__global__ __launch_bounds__(512, 1)
void gk_pair(const float* __restrict__ X, const float* __restrict__ Y,
             const int* __restrict__ idx0, const int* __restrict__ idx1,
             const u16* __restrict__ Wth, const u16* __restrict__ Wtl,
             const float* __restrict__ b1, const float* __restrict__ b2,
             const float* __restrict__ W3, const float* __restrict__ b3,
             float* __restrict__ pout,
             int nrows, int ntiles, int logit_off)
{
    extern __shared__ uint sm[];
    float* sp = (float*)(sm + CTRL_W);

    const int tid = threadIdx.x;
    const int lane = tid & 31, w = tid >> 5;
    const int wm = (w & 3) * 16, wn = (w >> 2) * 32;

    load_weights<8>(sm, WH_W, WL_W, Wth, Wtl, tid);

    const int r8 = tid >> 3, c8 = tid & 7;

    for (int t = blockIdx.x; t < ntiles; t += gridDim.x) {
        const int t0 = t * 64;
        {
            int gr = t0 + r8;
            int rr = (gr < nrows) ? gr : 0;
            int i0 = __ldg(&idx0[rr]);
            int i1 = __ldg(&idx1[rr]);
            int ch = c8 * 16;
            const float4* xp = (const float4*)(X + (size_t)i0 * H + ch);
            const float4* yp = (const float4*)(Y + (size_t)i1 * H + ch);
            int base = ABASE + r8 * WROW + c8 * 8;
            __syncthreads();
#pragma unroll
            for (int q = 0; q < 4; q++) {
                float4 xv = xp[q], yv = yp[q];
                int c = ch + q * 4;
                float v0 = fmaxf(xv.x + yv.x + __ldg(&b1[c]),     0.f);
                float v1 = fmaxf(xv.y + yv.y + __ldg(&b1[c + 1]), 0.f);
                float v2 = fmaxf(xv.z + yv.z + __ldg(&b1[c + 2]), 0.f);
                float v3 = fmaxf(xv.w + yv.w + __ldg(&b1[c + 3]), 0.f);
                *(uint2*)(sm + base + 2 * q)         = make_uint2(phi(v0, v1), phi(v2, v3));
                *(uint2*)(sm + base + AHALF + 2 * q) = make_uint2(plo(v0, v1), plo(v2, v3));
            }
        }
        __syncthreads();

        float acc[4][4];
#pragma unroll
        for (int nf = 0; nf < 4; nf++)
#pragma unroll
            for (int q = 0; q < 4; q++) acc[nf][q] = 0.f;
        gemm_core16<8>(sm, ABASE, ABASE + AHALF, WH_W, WL_W, acc, wm, wn, lane);

        const int lg = lane >> 2, lt = lane & 3;
        float p0 = 0.f, p1 = 0.f;
#pragma unroll
        for (int nf = 0; nf < 4; nf++) {
            int col = wn + nf * 8 + lt * 2;
            float b0 = __ldg(&b2[col]), b1v = __ldg(&b2[col + 1]);
            float w30 = __ldg(&W3[col]), w31 = __ldg(&W3[col + 1]);
            p0 += fmaxf(acc[nf][0] + b0, 0.f) * w30
                + fmaxf(acc[nf][1] + b1v, 0.f) * w31;
            p1 += fmaxf(acc[nf][2] + b0, 0.f) * w30
                + fmaxf(acc[nf][3] + b1v, 0.f) * w31;
        }
        p0 += __shfl_xor_sync(0xFFFFFFFFu, p0, 1);
        p0 += __shfl_xor_sync(0xFFFFFFFFu, p0, 2);
        p1 += __shfl_xor_sync(0xFFFFFFFFu, p1, 1);
        p1 += __shfl_xor_sync(0xFFFFFFFFu, p1, 2);
        if (lt == 0) {
            sp[wm + lg +     64 * (wn >> 5)] = p0;
            sp[wm + lg + 8 + 64 * (wn >> 5)] = p1;
        }
        __syncthreads();
        if (tid < 64) {
            int r = t0 + tid;
            if (r < nrows) {
                float s = sp[tid] + sp[tid + 64] + sp[tid + 128] + sp[tid + 192] + __ldg(&b3[0]);
                pout[r] = 1.f / (1.f + expf(-s));
                if (logit_off > 0) pout[logit_off + r] = s;
            }
        }
    }
}

// ---------------- host ----------------
extern "C" void kernel_launch(void* const* d_in, const int* in_sizes, int n_in,
                              void* d_out, int out_size) {
    const float* feat    = (const float*)d_in[0];
    const int*   adj_dst = (const int*)  d_in[1];
    const int*   adj_src = (const int*)  d_in[2];
    const int*   cand_i  = (const int*)  d_in[3];
    const int*   cand_j  = (const int*)  d_in[4];
    const float* enc_W1 = (const float*)d_in[5];
    const float* enc_b1 = (const float*)d_in[6];
    const float* enc_W2 = (const float*)d_in[7];
    const float* enc_b2 = (const float*)d_in[8];
    const float* msg_W1 = (const float*)d_in[9];
    const float* msg_b1 = (const float*)d_in[10];
    const float* msg_W2 = (const float*)d_in[11];
    const float* msg_b2 = (const float*)d_in[12];
    const float* upd_W1 = (const float*)d_in[13];
    const float* upd_b1 = (const float*)d_in[14];
    const float* upd_W2 = (const float*)d_in[15];
    const float* upd_b2 = (const float*)d_in[16];
    const float* pred_W1 = (const float*)d_in[17];
    const float* pred_b1 = (const float*)d_in[18];
    const float* pred_W2 = (const float*)d_in[19];
    const float* pred_b2 = (const float*)d_in[20];
    const float* pred_W3 = (const float*)d_in[21];
    const float* pred_b3 = (const float*)d_in[22];

    int NE = in_sizes[0] / 64;
    int NA = in_sizes[1];
    int NC = in_sizes[3];
    if (NE > NE_MAX) NE = NE_MAX;

    float *P, *Q, *Hagg, *bc;
    int* deg;
    u16 *eh, *el, *e2h, *e2l, *hh, *hl, *wh, *wl;
    cudaGetSymbolAddress((void**)&P,    g_P);
    cudaGetSymbolAddress((void**)&Q,    g_Q);
    cudaGetSymbolAddress((void**)&Hagg, g_agg);
    cudaGetSymbolAddress((void**)&deg,  g_deg);
    cudaGetSymbolAddress((void**)&bc,   g_bc);
    cudaGetSymbolAddress((void**)&eh,   g_eh);
    cudaGetSymbolAddress((void**)&el,   g_el);
    cudaGetSymbolAddress((void**)&e2h,  g_e2h);
    cudaGetSymbolAddress((void**)&e2l,  g_e2l);
    cudaGetSymbolAddress((void**)&hh,   g_hh);
    cudaGetSymbolAddress((void**)&hl,   g_hl);
    cudaGetSymbolAddress((void**)&wh,   g_wh);
    cudaGetSymbolAddress((void**)&wl,   g_wl);

    cudaFuncSetAttribute(gk_plain<2, 4, 1>, cudaFuncAttributeMaxDynamicSharedMemorySize, SMEM_BYTES);
    cudaFuncSetAttribute(gk_plain<0, 8, 2>, cudaFuncAttributeMaxDynamicSharedMemorySize, SMEM_BYTES);
    cudaFuncSetAttribute(gk_plain<0, 8, 1>, cudaFuncAttributeMaxDynamicSharedMemorySize, SMEM_BYTES);
    cudaFuncSetAttribute(gk_dual, cudaFuncAttributeMaxDynamicSharedMemorySize, D_SMEM_BYTES);
    cudaFuncSetAttribute(gk_upd,  cudaFuncAttributeMaxDynamicSharedMemorySize, D_SMEM_BYTES);
    cudaFuncSetAttribute(gk_pair, cudaFuncAttributeMaxDynamicSharedMemorySize, SMEM_BYTES);

    cudaMemsetAsync(deg, 0, (size_t)NE * sizeof(int));
    deg_kernel<<<(NA + 255) / 256, 256>>>(adj_dst, NA, deg);

    // ---- weight prep ----
    PJobs pj;
    int cursor = 0, nj = 0;
    auto addjob = [&](const float* W, int ro, int K, int off) {
        pj.W[nj] = W; pj.rowoff[nj] = ro; pj.K[nj] = K; pj.off[nj] = off;
        pj.start[nj] = cursor; cursor += 128 * K; nj++;
    };
    addjob(enc_W1, 0, 64, OFF_ENC1);
    addjob(enc_W2, 0, 128, OFF_ENC2);
    for (int l = 0; l < 3; l++) {
        const float* mW1 = msg_W1 + (size_t)l * 2 * H * H;
        const float* uW1 = upd_W1 + (size_t)l * 2 * H * H;
        const float* uW2 = upd_W2 + (size_t)l * H * H;
        addjob(mW1, 0,   128, OFF_W1T(l));
        addjob(mW1, 128, 128, OFF_W1B(l));
        addjob(uW1, 0,   128, OFF_U1T(l));
        addjob(uW2, 0,   128, OFF_UW2(l));
    }
    addjob(pred_W1, 0,   128, OFF_P1T);
    addjob(pred_W1, 128, 128, OFF_P1B);
    addjob(pred_W2, 0,   128, OFF_P2);
    pj.njobs = nj; pj.total = cursor;
    prep_all<<<(cursor + 255) / 256, 256>>>(pj);
    compprep<<<195, 256>>>(upd_W1, msg_W2, msg_b2, upd_b1);

    int gNE = (NE + 63) / 64;
    int gNC = (NC + 63) / 64;
    int gE = gNE < 148 ? gNE : 148;
    int gC = gNC < 148 ? gNC : 148;

    // encoder
    gk_plain<2, 4, 1><<<gE, 512, SMEM_BYTES>>>(
        feat, nullptr, nullptr, wh + OFF_ENC1, wl + OFF_ENC1,
        enc_b1, e2h, e2l, NE, gNE);
    gk_plain<0, 8, 2><<<gE, 512, SMEM_BYTES>>>(
        nullptr, e2h, e2l, wh + OFF_ENC2, wl + OFF_ENC2,
        enc_b2, eh, el, NE, gNE);

    u16 *ch = eh, *cl = el, *nh = e2h, *nl = e2l;
    for (int l = 0; l < 3; l++) {
        const float* mb1 = msg_b1 + (size_t)l * H;
        const float* ub2 = upd_b2 + (size_t)l * H;

        // P = e@W1top, Q = e@W1bot (one fused launch)
        gk_dual<<<gE, 512, D_SMEM_BYTES>>>(
            ch, cl, wh + OFF_W1T(l), wl + OFF_W1T(l),
            wh + OFF_W1B(l), wl + OFF_W1B(l), P, Q, NE, gNE);

        cudaMemsetAsync(Hagg, 0, (size_t)NE * H * sizeof(float));
        msum<<<(NA + 127) / 128, 256>>>(P, Q, mb1, adj_dst, adj_src, Hagg, NA);
        fixup<<<(NE + 255) / 256, 256>>>(P, Q, mb1, deg, Hagg, NE);

        // hid = ReLU(e@U1T + (Hagg*inv)@WC + bc)  (one fused launch, bf16 out)
        gk_upd<<<gE, 512, D_SMEM_BYTES>>>(
            ch, cl, Hagg,
            wh + OFF_U1T(l), wl + OFF_U1T(l), wh + OFF_WC(l), wl + OFF_WC(l),
            bc + l * H, deg, hh, hl, NE, gNE);

        // e' = ReLU(hid@UW2 + ub2)
        gk_plain<0, 8, 1><<<gE, 512, SMEM_BYTES>>>(
            nullptr, hh, hl, wh + OFF_UW2(l), wl + OFF_UW2(l),
            ub2, nh, nl, NE, gNE);

        u16* t1 = ch; ch = nh; nh = t1;
        u16* t2 = cl; cl = nl; nl = t2;
    }

    // predictor: R,S in one fused launch, then pair kernel
    gk_dual<<<gE, 512, D_SMEM_BYTES>>>(
        ch, cl, wh + OFF_P1T, wl + OFF_P1T,
        wh + OFF_P1B, wl + OFF_P1B, P, Q, NE, gNE);
    int logit_off = (out_size >= 2 * NC) ? NC : -1;
    gk_pair<<<gC, 512, SMEM_BYTES>>>(
        P, Q, cand_i, cand_j, wh + OFF_P2, wl + OFF_P2,
        pred_b1, pred_b2, pred_W3, pred_b3,
        (float*)d_out, NC, gNC, logit_off);
}

// round 12
// speedup vs baseline: 12.8263x; 1.0091x over previous
#include <cuda_runtime.h>
#include <cuda_bf16.h>
#include <stdint.h>
#include <math.h>

#define H 128
#define NE_MAX 50000

typedef unsigned int uint;
typedef unsigned short u16;

// ---------------- device scratch (allocation-free rule) ----------------
__device__ u16   g_eh [NE_MAX * H];
__device__ u16   g_el [NE_MAX * H];
__device__ u16   g_e2h[NE_MAX * H];
__device__ u16   g_e2l[NE_MAX * H];
__device__ u16   g_hh [NE_MAX * H];
__device__ u16   g_hl [NE_MAX * H];
__device__ float g_P  [NE_MAX * H];
__device__ float g_Q  [NE_MAX * H];
__device__ float g_agg[NE_MAX * H];
__device__ int   g_deg[NE_MAX];
__device__ float g_bc [3 * H];
#define WSCRATCH 368640
__device__ u16 g_wh[WSCRATCH];
__device__ u16 g_wl[WSCRATCH];

// transposed/split weight offsets (elements)
#define OFF_ENC1 0
#define OFF_ENC2 8192
#define OFF_L(l)   (24576 + (l) * 98304)
#define OFF_W1T(l) (OFF_L(l))
#define OFF_W1B(l) (OFF_L(l) + 16384)
#define OFF_WC(l)  (OFF_L(l) + 32768)
#define OFF_U1T(l) (OFF_L(l) + 49152)
#define OFF_UW2(l) (OFF_L(l) + 81920)
#define OFF_P1T 319488
#define OFF_P1B 335872
#define OFF_P2  352256

// ---- single-GEMM smem layout ----
#define WROW 68
#define WH_W 0
#define WL_W 8704
#define ABASE 17408
#define ABUF  8704
#define AHALF 4352
#define CTRL_W 34816
#define SMEM_WORDS 35104
#define SMEM_BYTES (SMEM_WORDS * 4)

// ---- dual-GEMM smem layout ----
#define D_W1H 0
#define D_W1L 8704
#define D_W2H 17408
#define D_W2L 26112
#define D_ABASE 34816
#define D_ABUF  8704
#define D_AHALF 4352
#define D_SMEM_WORDS 52224
#define D_SMEM_BYTES (D_SMEM_WORDS * 4)

// ---------------- helpers ----------------
__device__ __forceinline__ uint phi(float a, float b) {
    return (uint)__bfloat16_as_ushort(__float2bfloat16_rn(a))
         | ((uint)__bfloat16_as_ushort(__float2bfloat16_rn(b)) << 16);
}
__device__ __forceinline__ uint plo(float a, float b) {
    float ah = __bfloat162float(__float2bfloat16_rn(a));
    float bh = __bfloat162float(__float2bfloat16_rn(b));
    return phi(a - ah, b - bh);
}
__device__ __forceinline__ uint smem_u32(const void* p) {
    uint a;
    asm("{ .reg .u64 t; cvta.to.shared.u64 t, %1; cvt.u32.u64 %0, t; }" : "=r"(a) : "l"(p));
    return a;
}
__device__ __forceinline__ void cpa16(uint dst, const void* src) {
    asm volatile("cp.async.cg.shared.global [%0], [%1], 16;" :: "r"(dst), "l"(src));
}
#define CPA_COMMIT() asm volatile("cp.async.commit_group;" ::: "memory")
#define CPA_WAIT(n)  asm volatile("cp.async.wait_group %0;" :: "n"(n) : "memory")

__device__ __forceinline__ void mma_bf(float* c, uint a0, uint a1, uint a2, uint a3,
                                       uint b0, uint b1) {
    asm volatile(
        "mma.sync.aligned.m16n8k16.row.col.f32.bf16.bf16.f32 "
        "{%0,%1,%2,%3},{%4,%5,%6,%7},{%8,%9},{%0,%1,%2,%3};"
        : "+f"(c[0]), "+f"(c[1]), "+f"(c[2]), "+f"(c[3])
        : "r"(a0), "r"(a1), "r"(a2), "r"(a3), "r"(b0), "r"(b1));
}
__device__ __forceinline__ void ldsm4(uint& r0, uint& r1, uint& r2, uint& r3, uint addr) {
    asm volatile("ldmatrix.sync.aligned.m8n8.x4.shared.b16 {%0,%1,%2,%3}, [%4];"
        : "=r"(r0), "=r"(r1), "=r"(r2), "=r"(r3) : "r"(addr));
}

// warp tile 16x32 via ldmatrix; 16 warps = 4(M) x 4(N); M-tile 64, N 128
// smem rows stride WROW=68 words -> 4-bank stagger per row: LDSM conflict-free.
template <int NK>
__device__ __forceinline__ void gemm_core_lm(uint sb, int aH, int aL, int wH, int wL,
                                             float acc[4][4], int wm, int wn, int lane) {
    const int l7 = lane & 7, lm = lane >> 3;           // matrix id 0..3
    const int radd = (lm & 1) * 8;                     // row block
    const int koff = (lm >> 1) * 4;                    // k8 block (words)
    uint aBh  = sb + ((uint)(aH + (wm + l7 + radd) * WROW + koff) << 2);
    uint aBl  = sb + ((uint)(aL + (wm + l7 + radd) * WROW + koff) << 2);
    uint bBh0 = sb + ((uint)(wH + (wn + l7 + radd) * WROW + koff) << 2);
    uint bBl0 = sb + ((uint)(wL + (wn + l7 + radd) * WROW + koff) << 2);
    uint bBh1 = bBh0 + 16 * WROW * 4;
    uint bBl1 = bBl0 + 16 * WROW * 4;
#pragma unroll
    for (int ks = 0; ks < NK; ks++) {
        uint ko = ks * 32;
        uint ah0, ah1, ah2, ah3, al0, al1, al2, al3;
        ldsm4(ah0, ah1, ah2, ah3, aBh + ko);
        ldsm4(al0, al1, al2, al3, aBl + ko);
        uint p0, p1, p2, p3, q0, q1, q2, q3;
        ldsm4(p0, p1, p2, p3, bBh0 + ko);   // nf0.b0, nf1.b0, nf0.b1, nf1.b1
        ldsm4(q0, q1, q2, q3, bBh1 + ko);   // nf2/nf3
        uint u0, u1, u2, u3, v0, v1, v2, v3;
        ldsm4(u0, u1, u2, u3, bBl0 + ko);
        ldsm4(v0, v1, v2, v3, bBl1 + ko);
        mma_bf(acc[0], ah0, ah1, ah2, ah3, p0, p2);
        mma_bf(acc[1], ah0, ah1, ah2, ah3, p1, p3);
        mma_bf(acc[2], ah0, ah1, ah2, ah3, q0, q2);
        mma_bf(acc[3], ah0, ah1, ah2, ah3, q1, q3);
        mma_bf(acc[0], ah0, ah1, ah2, ah3, u0, u2);
        mma_bf(acc[1], ah0, ah1, ah2, ah3, u1, u3);
        mma_bf(acc[2], ah0, ah1, ah2, ah3, v0, v2);
        mma_bf(acc[3], ah0, ah1, ah2, ah3, v1, v3);
        mma_bf(acc[0], al0, al1, al2, al3, p0, p2);
        mma_bf(acc[1], al0, al1, al2, al3, p1, p3);
        mma_bf(acc[2], al0, al1, al2, al3, q0, q2);
        mma_bf(acc[3], al0, al1, al2, al3, q1, q3);
    }
}

template <int NK>
__device__ __forceinline__ void load_weights(uint* sm, int dH, int dL,
                                             const u16* Wth, const u16* Wtl, int tid) {
    const int nv = 128 * NK * 2;
    const uint4* sh = (const uint4*)Wth;
    const uint4* sl = (const uint4*)Wtl;
    for (int i = tid; i < nv; i += 512) {
        int n = i / (NK * 2), q = i % (NK * 2);
        *(uint4*)(sm + dH + n * WROW + q * 4) = sh[i];
        *(uint4*)(sm + dL + n * WROW + q * 4) = sl[i];
    }
}

// ---------------- small kernels ----------------
__global__ void deg_kernel(const int* __restrict__ dst, int na, int* __restrict__ deg) {
    int i = blockIdx.x * blockDim.x + threadIdx.x;
    if (i < na) atomicAdd(&deg[dst[i]], 1);
}

struct PJobs {
    const float* W[20];
    int rowoff[20], K[20], off[20], start[20];
    int njobs, total;
};
__global__ void prep_all(PJobs j) {
    int i = blockIdx.x * 256 + threadIdx.x;
    if (i >= j.total) return;
    int a = 0;
    while (a + 1 < j.njobs && i >= j.start[a + 1]) a++;
    int e = i - j.start[a];
    int K = j.K[a];
    int n = e / K, k = e % K;
    float v = j.W[a][(size_t)(j.rowoff[a] + k) * 128 + n];
    __nv_bfloat16 h = __float2bfloat16_rn(v);
    g_wh[j.off[a] + e] = __bfloat16_as_ushort(h);
    g_wl[j.off[a] + e] = __bfloat16_as_ushort(__float2bfloat16_rn(v - __bfloat162float(h)));
}

__global__ void compprep(const float* __restrict__ upd_W1,
                         const float* __restrict__ msg_W2,
                         const float* __restrict__ msg_b2,
                         const float* __restrict__ upd_b1) {
    int b = blockIdx.x;
    if (b < 192) {
        int l = b >> 6;
        int i = (b & 63) * 256 + threadIdx.x;
        int o = i & 127, h = i >> 7;
        const float* W2  = msg_W2 + (size_t)l * 16384;
        const float* U1b = upd_W1 + (size_t)l * 32768 + 16384;
        float s = 0.f;
        for (int a2 = 0; a2 < 128; a2++) s += W2[h * 128 + a2] * U1b[a2 * 128 + o];
        int li = OFF_WC(l) + o * 128 + h;
        __nv_bfloat16 hh = __float2bfloat16_rn(s);
        g_wh[li] = __bfloat16_as_ushort(hh);
        g_wl[li] = __bfloat16_as_ushort(__float2bfloat16_rn(s - __bfloat162float(hh)));
    } else if (b < 195) {
        int l = b - 192;
        int o = threadIdx.x;
        if (o < 128) {
            const float* U1b = upd_W1 + (size_t)l * 32768 + 16384;
            const float* b2  = msg_b2 + (size_t)l * 128;
            float s = upd_b1[l * 128 + o];
            for (int a2 = 0; a2 < 128; a2++) s += b2[a2] * U1b[a2 * 128 + o];
            g_bc[l * 128 + o] = s;
        }
    }
}

// pair hidden aggregation: Hagg[dst] += ReLU(P[dst] + Q[src] + b1)
__global__ __launch_bounds__(256) void msum(const float* __restrict__ P,
                                            const float* __restrict__ Q,
                                            const float* __restrict__ b1,
                                            const int* __restrict__ dst,
                                            const int* __restrict__ src,
                                            float* __restrict__ Hagg, int na) {
    int team = threadIdx.x >> 7, col = threadIdx.x & 127;
    int p0 = blockIdx.x * 128 + team * 64;
    if (p0 >= na) return;
    float bias = __ldg(&b1[col]);
    float sum = 0.f, pv = 0.f;
    int cur = -1;
    for (int base = 0; base < 64; base += 8) {
        int dd[8], ss[8];
#pragma unroll
        for (int j = 0; j < 8; j++) {
            int a = p0 + base + j;
            bool v = a < na;
            dd[j] = v ? __ldg(&dst[a]) : -1;
            ss[j] = v ? __ldg(&src[a]) : 0;
        }
        float qv[8];
#pragma unroll
        for (int j = 0; j < 8; j++) qv[j] = __ldg(&Q[(size_t)ss[j] * H + col]);
#pragma unroll
        for (int j = 0; j < 8; j++) {
            if (dd[j] != cur) {
                if (cur >= 0) atomicAdd(&Hagg[(size_t)cur * H + col], sum);
                cur = dd[j];
                sum = 0.f;
                if (cur >= 0) pv = __ldg(&P[(size_t)cur * H + col]) + bias;
            }
            if (dd[j] >= 0) sum += fmaxf(pv + qv[j], 0.f);
        }
    }
    if (cur >= 0) atomicAdd(&Hagg[(size_t)cur * H + col], sum);
}

__global__ void fixup(const float* __restrict__ P, const float* __restrict__ Q,
                      const float* __restrict__ b1, const int* __restrict__ deg,
                      float* __restrict__ Hagg, int ne) {
    int n = blockIdx.x * 256 + threadIdx.x;
    if (n >= ne || deg[n] != 0) return;
    for (int c = 0; c < H; c++)
        Hagg[(size_t)n * H + c] = fmaxf(P[(size_t)n * H + c] + Q[(size_t)n * H + c] + b1[c], 0.f);
}

// ---------------- fused encoder: e = (ReLU(feat@W1+b1))@W2 + b2 -> bf16 pair ----------------
__global__ __launch_bounds__(512, 1)
void gk_enc(const float* __restrict__ feat,
            const u16* __restrict__ W1h_, const u16* __restrict__ W1l_,
            const u16* __restrict__ W2h_, const u16* __restrict__ W2l_,
            const float* __restrict__ b1, const float* __restrict__ b2,
            u16* __restrict__ obh, u16* __restrict__ obl,
            int nrows, int ntiles)
{
    extern __shared__ uint sm[];
    const int tid = threadIdx.x;
    const int lane = tid & 31, w = tid >> 5;
    const int wm = (w & 3) * 16, wn = (w >> 2) * 32;
    const uint sb = smem_u32(sm);
    const int HID = D_ABASE + D_ABUF;

    load_weights<4>(sm, D_W1H, D_W1L, W1h_, W1l_, tid);
    load_weights<8>(sm, D_W2H, D_W2L, W2h_, W2l_, tid);

    const int r8 = tid >> 3, c8 = tid & 7;
    const int lg = lane >> 2, lt = lane & 3;

    for (int t = blockIdx.x; t < ntiles; t += gridDim.x) {
        const int t0 = t * 64;
        __syncthreads();
        {   // A1 = feat rows (fp32 K=64 -> bf16 hi/lo)
            int gr = t0 + r8;
            int rr = (gr < nrows) ? gr : 0;
            const float4* s = (const float4*)(feat + (size_t)rr * 64) + c8 * 2;
            int base = D_ABASE + r8 * WROW + c8 * 4;
#pragma unroll
            for (int q = 0; q < 2; q++) {
                float4 v = s[q];
                *(uint2*)(sm + base + 2 * q)           = make_uint2(phi(v.x, v.y), phi(v.z, v.w));
                *(uint2*)(sm + base + D_AHALF + 2 * q) = make_uint2(plo(v.x, v.y), plo(v.z, v.w));
            }
        }
        __syncthreads();

        float acc[4][4];
#pragma unroll
        for (int nf = 0; nf < 4; nf++)
#pragma unroll
            for (int q = 0; q < 4; q++) acc[nf][q] = 0.f;
        gemm_core_lm<4>(sb, D_ABASE, D_ABASE + D_AHALF, D_W1H, D_W1L, acc, wm, wn, lane);

        // hid = ReLU(acc + b1) -> smem (bf16 hi/lo pairs)
#pragma unroll
        for (int nf = 0; nf < 4; nf++) {
            int row = wm + lg;
            int col = wn + nf * 8 + lt * 2;
            float b0 = __ldg(&b1[col]), b1v = __ldg(&b1[col + 1]);
            float v0 = fmaxf(acc[nf][0] + b0, 0.f);
            float v1 = fmaxf(acc[nf][1] + b1v, 0.f);
            float v2 = fmaxf(acc[nf][2] + b0, 0.f);
            float v3 = fmaxf(acc[nf][3] + b1v, 0.f);
            int wi = col >> 1;
            sm[HID + row * WROW + wi]                 = phi(v0, v1);
            sm[HID + D_AHALF + row * WROW + wi]       = plo(v0, v1);
            sm[HID + (row + 8) * WROW + wi]           = phi(v2, v3);
            sm[HID + D_AHALF + (row + 8) * WROW + wi] = plo(v2, v3);
        }
        __syncthreads();

#pragma unroll
        for (int nf = 0; nf < 4; nf++)
#pragma unroll
            for (int q = 0; q < 4; q++) acc[nf][q] = 0.f;
        gemm_core_lm<8>(sb, HID, HID + D_AHALF, D_W2H, D_W2L, acc, wm, wn, lane);

#pragma unroll
        for (int nf = 0; nf < 4; nf++) {
            int row = wm + lg;
            int col = wn + nf * 8 + lt * 2;
            int g0 = t0 + row, g1 = g0 + 8;
            float b0 = __ldg(&b2[col]), b1v = __ldg(&b2[col + 1]);
            float v0 = acc[nf][0] + b0, v1 = acc[nf][1] + b1v;
            float v2 = acc[nf][2] + b0, v3 = acc[nf][3] + b1v;
            int wi = col >> 1;
            if (g0 < nrows) {
                ((uint*)obh)[(size_t)g0 * 64 + wi] = phi(v0, v1);
                ((uint*)obl)[(size_t)g0 * 64 + wi] = plo(v0, v1);
            }
            if (g1 < nrows) {
                ((uint*)obh)[(size_t)g1 * 64 + wi] = phi(v2, v3);
                ((uint*)obl)[(size_t)g1 * 64 + wi] = plo(v2, v3);
            }
        }
    }
}

// ---------------- single GEMM (bf16 in, cp.async double-buffer) ----------------
// EPI: 1 = bias+ReLU -> bf16 pair
__global__ __launch_bounds__(512, 1)
void gk_plain(const u16* __restrict__ Aph, const u16* __restrict__ Apl,
              const u16* __restrict__ Wth, const u16* __restrict__ Wtl,
              const float* __restrict__ bias,
              u16* __restrict__ obh, u16* __restrict__ obl,
              int nrows, int ntiles)
{
    extern __shared__ uint sm[];
    const int tid = threadIdx.x;
    const int lane = tid & 31, w = tid >> 5;
    const int wm = (w & 3) * 16, wn = (w >> 2) * 32;
    const uint sb = smem_u32(sm);

    load_weights<8>(sm, WH_W, WL_W, Wth, Wtl, tid);

    const int r8 = tid >> 3, c8 = tid & 7;

    auto fill_async = [&](int t, int p) {
        int gr = t * 64 + r8;
        int rr = (gr < nrows) ? gr : 0;
        const char* shp = (const char*)(Aph + (size_t)rr * H) + c8 * 16;
        const char* slp = (const char*)(Apl + (size_t)rr * H) + c8 * 16;
        uint dh = sb + (ABASE + p * ABUF + r8 * WROW + c8 * 4) * 4;
        uint dl = dh + AHALF * 4;
        cpa16(dh, shp);        cpa16(dh + 128, shp + 128);
        cpa16(dl, slp);        cpa16(dl + 128, slp + 128);
        CPA_COMMIT();
    };

    int p = 0;
    fill_async(blockIdx.x < ntiles ? blockIdx.x : 0, 0);

    for (int t = blockIdx.x; t < ntiles; t += gridDim.x) {
        __syncthreads();
        int tn = t + gridDim.x;
        fill_async(tn < ntiles ? tn : t, p ^ 1);
        CPA_WAIT(1);
        __syncthreads();

        float acc[4][4];
#pragma unroll
        for (int nf = 0; nf < 4; nf++)
#pragma unroll
            for (int q = 0; q < 4; q++) acc[nf][q] = 0.f;
        int aH = ABASE + p * ABUF;
        gemm_core_lm<8>(sb, aH, aH + AHALF, WH_W, WL_W, acc, wm, wn, lane);

        const int t0 = t * 64;
        const int lg = lane >> 2, lt = lane & 3;
#pragma unroll
        for (int nf = 0; nf < 4; nf++) {
            int row = wm + lg;
            int col = wn + nf * 8 + lt * 2;
            int g0 = t0 + row, g1 = g0 + 8;
            float b0 = __ldg(&bias[col]), b1v = __ldg(&bias[col + 1]);
            float v0 = fmaxf(acc[nf][0] + b0, 0.f);
            float v1 = fmaxf(acc[nf][1] + b1v, 0.f);
            float v2 = fmaxf(acc[nf][2] + b0, 0.f);
            float v3 = fmaxf(acc[nf][3] + b1v, 0.f);
            int wi = col >> 1;
            if (g0 < nrows) {
                ((uint*)obh)[(size_t)g0 * 64 + wi] = phi(v0, v1);
                ((uint*)obl)[(size_t)g0 * 64 + wi] = plo(v0, v1);
            }
            if (g1 < nrows) {
                ((uint*)obh)[(size_t)g1 * 64 + wi] = phi(v2, v3);
                ((uint*)obl)[(size_t)g1 * 64 + wi] = plo(v2, v3);
            }
        }
        p ^= 1;
    }
}

// ---------------- dual GEMM, shared A: out1 = A@W1, out2 = A@W2 (fp32 raw) ----------------
__global__ __launch_bounds__(512, 1)
void gk_dual(const u16* __restrict__ Aph, const u16* __restrict__ Apl,
             const u16* __restrict__ W1h_, const u16* __restrict__ W1l_,
             const u16* __restrict__ W2h_, const u16* __restrict__ W2l_,
             float* __restrict__ out1, float* __restrict__ out2,
             int nrows, int ntiles)
{
    extern __shared__ uint sm[];
    const int tid = threadIdx.x;
    const int lane = tid & 31, w = tid >> 5;
    const int wm = (w & 3) * 16, wn = (w >> 2) * 32;
    const uint sb = smem_u32(sm);

    load_weights<8>(sm, D_W1H, D_W1L, W1h_, W1l_, tid);
    load_weights<8>(sm, D_W2H, D_W2L, W2h_, W2l_, tid);

    const int r8 = tid >> 3, c8 = tid & 7;
    auto fill_async = [&](int t, int p) {
        int gr = t * 64 + r8;
        int rr = (gr < nrows) ? gr : 0;
        const char* shp = (const char*)(Aph + (size_t)rr * H) + c8 * 16;
        const char* slp = (const char*)(Apl + (size_t)rr * H) + c8 * 16;
        uint dh = sb + (D_ABASE + p * D_ABUF + r8 * WROW + c8 * 4) * 4;
        uint dl = dh + D_AHALF * 4;
        cpa16(dh, shp);        cpa16(dh + 128, shp + 128);
        cpa16(dl, slp);        cpa16(dl + 128, slp + 128);
        CPA_COMMIT();
    };

    int p = 0;
    fill_async(blockIdx.x < ntiles ? blockIdx.x : 0, 0);

    for (int t = blockIdx.x; t < ntiles; t += gridDim.x) {
        __syncthreads();
        int tn = t + gridDim.x;
        fill_async(tn < ntiles ? tn : t, p ^ 1);
        CPA_WAIT(1);
        __syncthreads();

        int aH = D_ABASE + p * D_ABUF;
        float acc1[4][4], acc2[4][4];
#pragma unroll
        for (int nf = 0; nf < 4; nf++)
#pragma unroll
            for (int q = 0; q < 4; q++) { acc1[nf][q] = 0.f; acc2[nf][q] = 0.f; }
        gemm_core_lm<8>(sb, aH, aH + D_AHALF, D_W1H, D_W1L, acc1, wm, wn, lane);
        gemm_core_lm<8>(sb, aH, aH + D_AHALF, D_W2H, D_W2L, acc2, wm, wn, lane);

        const int t0 = t * 64;
        const int lg = lane >> 2, lt = lane & 3;
#pragma unroll
        for (int nf = 0; nf < 4; nf++) {
            int row = wm + lg;
            int col = wn + nf * 8 + lt * 2;
            int g0 = t0 + row, g1 = g0 + 8;
            if (g0 < nrows) {
                *(float2*)&out1[(size_t)g0 * H + col] = make_float2(acc1[nf][0], acc1[nf][1]);
                *(float2*)&out2[(size_t)g0 * H + col] = make_float2(acc2[nf][0], acc2[nf][1]);
            }
            if (g1 < nrows) {
                *(float2*)&out1[(size_t)g1 * H + col] = make_float2(acc1[nf][2], acc1[nf][3]);
                *(float2*)&out2[(size_t)g1 * H + col] = make_float2(acc2[nf][2], acc2[nf][3]);
            }
        }
        p ^= 1;
    }
}

// ---------------- update fused: hid = ReLU(e@U1T + (Hagg*inv_deg)@WC + bias) -> bf16 ----------------
__global__ __launch_bounds__(512, 1)
void gk_upd(const u16* __restrict__ Aph, const u16* __restrict__ Apl,
            const float* __restrict__ Hagg,
            const u16* __restrict__ W1h_, const u16* __restrict__ W1l_,
            const u16* __restrict__ W2h_, const u16* __restrict__ W2l_,
            const float* __restrict__ bias, const int* __restrict__ deg,
            u16* __restrict__ obh, u16* __restrict__ obl,
            int nrows, int ntiles)
{
    extern __shared__ uint sm[];
    const int tid = threadIdx.x;
    const int lane = tid & 31, w = tid >> 5;
    const int wm = (w & 3) * 16, wn = (w >> 2) * 32;
    const uint sb = smem_u32(sm);

    load_weights<8>(sm, D_W1H, D_W1L, W1h_, W1l_, tid);
    load_weights<8>(sm, D_W2H, D_W2L, W2h_, W2l_, tid);

    const int r8 = tid >> 3, c8 = tid & 7;

    for (int t = blockIdx.x; t < ntiles; t += gridDim.x) {
        const int t0 = t * 64;
        int gr = t0 + r8;
        int rr = (gr < nrows) ? gr : 0;
        __syncthreads();
        {   // A1: e via cp.async
            const char* shp = (const char*)(Aph + (size_t)rr * H) + c8 * 16;
            const char* slp = (const char*)(Apl + (size_t)rr * H) + c8 * 16;
            uint dh = sb + (D_ABASE + r8 * WROW + c8 * 4) * 4;
            uint dl = dh + D_AHALF * 4;
            cpa16(dh, shp);        cpa16(dh + 128, shp + 128);
            cpa16(dl, slp);        cpa16(dl + 128, slp + 128);
            CPA_COMMIT();
        }
        {   // A2: Hagg * inv_deg
            int d = deg[rr];
            float sc = 1.f / (d > 1 ? (float)d : 1.f);
            const float4* s = (const float4*)(Hagg + (size_t)rr * H) + c8 * 4;
            int base = D_ABASE + D_ABUF + r8 * WROW + c8 * 8;
#pragma unroll
            for (int q = 0; q < 4; q++) {
                float4 v = s[q];
                v.x *= sc; v.y *= sc; v.z *= sc; v.w *= sc;
                *(uint2*)(sm + base + 2 * q)           = make_uint2(phi(v.x, v.y), phi(v.z, v.w));
                *(uint2*)(sm + base + D_AHALF + 2 * q) = make_uint2(plo(v.x, v.y), plo(v.z, v.w));
            }
        }
        CPA_WAIT(0);
        __syncthreads();

        float acc[4][4];
#pragma unroll
        for (int nf = 0; nf < 4; nf++)
#pragma unroll
            for (int q = 0; q < 4; q++) acc[nf][q] = 0.f;
        gemm_core_lm<8>(sb, D_ABASE, D_ABASE + D_AHALF, D_W1H, D_W1L, acc, wm, wn, lane);
        gemm_core_lm<8>(sb, D_ABASE + D_ABUF, D_ABASE + D_ABUF + D_AHALF, D_W2H, D_W2L, acc, wm, wn, lane);

        const int lg = lane >> 2, lt = lane & 3;
#pragma unroll
        for (int nf = 0; nf < 4; nf++) {
            int row = wm + lg;
            int col = wn + nf * 8 + lt * 2;
            int g0 = t0 + row, g1 = g0 + 8;
            float b0 = __ldg(&bias[col]), b1v = __ldg(&bias[col + 1]);
            float v0 = fmaxf(acc[nf][0] + b0, 0.f);
            float v1 = fmaxf(acc[nf][1] + b1v, 0.f);
            float v2 = fmaxf(acc[nf][2] + b0, 0.f);
            float v3 = fmaxf(acc[nf][3] + b1v, 0.f);
            int wi = col >> 1;
            if (g0 < nrows) {
                ((uint*)obh)[(size_t)g0 * 64 + wi] = phi(v0, v1);
                ((uint*)obl)[(size_t)g0 * 64 + wi] = plo(v0, v1);
            }
            if (g1 < nrows) {
                ((uint*)obh)[(size_t)g1 * 64 + wi] = phi(v2, v3);
                ((uint*)obl)[(size_t)g1 * 64 + wi] = plo(v2, v3);
            }
        }
    }
}

// ---------------- pairsum GEMM + predictor epilogue ----------------
__global__ __launch_bounds__(512, 1)
void gk_pair(const float* __restrict__ X, const float* __restrict__ Y,
             const int* __restrict__ idx0, const int* __restrict__ idx1,
             const u16* __restrict__ Wth, const u16* __restrict__ Wtl,
             const float* __restrict__ b1, const float* __restrict__ b2,
             const float* __restrict__ W3, const float* __restrict__ b3,
             float* __restrict__ pout,
             int nrows, int ntiles, int logit_off)
{
    extern __shared__ uint sm[];
    float* sp = (float*)(sm + CTRL_W);

    const int tid = threadIdx.x;
    const int lane = tid & 31, w = tid >> 5;
    const int wm = (w & 3) * 16, wn = (w >> 2) * 32;
    const uint sb = smem_u32(sm);

    load_weights<8>(sm, WH_W, WL_W, Wth, Wtl, tid);

    const int r8 = tid >> 3, c8 = tid & 7;

    for (int t = blockIdx.x; t < ntiles; t += gridDim.x) {
        const int t0 = t * 64;
        {
            int gr = t0 + r8;
            int rr = (gr < nrows) ? gr : 0;
            int i0 = __ldg(&idx0[rr]);
            int i1 = __ldg(&idx1[rr]);
            int ch = c8 * 16;
            const float4* xp = (const float4*)(X + (size_t)i0 * H + ch);
            const float4* yp = (const float4*)(Y + (size_t)i1 * H + ch);
            int base = ABASE + r8 * WROW + c8 * 8;
            __syncthreads();
#pragma unroll
            for (int q = 0; q < 4; q++) {
                float4 xv = xp[q], yv = yp[q];
                int c = ch + q * 4;
                float v0 = fmaxf(xv.x + yv.x + __ldg(&b1[c]),     0.f);
                float v1 = fmaxf(xv.y + yv.y + __ldg(&b1[c + 1]), 0.f);
                float v2 = fmaxf(xv.z + yv.z + __ldg(&b1[c + 2]), 0.f);
                float v3 = fmaxf(xv.w + yv.w + __ldg(&b1[c + 3]), 0.f);
                *(uint2*)(sm + base + 2 * q)         = make_uint2(phi(v0, v1), phi(v2, v3));
                *(uint2*)(sm + base + AHALF + 2 * q) = make_uint2(plo(v0, v1), plo(v2, v3));
            }
        }
        __syncthreads();

        float acc[4][4];
#pragma unroll
        for (int nf = 0; nf < 4; nf++)
#pragma unroll
            for (int q = 0; q < 4; q++) acc[nf][q] = 0.f;
        gemm_core_lm<8>(sb, ABASE, ABASE + AHALF, WH_W, WL_W, acc, wm, wn, lane);

        const int lg = lane >> 2, lt = lane & 3;
        float p0 = 0.f, p1 = 0.f;
#pragma unroll
        for (int nf = 0; nf < 4; nf++) {
            int col = wn + nf * 8 + lt * 2;
            float b0 = __ldg(&b2[col]), b1v = __ldg(&b2[col + 1]);
            float w30 = __ldg(&W3[col]), w31 = __ldg(&W3[col + 1]);
            p0 += fmaxf(acc[nf][0] + b0, 0.f) * w30
                + fmaxf(acc[nf][1] + b1v, 0.f) * w31;
            p1 += fmaxf(acc[nf][2] + b0, 0.f) * w30
                + fmaxf(acc[nf][3] + b1v, 0.f) * w31;
        }
        p0 += __shfl_xor_sync(0xFFFFFFFFu, p0, 1);
        p0 += __shfl_xor_sync(0xFFFFFFFFu, p0, 2);
        p1 += __shfl_xor_sync(0xFFFFFFFFu, p1, 1);
        p1 += __shfl_xor_sync(0xFFFFFFFFu, p1, 2);
        if (lt == 0) {
            sp[wm + lg +     64 * (wn >> 5)] = p0;
            sp[wm + lg + 8 + 64 * (wn >> 5)] = p1;
        }
        __syncthreads();
        if (tid < 64) {
            int r = t0 + tid;
            if (r < nrows) {
                float s = sp[tid] + sp[tid + 64] + sp[tid + 128] + sp[tid + 192] + __ldg(&b3[0]);
                pout[r] = 1.f / (1.f + expf(-s));
                if (logit_off > 0) pout[logit_off + r] = s;
            }
        }
    }
}

// ---------------- host ----------------
extern "C" void kernel_launch(void* const* d_in, const int* in_sizes, int n_in,
                              void* d_out, int out_size) {
    const float* feat    = (const float*)d_in[0];
    const int*   adj_dst = (const int*)  d_in[1];
    const int*   adj_src = (const int*)  d_in[2];
    const int*   cand_i  = (const int*)  d_in[3];
    const int*   cand_j  = (const int*)  d_in[4];
    const float* enc_W1 = (const float*)d_in[5];
    const float* enc_b1 = (const float*)d_in[6];
    const float* enc_W2 = (const float*)d_in[7];
    const float* enc_b2 = (const float*)d_in[8];
    const float* msg_W1 = (const float*)d_in[9];
    const float* msg_b1 = (const float*)d_in[10];
    const float* msg_W2 = (const float*)d_in[11];
    const float* msg_b2 = (const float*)d_in[12];
    const float* upd_W1 = (const float*)d_in[13];
    const float* upd_b1 = (const float*)d_in[14];
    const float* upd_W2 = (const float*)d_in[15];
    const float* upd_b2 = (const float*)d_in[16];
    const float* pred_W1 = (const float*)d_in[17];
    const float* pred_b1 = (const float*)d_in[18];
    const float* pred_W2 = (const float*)d_in[19];
    const float* pred_b2 = (const float*)d_in[20];
    const float* pred_W3 = (const float*)d_in[21];
    const float* pred_b3 = (const float*)d_in[22];

    int NE = in_sizes[0] / 64;
    int NA = in_sizes[1];
    int NC = in_sizes[3];
    if (NE > NE_MAX) NE = NE_MAX;

    float *P, *Q, *Hagg, *bc;
    int* deg;
    u16 *eh, *el, *e2h, *e2l, *hh, *hl, *wh, *wl;
    cudaGetSymbolAddress((void**)&P,    g_P);
    cudaGetSymbolAddress((void**)&Q,    g_Q);
    cudaGetSymbolAddress((void**)&Hagg, g_agg);
    cudaGetSymbolAddress((void**)&deg,  g_deg);
    cudaGetSymbolAddress((void**)&bc,   g_bc);
    cudaGetSymbolAddress((void**)&eh,   g_eh);
    cudaGetSymbolAddress((void**)&el,   g_el);
    cudaGetSymbolAddress((void**)&e2h,  g_e2h);
    cudaGetSymbolAddress((void**)&e2l,  g_e2l);
    cudaGetSymbolAddress((void**)&hh,   g_hh);
    cudaGetSymbolAddress((void**)&hl,   g_hl);
    cudaGetSymbolAddress((void**)&wh,   g_wh);
    cudaGetSymbolAddress((void**)&wl,   g_wl);

    cudaFuncSetAttribute(gk_enc,   cudaFuncAttributeMaxDynamicSharedMemorySize, D_SMEM_BYTES);
    cudaFuncSetAttribute(gk_plain, cudaFuncAttributeMaxDynamicSharedMemorySize, SMEM_BYTES);
    cudaFuncSetAttribute(gk_dual,  cudaFuncAttributeMaxDynamicSharedMemorySize, D_SMEM_BYTES);
    cudaFuncSetAttribute(gk_upd,   cudaFuncAttributeMaxDynamicSharedMemorySize, D_SMEM_BYTES);
    cudaFuncSetAttribute(gk_pair,  cudaFuncAttributeMaxDynamicSharedMemorySize, SMEM_BYTES);

    cudaMemsetAsync(deg, 0, (size_t)NE * sizeof(int));
    deg_kernel<<<(NA + 255) / 256, 256>>>(adj_dst, NA, deg);

    // ---- weight prep ----
    PJobs pj;
    int cursor = 0, nj = 0;
    auto addjob = [&](const float* W, int ro, int K, int off) {
        pj.W[nj] = W; pj.rowoff[nj] = ro; pj.K[nj] = K; pj.off[nj] = off;
        pj.start[nj] = cursor; cursor += 128 * K; nj++;
    };
    addjob(enc_W1, 0, 64, OFF_ENC1);
    addjob(enc_W2, 0, 128, OFF_ENC2);
    for (int l = 0; l < 3; l++) {
        const float* mW1 = msg_W1 + (size_t)l * 2 * H * H;
        const float* uW1 = upd_W1 + (size_t)l * 2 * H * H;
        const float* uW2 = upd_W2 + (size_t)l * H * H;
        addjob(mW1, 0,   128, OFF_W1T(l));
        addjob(mW1, 128, 128, OFF_W1B(l));
        addjob(uW1, 0,   128, OFF_U1T(l));
        addjob(uW2, 0,   128, OFF_UW2(l));
    }
    addjob(pred_W1, 0,   128, OFF_P1T);
    addjob(pred_W1, 128, 128, OFF_P1B);
    addjob(pred_W2, 0,   128, OFF_P2);
    pj.njobs = nj; pj.total = cursor;
    prep_all<<<(cursor + 255) / 256, 256>>>(pj);
    compprep<<<195, 256>>>(upd_W1, msg_W2, msg_b2, upd_b1);

    int gNE = (NE + 63) / 64;
    int gNC = (NC + 63) / 64;
    int gE = gNE < 148 ? gNE : 148;
    int gC = gNC < 148 ? gNC : 148;

    // fused encoder
    gk_enc<<<gE, 512, D_SMEM_BYTES>>>(
        feat, wh + OFF_ENC1, wl + OFF_ENC1, wh + OFF_ENC2, wl + OFF_ENC2,
        enc_b1, enc_b2, eh, el, NE, gNE);

    u16 *ch = eh, *cl = el, *nh = e2h, *nl = e2l;
    for (int l = 0; l < 3; l++) {
        const float* mb1 = msg_b1 + (size_t)l * H;
        const float* ub2 = upd_b2 + (size_t)l * H;

        gk_dual<<<gE, 512, D_SMEM_BYTES>>>(
            ch, cl, wh + OFF_W1T(l), wl + OFF_W1T(l),
            wh + OFF_W1B(l), wl + OFF_W1B(l), P, Q, NE, gNE);

        cudaMemsetAsync(Hagg, 0, (size_t)NE * H * sizeof(float));
        msum<<<(NA + 127) / 128, 256>>>(P, Q, mb1, adj_dst, adj_src, Hagg, NA);
        fixup<<<(NE + 255) / 256, 256>>>(P, Q, mb1, deg, Hagg, NE);

        gk_upd<<<gE, 512, D_SMEM_BYTES>>>(
            ch, cl, Hagg,
            wh + OFF_U1T(l), wl + OFF_U1T(l), wh + OFF_WC(l), wl + OFF_WC(l),
            bc + l * H, deg, hh, hl, NE, gNE);

        gk_plain<<<gE, 512, SMEM_BYTES>>>(
            hh, hl, wh + OFF_UW2(l), wl + OFF_UW2(l),
            ub2, nh, nl, NE, gNE);

        u16* t1 = ch; ch = nh; nh = t1;
        u16* t2 = cl; cl = nl; nl = t2;
    }

    gk_dual<<<gE, 512, D_SMEM_BYTES>>>(
        ch, cl, wh + OFF_P1T, wl + OFF_P1T,
        wh + OFF_P1B, wl + OFF_P1B, P, Q, NE, gNE);
    int logit_off = (out_size >= 2 * NC) ? NC : -1;
    gk_pair<<<gC, 512, SMEM_BYTES>>>(
        P, Q, cand_i, cand_j, wh + OFF_P2, wl + OFF_P2,
        pred_b1, pred_b2, pred_W3, pred_b3,
        (float*)d_out, NC, gNC, logit_off);
}

// round 13
// speedup vs baseline: 13.1450x; 1.0248x over previous
#include <cuda_runtime.h>
#include <cuda_bf16.h>
#include <cuda_fp16.h>
#include <stdint.h>
#include <math.h>

#define H 128
#define NE_MAX 50000

typedef unsigned int uint;
typedef unsigned short u16;

// ---------------- device scratch (allocation-free rule) ----------------
__device__ u16   g_eh [NE_MAX * H];
__device__ u16   g_el [NE_MAX * H];
__device__ u16   g_e2h[NE_MAX * H];
__device__ u16   g_e2l[NE_MAX * H];
__device__ u16   g_hh [NE_MAX * H];
__device__ u16   g_hl [NE_MAX * H];
__device__ u16   g_Pq [NE_MAX * H];      // fp16 P
__device__ u16   g_Qq [NE_MAX * H];      // fp16 Q
__device__ float g_agg[NE_MAX * H];
__device__ int   g_deg[NE_MAX];
__device__ float g_bc [3 * H];
#define WSCRATCH 368640
__device__ u16 g_wh[WSCRATCH];
__device__ u16 g_wl[WSCRATCH];

// transposed/split weight offsets (elements)
#define OFF_ENC1 0
#define OFF_ENC2 8192
#define OFF_L(l)   (24576 + (l) * 98304)
#define OFF_W1T(l) (OFF_L(l))
#define OFF_W1B(l) (OFF_L(l) + 16384)
#define OFF_WC(l)  (OFF_L(l) + 32768)
#define OFF_U1T(l) (OFF_L(l) + 49152)
#define OFF_UW2(l) (OFF_L(l) + 81920)
#define OFF_P1T 319488
#define OFF_P1B 335872
#define OFF_P2  352256

// ---- single-GEMM smem layout ----
#define WROW 68
#define WH_W 0
#define WL_W 8704
#define ABASE 17408
#define ABUF  8704
#define AHALF 4352
#define CTRL_W 34816
#define SMEM_WORDS 35104
#define SMEM_BYTES (SMEM_WORDS * 4)

// ---- dual-GEMM smem layout ----
#define D_W1H 0
#define D_W1L 8704
#define D_W2H 17408
#define D_W2L 26112
#define D_ABASE 34816
#define D_ABUF  8704
#define D_AHALF 4352
#define D_SMEM_WORDS 52224
#define D_SMEM_BYTES (D_SMEM_WORDS * 4)

// ---------------- helpers ----------------
__device__ __forceinline__ uint phi(float a, float b) {
    return (uint)__bfloat16_as_ushort(__float2bfloat16_rn(a))
         | ((uint)__bfloat16_as_ushort(__float2bfloat16_rn(b)) << 16);
}
__device__ __forceinline__ uint plo(float a, float b) {
    float ah = __bfloat162float(__float2bfloat16_rn(a));
    float bh = __bfloat162float(__float2bfloat16_rn(b));
    return phi(a - ah, b - bh);
}
__device__ __forceinline__ uint h2u(float a, float b) {
    __half2 h = __floats2half2_rn(a, b);
    return *(uint*)&h;
}
__device__ __forceinline__ float2 u2f(uint u) {
    return __half22float2(*(const __half2*)&u);
}
__device__ __forceinline__ uint smem_u32(const void* p) {
    uint a;
    asm("{ .reg .u64 t; cvta.to.shared.u64 t, %1; cvt.u32.u64 %0, t; }" : "=r"(a) : "l"(p));
    return a;
}
__device__ __forceinline__ void cpa16(uint dst, const void* src) {
    asm volatile("cp.async.cg.shared.global [%0], [%1], 16;" :: "r"(dst), "l"(src));
}
#define CPA_COMMIT() asm volatile("cp.async.commit_group;" ::: "memory")
#define CPA_WAIT(n)  asm volatile("cp.async.wait_group %0;" :: "n"(n) : "memory")

__device__ __forceinline__ void mma_bf(float* c, uint a0, uint a1, uint a2, uint a3,
                                       uint b0, uint b1) {
    asm volatile(
        "mma.sync.aligned.m16n8k16.row.col.f32.bf16.bf16.f32 "
        "{%0,%1,%2,%3},{%4,%5,%6,%7},{%8,%9},{%0,%1,%2,%3};"
        : "+f"(c[0]), "+f"(c[1]), "+f"(c[2]), "+f"(c[3])
        : "r"(a0), "r"(a1), "r"(a2), "r"(a3), "r"(b0), "r"(b1));
}
__device__ __forceinline__ void ldsm4(uint& r0, uint& r1, uint& r2, uint& r3, uint addr) {
    asm volatile("ldmatrix.sync.aligned.m8n8.x4.shared.b16 {%0,%1,%2,%3}, [%4];"
        : "=r"(r0), "=r"(r1), "=r"(r2), "=r"(r3) : "r"(addr));
}

// warp tile 16x32 via ldmatrix; 16 warps = 4(M) x 4(N); M-tile 64, N 128
template <int NK>
__device__ __forceinline__ void gemm_core_lm(uint sb, int aH, int aL, int wH, int wL,
                                             float acc[4][4], int wm, int wn, int lane) {
    const int l7 = lane & 7, lm = lane >> 3;
    const int radd = (lm & 1) * 8;
    const int koff = (lm >> 1) * 4;
    uint aBh  = sb + ((uint)(aH + (wm + l7 + radd) * WROW + koff) << 2);
    uint aBl  = sb + ((uint)(aL + (wm + l7 + radd) * WROW + koff) << 2);
    uint bBh0 = sb + ((uint)(wH + (wn + l7 + radd) * WROW + koff) << 2);
    uint bBl0 = sb + ((uint)(wL + (wn + l7 + radd) * WROW + koff) << 2);
    uint bBh1 = bBh0 + 16 * WROW * 4;
    uint bBl1 = bBl0 + 16 * WROW * 4;
#pragma unroll
    for (int ks = 0; ks < NK; ks++) {
        uint ko = ks * 32;
        uint ah0, ah1, ah2, ah3, al0, al1, al2, al3;
        ldsm4(ah0, ah1, ah2, ah3, aBh + ko);
        ldsm4(al0, al1, al2, al3, aBl + ko);
        uint p0, p1, p2, p3, q0, q1, q2, q3;
        ldsm4(p0, p1, p2, p3, bBh0 + ko);
        ldsm4(q0, q1, q2, q3, bBh1 + ko);
        uint u0, u1, u2, u3, v0, v1, v2, v3;
        ldsm4(u0, u1, u2, u3, bBl0 + ko);
        ldsm4(v0, v1, v2, v3, bBl1 + ko);
        mma_bf(acc[0], ah0, ah1, ah2, ah3, p0, p2);
        mma_bf(acc[1], ah0, ah1, ah2, ah3, p1, p3);
        mma_bf(acc[2], ah0, ah1, ah2, ah3, q0, q2);
        mma_bf(acc[3], ah0, ah1, ah2, ah3, q1, q3);
        mma_bf(acc[0], ah0, ah1, ah2, ah3, u0, u2);
        mma_bf(acc[1], ah0, ah1, ah2, ah3, u1, u3);
        mma_bf(acc[2], ah0, ah1, ah2, ah3, v0, v2);
        mma_bf(acc[3], ah0, ah1, ah2, ah3, v1, v3);
        mma_bf(acc[0], al0, al1, al2, al3, p0, p2);
        mma_bf(acc[1], al0, al1, al2, al3, p1, p3);
        mma_bf(acc[2], al0, al1, al2, al3, q0, q2);
        mma_bf(acc[3], al0, al1, al2, al3, q1, q3);
    }
}

template <int NK>
__device__ __forceinline__ void load_weights(uint* sm, int dH, int dL,
                                             const u16* Wth, const u16* Wtl, int tid) {
    const int nv = 128 * NK * 2;
    const uint4* sh = (const uint4*)Wth;
    const uint4* sl = (const uint4*)Wtl;
    for (int i = tid; i < nv; i += 512) {
        int n = i / (NK * 2), q = i % (NK * 2);
        *(uint4*)(sm + dH + n * WROW + q * 4) = sh[i];
        *(uint4*)(sm + dL + n * WROW + q * 4) = sl[i];
    }
}

// ---------------- small kernels ----------------
__global__ void deg_kernel(const int* __restrict__ dst, int na, int* __restrict__ deg) {
    int i = blockIdx.x * blockDim.x + threadIdx.x;
    if (i < na) atomicAdd(&deg[dst[i]], 1);
}

struct PJobs {
    const float* W[20];
    int rowoff[20], K[20], off[20], start[20];
    int njobs, total;
};
__global__ void prep_all(PJobs j) {
    int i = blockIdx.x * 256 + threadIdx.x;
    if (i >= j.total) return;
    int a = 0;
    while (a + 1 < j.njobs && i >= j.start[a + 1]) a++;
    int e = i - j.start[a];
    int K = j.K[a];
    int n = e / K, k = e % K;
    float v = j.W[a][(size_t)(j.rowoff[a] + k) * 128 + n];
    __nv_bfloat16 h = __float2bfloat16_rn(v);
    g_wh[j.off[a] + e] = __bfloat16_as_ushort(h);
    g_wl[j.off[a] + e] = __bfloat16_as_ushort(__float2bfloat16_rn(v - __bfloat162float(h)));
}

__global__ void compprep(const float* __restrict__ upd_W1,
                         const float* __restrict__ msg_W2,
                         const float* __restrict__ msg_b2,
                         const float* __restrict__ upd_b1) {
    int b = blockIdx.x;
    if (b < 192) {
        int l = b >> 6;
        int i = (b & 63) * 256 + threadIdx.x;
        int o = i & 127, h = i >> 7;
        const float* W2  = msg_W2 + (size_t)l * 16384;
        const float* U1b = upd_W1 + (size_t)l * 32768 + 16384;
        float s = 0.f;
        for (int a2 = 0; a2 < 128; a2++) s += W2[h * 128 + a2] * U1b[a2 * 128 + o];
        int li = OFF_WC(l) + o * 128 + h;
        __nv_bfloat16 hh = __float2bfloat16_rn(s);
        g_wh[li] = __bfloat16_as_ushort(hh);
        g_wl[li] = __bfloat16_as_ushort(__float2bfloat16_rn(s - __bfloat162float(hh)));
    } else if (b < 195) {
        int l = b - 192;
        int o = threadIdx.x;
        if (o < 128) {
            const float* U1b = upd_W1 + (size_t)l * 32768 + 16384;
            const float* b2  = msg_b2 + (size_t)l * 128;
            float s = upd_b1[l * 128 + o];
            for (int a2 = 0; a2 < 128; a2++) s += b2[a2] * U1b[a2 * 128 + o];
            g_bc[l * 128 + o] = s;
        }
    }
}

// pair hidden aggregation: Hagg[dst] += ReLU(P[dst] + Q[src] + b1)  (P,Q fp16)
__global__ __launch_bounds__(256) void msum(const u16* __restrict__ P,
                                            const u16* __restrict__ Q,
                                            const float* __restrict__ b1,
                                            const int* __restrict__ dst,
                                            const int* __restrict__ src,
                                            float* __restrict__ Hagg, int na) {
    int team = threadIdx.x >> 7, col = threadIdx.x & 127;
    int p0 = blockIdx.x * 128 + team * 64;
    if (p0 >= na) return;
    float bias = __ldg(&b1[col]);
    float sum = 0.f, pv = 0.f;
    int cur = -1;
    for (int base = 0; base < 64; base += 8) {
        int dd[8], ss[8];
#pragma unroll
        for (int j = 0; j < 8; j++) {
            int a = p0 + base + j;
            bool v = a < na;
            dd[j] = v ? __ldg(&dst[a]) : -1;
            ss[j] = v ? __ldg(&src[a]) : 0;
        }
        float qv[8];
#pragma unroll
        for (int j = 0; j < 8; j++)
            qv[j] = __half2float(((const __half*)Q)[(size_t)ss[j] * H + col]);
#pragma unroll
        for (int j = 0; j < 8; j++) {
            if (dd[j] != cur) {
                if (cur >= 0) atomicAdd(&Hagg[(size_t)cur * H + col], sum);
                cur = dd[j];
                sum = 0.f;
                if (cur >= 0)
                    pv = __half2float(((const __half*)P)[(size_t)cur * H + col]) + bias;
            }
            if (dd[j] >= 0) sum += fmaxf(pv + qv[j], 0.f);
        }
    }
    if (cur >= 0) atomicAdd(&Hagg[(size_t)cur * H + col], sum);
}

// ---------------- fused encoder ----------------
__global__ __launch_bounds__(512, 1)
void gk_enc(const float* __restrict__ feat,
            const u16* __restrict__ W1h_, const u16* __restrict__ W1l_,
            const u16* __restrict__ W2h_, const u16* __restrict__ W2l_,
            const float* __restrict__ b1, const float* __restrict__ b2,
            u16* __restrict__ obh, u16* __restrict__ obl,
            int nrows, int ntiles)
{
    extern __shared__ uint sm[];
    const int tid = threadIdx.x;
    const int lane = tid & 31, w = tid >> 5;
    const int wm = (w & 3) * 16, wn = (w >> 2) * 32;
    const uint sb = smem_u32(sm);
    const int HID = D_ABASE + D_ABUF;

    load_weights<4>(sm, D_W1H, D_W1L, W1h_, W1l_, tid);
    load_weights<8>(sm, D_W2H, D_W2L, W2h_, W2l_, tid);

    const int r8 = tid >> 3, c8 = tid & 7;
    const int lg = lane >> 2, lt = lane & 3;

    for (int t = blockIdx.x; t < ntiles; t += gridDim.x) {
        const int t0 = t * 64;
        __syncthreads();
        {
            int gr = t0 + r8;
            int rr = (gr < nrows) ? gr : 0;
            const float4* s = (const float4*)(feat + (size_t)rr * 64) + c8 * 2;
            int base = D_ABASE + r8 * WROW + c8 * 4;
#pragma unroll
            for (int q = 0; q < 2; q++) {
                float4 v = s[q];
                *(uint2*)(sm + base + 2 * q)           = make_uint2(phi(v.x, v.y), phi(v.z, v.w));
                *(uint2*)(sm + base + D_AHALF + 2 * q) = make_uint2(plo(v.x, v.y), plo(v.z, v.w));
            }
        }
        __syncthreads();

        float acc[4][4];
#pragma unroll
        for (int nf = 0; nf < 4; nf++)
#pragma unroll
            for (int q = 0; q < 4; q++) acc[nf][q] = 0.f;
        gemm_core_lm<4>(sb, D_ABASE, D_ABASE + D_AHALF, D_W1H, D_W1L, acc, wm, wn, lane);

#pragma unroll
        for (int nf = 0; nf < 4; nf++) {
            int row = wm + lg;
            int col = wn + nf * 8 + lt * 2;
            float b0 = __ldg(&b1[col]), b1v = __ldg(&b1[col + 1]);
            float v0 = fmaxf(acc[nf][0] + b0, 0.f);
            float v1 = fmaxf(acc[nf][1] + b1v, 0.f);
            float v2 = fmaxf(acc[nf][2] + b0, 0.f);
            float v3 = fmaxf(acc[nf][3] + b1v, 0.f);
            int wi = col >> 1;
            sm[HID + row * WROW + wi]                 = phi(v0, v1);
            sm[HID + D_AHALF + row * WROW + wi]       = plo(v0, v1);
            sm[HID + (row + 8) * WROW + wi]           = phi(v2, v3);
            sm[HID + D_AHALF + (row + 8) * WROW + wi] = plo(v2, v3);
        }
        __syncthreads();

#pragma unroll
        for (int nf = 0; nf < 4; nf++)
#pragma unroll
            for (int q = 0; q < 4; q++) acc[nf][q] = 0.f;
        gemm_core_lm<8>(sb, HID, HID + D_AHALF, D_W2H, D_W2L, acc, wm, wn, lane);

#pragma unroll
        for (int nf = 0; nf < 4; nf++) {
            int row = wm + lg;
            int col = wn + nf * 8 + lt * 2;
            int g0 = t0 + row, g1 = g0 + 8;
            float b0 = __ldg(&b2[col]), b1v = __ldg(&b2[col + 1]);
            float v0 = acc[nf][0] + b0, v1 = acc[nf][1] + b1v;
            float v2 = acc[nf][2] + b0, v3 = acc[nf][3] + b1v;
            int wi = col >> 1;
            if (g0 < nrows) {
                ((uint*)obh)[(size_t)g0 * 64 + wi] = phi(v0, v1);
                ((uint*)obl)[(size_t)g0 * 64 + wi] = plo(v0, v1);
            }
            if (g1 < nrows) {
                ((uint*)obh)[(size_t)g1 * 64 + wi] = phi(v2, v3);
                ((uint*)obl)[(size_t)g1 * 64 + wi] = plo(v2, v3);
            }
        }
    }
}

// ---------------- single GEMM (bf16 in, cp.async double-buffer), bias+ReLU -> bf16 ----------------
__global__ __launch_bounds__(512, 1)
void gk_plain(const u16* __restrict__ Aph, const u16* __restrict__ Apl,
              const u16* __restrict__ Wth, const u16* __restrict__ Wtl,
              const float* __restrict__ bias,
              u16* __restrict__ obh, u16* __restrict__ obl,
              int nrows, int ntiles)
{
    extern __shared__ uint sm[];
    const int tid = threadIdx.x;
    const int lane = tid & 31, w = tid >> 5;
    const int wm = (w & 3) * 16, wn = (w >> 2) * 32;
    const uint sb = smem_u32(sm);

    load_weights<8>(sm, WH_W, WL_W, Wth, Wtl, tid);

    const int r8 = tid >> 3, c8 = tid & 7;

    auto fill_async = [&](int t, int p) {
        int gr = t * 64 + r8;
        int rr = (gr < nrows) ? gr : 0;
        const char* shp = (const char*)(Aph + (size_t)rr * H) + c8 * 16;
        const char* slp = (const char*)(Apl + (size_t)rr * H) + c8 * 16;
        uint dh = sb + (ABASE + p * ABUF + r8 * WROW + c8 * 4) * 4;
        uint dl = dh + AHALF * 4;
        cpa16(dh, shp);        cpa16(dh + 128, shp + 128);
        cpa16(dl, slp);        cpa16(dl + 128, slp + 128);
        CPA_COMMIT();
    };

    int p = 0;
    fill_async(blockIdx.x < ntiles ? blockIdx.x : 0, 0);

    for (int t = blockIdx.x; t < ntiles; t += gridDim.x) {
        __syncthreads();
        int tn = t + gridDim.x;
        fill_async(tn < ntiles ? tn : t, p ^ 1);
        CPA_WAIT(1);
        __syncthreads();

        float acc[4][4];
#pragma unroll
        for (int nf = 0; nf < 4; nf++)
#pragma unroll
            for (int q = 0; q < 4; q++) acc[nf][q] = 0.f;
        int aH = ABASE + p * ABUF;
        gemm_core_lm<8>(sb, aH, aH + AHALF, WH_W, WL_W, acc, wm, wn, lane);

        const int t0 = t * 64;
        const int lg = lane >> 2, lt = lane & 3;
#pragma unroll
        for (int nf = 0; nf < 4; nf++) {
            int row = wm + lg;
            int col = wn + nf * 8 + lt * 2;
            int g0 = t0 + row, g1 = g0 + 8;
            float b0 = __ldg(&bias[col]), b1v = __ldg(&bias[col + 1]);
            float v0 = fmaxf(acc[nf][0] + b0, 0.f);
            float v1 = fmaxf(acc[nf][1] + b1v, 0.f);
            float v2 = fmaxf(acc[nf][2] + b0, 0.f);
            float v3 = fmaxf(acc[nf][3] + b1v, 0.f);
            int wi = col >> 1;
            if (g0 < nrows) {
                ((uint*)obh)[(size_t)g0 * 64 + wi] = phi(v0, v1);
                ((uint*)obl)[(size_t)g0 * 64 + wi] = plo(v0, v1);
            }
            if (g1 < nrows) {
                ((uint*)obh)[(size_t)g1 * 64 + wi] = phi(v2, v3);
                ((uint*)obl)[(size_t)g1 * 64 + wi] = plo(v2, v3);
            }
        }
        p ^= 1;
    }
}

// ---------------- dual GEMM, shared A: out1 = A@W1, out2 = A@W2 -> fp16 ----------------
__global__ __launch_bounds__(512, 1)
void gk_dual(const u16* __restrict__ Aph, const u16* __restrict__ Apl,
             const u16* __restrict__ W1h_, const u16* __restrict__ W1l_,
             const u16* __restrict__ W2h_, const u16* __restrict__ W2l_,
             u16* __restrict__ out1, u16* __restrict__ out2,
             int nrows, int ntiles)
{
    extern __shared__ uint sm[];
    const int tid = threadIdx.x;
    const int lane = tid & 31, w = tid >> 5;
    const int wm = (w & 3) * 16, wn = (w >> 2) * 32;
    const uint sb = smem_u32(sm);

    load_weights<8>(sm, D_W1H, D_W1L, W1h_, W1l_, tid);
    load_weights<8>(sm, D_W2H, D_W2L, W2h_, W2l_, tid);

    const int r8 = tid >> 3, c8 = tid & 7;
    auto fill_async = [&](int t, int p) {
        int gr = t * 64 + r8;
        int rr = (gr < nrows) ? gr : 0;
        const char* shp = (const char*)(Aph + (size_t)rr * H) + c8 * 16;
        const char* slp = (const char*)(Apl + (size_t)rr * H) + c8 * 16;
        uint dh = sb + (D_ABASE + p * D_ABUF + r8 * WROW + c8 * 4) * 4;
        uint dl = dh + D_AHALF * 4;
        cpa16(dh, shp);        cpa16(dh + 128, shp + 128);
        cpa16(dl, slp);        cpa16(dl + 128, slp + 128);
        CPA_COMMIT();
    };

    int p = 0;
    fill_async(blockIdx.x < ntiles ? blockIdx.x : 0, 0);

    for (int t = blockIdx.x; t < ntiles; t += gridDim.x) {
        __syncthreads();
        int tn = t + gridDim.x;
        fill_async(tn < ntiles ? tn : t, p ^ 1);
        CPA_WAIT(1);
        __syncthreads();

        int aH = D_ABASE + p * D_ABUF;
        float acc1[4][4], acc2[4][4];
#pragma unroll
        for (int nf = 0; nf < 4; nf++)
#pragma unroll
            for (int q = 0; q < 4; q++) { acc1[nf][q] = 0.f; acc2[nf][q] = 0.f; }
        gemm_core_lm<8>(sb, aH, aH + D_AHALF, D_W1H, D_W1L, acc1, wm, wn, lane);
        gemm_core_lm<8>(sb, aH, aH + D_AHALF, D_W2H, D_W2L, acc2, wm, wn, lane);

        const int t0 = t * 64;
        const int lg = lane >> 2, lt = lane & 3;
#pragma unroll
        for (int nf = 0; nf < 4; nf++) {
            int row = wm + lg;
            int col = wn + nf * 8 + lt * 2;
            int g0 = t0 + row, g1 = g0 + 8;
            int wi = col >> 1;
            if (g0 < nrows) {
                ((uint*)out1)[(size_t)g0 * 64 + wi] = h2u(acc1[nf][0], acc1[nf][1]);
                ((uint*)out2)[(size_t)g0 * 64 + wi] = h2u(acc2[nf][0], acc2[nf][1]);
            }
            if (g1 < nrows) {
                ((uint*)out1)[(size_t)g1 * 64 + wi] = h2u(acc1[nf][2], acc1[nf][3]);
                ((uint*)out2)[(size_t)g1 * 64 + wi] = h2u(acc2[nf][2], acc2[nf][3]);
            }
        }
        p ^= 1;
    }
}

// ---------------- update fused: hid = ReLU(e@U1T + (Hagg*inv_deg)@WC + bias) -> bf16 ----------------
// deg==0 rows: A2 = ReLU(P+Q+mb1) inline (replaces fixup kernel)
__global__ __launch_bounds__(512, 1)
void gk_upd(const u16* __restrict__ Aph, const u16* __restrict__ Apl,
            const float* __restrict__ Hagg,
            const u16* __restrict__ Pq, const u16* __restrict__ Qq,
            const float* __restrict__ mb1,
            const u16* __restrict__ W1h_, const u16* __restrict__ W1l_,
            const u16* __restrict__ W2h_, const u16* __restrict__ W2l_,
            const float* __restrict__ bias, const int* __restrict__ deg,
            u16* __restrict__ obh, u16* __restrict__ obl,
            int nrows, int ntiles)
{
    extern __shared__ uint sm[];
    const int tid = threadIdx.x;
    const int lane = tid & 31, w = tid >> 5;
    const int wm = (w & 3) * 16, wn = (w >> 2) * 32;
    const uint sb = smem_u32(sm);

    load_weights<8>(sm, D_W1H, D_W1L, W1h_, W1l_, tid);
    load_weights<8>(sm, D_W2H, D_W2L, W2h_, W2l_, tid);

    const int r8 = tid >> 3, c8 = tid & 7;

    for (int t = blockIdx.x; t < ntiles; t += gridDim.x) {
        const int t0 = t * 64;
        int gr = t0 + r8;
        int rr = (gr < nrows) ? gr : 0;
        __syncthreads();
        {   // A1: e via cp.async
            const char* shp = (const char*)(Aph + (size_t)rr * H) + c8 * 16;
            const char* slp = (const char*)(Apl + (size_t)rr * H) + c8 * 16;
            uint dh = sb + (D_ABASE + r8 * WROW + c8 * 4) * 4;
            uint dl = dh + D_AHALF * 4;
            cpa16(dh, shp);        cpa16(dh + 128, shp + 128);
            cpa16(dl, slp);        cpa16(dl + 128, slp + 128);
            CPA_COMMIT();
        }
        {   // A2: Hagg * inv_deg  (or iso: ReLU(P+Q+mb1))
            int d = deg[rr];
            int base = D_ABASE + D_ABUF + r8 * WROW + c8 * 8;
            float vals[16];
            if (d == 0) {
                const uint4* pp = (const uint4*)(Pq + (size_t)rr * H + c8 * 16);
                const uint4* qq = (const uint4*)(Qq + (size_t)rr * H + c8 * 16);
#pragma unroll
                for (int q = 0; q < 2; q++) {
                    uint4 xv = pp[q], yv = qq[q];
                    uint xu[4] = {xv.x, xv.y, xv.z, xv.w};
                    uint yu[4] = {yv.x, yv.y, yv.z, yv.w};
#pragma unroll
                    for (int k = 0; k < 4; k++) {
                        float2 fx = u2f(xu[k]), fy = u2f(yu[k]);
                        int c = c8 * 16 + q * 8 + k * 2;
                        vals[q * 8 + k * 2]     = fmaxf(fx.x + fy.x + __ldg(&mb1[c]),     0.f);
                        vals[q * 8 + k * 2 + 1] = fmaxf(fx.y + fy.y + __ldg(&mb1[c + 1]), 0.f);
                    }
                }
            } else {
                float sc = 1.f / (d > 1 ? (float)d : 1.f);
                const float4* s = (const float4*)(Hagg + (size_t)rr * H) + c8 * 4;
#pragma unroll
                for (int q = 0; q < 4; q++) {
                    float4 v = s[q];
                    vals[4*q] = v.x*sc; vals[4*q+1] = v.y*sc; vals[4*q+2] = v.z*sc; vals[4*q+3] = v.w*sc;
                }
            }
#pragma unroll
            for (int q = 0; q < 4; q++) {
                *(uint2*)(sm + base + 2 * q) =
                    make_uint2(phi(vals[4*q], vals[4*q+1]), phi(vals[4*q+2], vals[4*q+3]));
                *(uint2*)(sm + base + D_AHALF + 2 * q) =
                    make_uint2(plo(vals[4*q], vals[4*q+1]), plo(vals[4*q+2], vals[4*q+3]));
            }
        }
        CPA_WAIT(0);
        __syncthreads();

        float acc[4][4];
#pragma unroll
        for (int nf = 0; nf < 4; nf++)
#pragma unroll
            for (int q = 0; q < 4; q++) acc[nf][q] = 0.f;
        gemm_core_lm<8>(sb, D_ABASE, D_ABASE + D_AHALF, D_W1H, D_W1L, acc, wm, wn, lane);
        gemm_core_lm<8>(sb, D_ABASE + D_ABUF, D_ABASE + D_ABUF + D_AHALF, D_W2H, D_W2L, acc, wm, wn, lane);

        const int lg = lane >> 2, lt = lane & 3;
#pragma unroll
        for (int nf = 0; nf < 4; nf++) {
            int row = wm + lg;
            int col = wn + nf * 8 + lt * 2;
            int g0 = t0 + row, g1 = g0 + 8;
            float b0 = __ldg(&bias[col]), b1v = __ldg(&bias[col + 1]);
            float v0 = fmaxf(acc[nf][0] + b0, 0.f);
            float v1 = fmaxf(acc[nf][1] + b1v, 0.f);
            float v2 = fmaxf(acc[nf][2] + b0, 0.f);
            float v3 = fmaxf(acc[nf][3] + b1v, 0.f);
            int wi = col >> 1;
            if (g0 < nrows) {
                ((uint*)obh)[(size_t)g0 * 64 + wi] = phi(v0, v1);
                ((uint*)obl)[(size_t)g0 * 64 + wi] = plo(v0, v1);
            }
            if (g1 < nrows) {
                ((uint*)obh)[(size_t)g1 * 64 + wi] = phi(v2, v3);
                ((uint*)obl)[(size_t)g1 * 64 + wi] = plo(v2, v3);
            }
        }
    }
}

// ---------------- pairsum GEMM + predictor epilogue (X,Y fp16) ----------------
__global__ __launch_bounds__(512, 1)
void gk_pair(const u16* __restrict__ X, const u16* __restrict__ Y,
             const int* __restrict__ idx0, const int* __restrict__ idx1,
             const u16* __restrict__ Wth, const u16* __restrict__ Wtl,
             const float* __restrict__ b1, const float* __restrict__ b2,
             const float* __restrict__ W3, const float* __restrict__ b3,
             float* __restrict__ pout,
             int nrows, int ntiles, int logit_off)
{
    extern __shared__ uint sm[];
    float* sp = (float*)(sm + CTRL_W);

    const int tid = threadIdx.x;
    const int lane = tid & 31, w = tid >> 5;
    const int wm = (w & 3) * 16, wn = (w >> 2) * 32;
    const uint sb = smem_u32(sm);

    load_weights<8>(sm, WH_W, WL_W, Wth, Wtl, tid);

    const int r8 = tid >> 3, c8 = tid & 7;

    for (int t = blockIdx.x; t < ntiles; t += gridDim.x) {
        const int t0 = t * 64;
        {
            int gr = t0 + r8;
            int rr = (gr < nrows) ? gr : 0;
            int i0 = __ldg(&idx0[rr]);
            int i1 = __ldg(&idx1[rr]);
            int ch = c8 * 16;
            const uint4* xp = (const uint4*)(X + (size_t)i0 * H + ch);
            const uint4* yp = (const uint4*)(Y + (size_t)i1 * H + ch);
            int base = ABASE + r8 * WROW + c8 * 8;
            __syncthreads();
#pragma unroll
            for (int q = 0; q < 2; q++) {
                uint4 xv = xp[q], yv = yp[q];
                uint xu[4] = {xv.x, xv.y, xv.z, xv.w};
                uint yu[4] = {yv.x, yv.y, yv.z, yv.w};
                float v[8];
#pragma unroll
                for (int k = 0; k < 4; k++) {
                    float2 fx = u2f(xu[k]), fy = u2f(yu[k]);
                    int c = ch + q * 8 + k * 2;
                    v[2*k]     = fmaxf(fx.x + fy.x + __ldg(&b1[c]),     0.f);
                    v[2*k + 1] = fmaxf(fx.y + fy.y + __ldg(&b1[c + 1]), 0.f);
                }
#pragma unroll
                for (int k = 0; k < 4; k++) {
                    sm[base + q * 4 + k]         = phi(v[2*k], v[2*k+1]);
                    sm[base + AHALF + q * 4 + k] = plo(v[2*k], v[2*k+1]);
                }
            }
        }
        __syncthreads();

        float acc[4][4];
#pragma unroll
        for (int nf = 0; nf < 4; nf++)
#pragma unroll
            for (int q = 0; q < 4; q++) acc[nf][q] = 0.f;
        gemm_core_lm<8>(sb, ABASE, ABASE + AHALF, WH_W, WL_W, acc, wm, wn, lane);

        const int lg = lane >> 2, lt = lane & 3;
        float p0 = 0.f, p1 = 0.f;
#pragma unroll
        for (int nf = 0; nf < 4; nf++) {
            int col = wn + nf * 8 + lt * 2;
            float b0 = __ldg(&b2[col]), b1v = __ldg(&b2[col + 1]);
            float w30 = __ldg(&W3[col]), w31 = __ldg(&W3[col + 1]);
            p0 += fmaxf(acc[nf][0] + b0, 0.f) * w30
                + fmaxf(acc[nf][1] + b1v, 0.f) * w31;
            p1 += fmaxf(acc[nf][2] + b0, 0.f) * w30
                + fmaxf(acc[nf][3] + b1v, 0.f) * w31;
        }
        p0 += __shfl_xor_sync(0xFFFFFFFFu, p0, 1);
        p0 += __shfl_xor_sync(0xFFFFFFFFu, p0, 2);
        p1 += __shfl_xor_sync(0xFFFFFFFFu, p1, 1);
        p1 += __shfl_xor_sync(0xFFFFFFFFu, p1, 2);
        if (lt == 0) {
            sp[wm + lg +     64 * (wn >> 5)] = p0;
            sp[wm + lg + 8 + 64 * (wn >> 5)] = p1;
        }
        __syncthreads();
        if (tid < 64) {
            int r = t0 + tid;
            if (r < nrows) {
                float s = sp[tid] + sp[tid + 64] + sp[tid + 128] + sp[tid + 192] + __ldg(&b3[0]);
                pout[r] = 1.f / (1.f + expf(-s));
                if (logit_off > 0) pout[logit_off + r] = s;
            }
        }
    }
}

// ---------------- host ----------------
extern "C" void kernel_launch(void* const* d_in, const int* in_sizes, int n_in,
                              void* d_out, int out_size) {
    const float* feat    = (const float*)d_in[0];
    const int*   adj_dst = (const int*)  d_in[1];
    const int*   adj_src = (const int*)  d_in[2];
    const int*   cand_i  = (const int*)  d_in[3];
    const int*   cand_j  = (const int*)  d_in[4];
    const float* enc_W1 = (const float*)d_in[5];
    const float* enc_b1 = (const float*)d_in[6];
    const float* enc_W2 = (const float*)d_in[7];
    const float* enc_b2 = (const float*)d_in[8];
    const float* msg_W1 = (const float*)d_in[9];
    const float* msg_b1 = (const float*)d_in[10];
    const float* msg_W2 = (const float*)d_in[11];
    const float* msg_b2 = (const float*)d_in[12];
    const float* upd_W1 = (const float*)d_in[13];
    const float* upd_b1 = (const float*)d_in[14];
    const float* upd_W2 = (const float*)d_in[15];
    const float* upd_b2 = (const float*)d_in[16];
    const float* pred_W1 = (const float*)d_in[17];
    const float* pred_b1 = (const float*)d_in[18];
    const float* pred_W2 = (const float*)d_in[19];
    const float* pred_b2 = (const float*)d_in[20];
    const float* pred_W3 = (const float*)d_in[21];
    const float* pred_b3 = (const float*)d_in[22];

    int NE = in_sizes[0] / 64;
    int NA = in_sizes[1];
    int NC = in_sizes[3];
    if (NE > NE_MAX) NE = NE_MAX;

    float *Hagg, *bc;
    int* deg;
    u16 *eh, *el, *e2h, *e2l, *hh, *hl, *wh, *wl, *Pq, *Qq;
    cudaGetSymbolAddress((void**)&Pq,   g_Pq);
    cudaGetSymbolAddress((void**)&Qq,   g_Qq);
    cudaGetSymbolAddress((void**)&Hagg, g_agg);
    cudaGetSymbolAddress((void**)&deg,  g_deg);
    cudaGetSymbolAddress((void**)&bc,   g_bc);
    cudaGetSymbolAddress((void**)&eh,   g_eh);
    cudaGetSymbolAddress((void**)&el,   g_el);
    cudaGetSymbolAddress((void**)&e2h,  g_e2h);
    cudaGetSymbolAddress((void**)&e2l,  g_e2l);
    cudaGetSymbolAddress((void**)&hh,   g_hh);
    cudaGetSymbolAddress((void**)&hl,   g_hl);
    cudaGetSymbolAddress((void**)&wh,   g_wh);
    cudaGetSymbolAddress((void**)&wl,   g_wl);

    cudaFuncSetAttribute(gk_enc,   cudaFuncAttributeMaxDynamicSharedMemorySize, D_SMEM_BYTES);
    cudaFuncSetAttribute(gk_plain, cudaFuncAttributeMaxDynamicSharedMemorySize, SMEM_BYTES);
    cudaFuncSetAttribute(gk_dual,  cudaFuncAttributeMaxDynamicSharedMemorySize, D_SMEM_BYTES);
    cudaFuncSetAttribute(gk_upd,   cudaFuncAttributeMaxDynamicSharedMemorySize, D_SMEM_BYTES);
    cudaFuncSetAttribute(gk_pair,  cudaFuncAttributeMaxDynamicSharedMemorySize, SMEM_BYTES);

    cudaMemsetAsync(deg, 0, (size_t)NE * sizeof(int));
    deg_kernel<<<(NA + 255) / 256, 256>>>(adj_dst, NA, deg);

    // ---- weight prep ----
    PJobs pj;
    int cursor = 0, nj = 0;
    auto addjob = [&](const float* W, int ro, int K, int off) {
        pj.W[nj] = W; pj.rowoff[nj] = ro; pj.K[nj] = K; pj.off[nj] = off;
        pj.start[nj] = cursor; cursor += 128 * K; nj++;
    };
    addjob(enc_W1, 0, 64, OFF_ENC1);
    addjob(enc_W2, 0, 128, OFF_ENC2);
    for (int l = 0; l < 3; l++) {
        const float* mW1 = msg_W1 + (size_t)l * 2 * H * H;
        const float* uW1 = upd_W1 + (size_t)l * 2 * H * H;
        const float* uW2 = upd_W2 + (size_t)l * H * H;
        addjob(mW1, 0,   128, OFF_W1T(l));
        addjob(mW1, 128, 128, OFF_W1B(l));
        addjob(uW1, 0,   128, OFF_U1T(l));
        addjob(uW2, 0,   128, OFF_UW2(l));
    }
    addjob(pred_W1, 0,   128, OFF_P1T);
    addjob(pred_W1, 128, 128, OFF_P1B);
    addjob(pred_W2, 0,   128, OFF_P2);
    pj.njobs = nj; pj.total = cursor;
    prep_all<<<(cursor + 255) / 256, 256>>>(pj);
    compprep<<<195, 256>>>(upd_W1, msg_W2, msg_b2, upd_b1);

    int gNE = (NE + 63) / 64;
    int gNC = (NC + 63) / 64;
    int gE = gNE < 148 ? gNE : 148;
    int gC = gNC < 148 ? gNC : 148;

    // fused encoder
    gk_enc<<<gE, 512, D_SMEM_BYTES>>>(
        feat, wh + OFF_ENC1, wl + OFF_ENC1, wh + OFF_ENC2, wl + OFF_ENC2,
        enc_b1, enc_b2, eh, el, NE, gNE);

    u16 *ch = eh, *cl = el, *nh = e2h, *nl = e2l;
    for (int l = 0; l < 3; l++) {
        const float* mb1 = msg_b1 + (size_t)l * H;
        const float* ub2 = upd_b2 + (size_t)l * H;

        gk_dual<<<gE, 512, D_SMEM_BYTES>>>(
            ch, cl, wh + OFF_W1T(l), wl + OFF_W1T(l),
            wh + OFF_W1B(l), wl + OFF_W1B(l), Pq, Qq, NE, gNE);

        cudaMemsetAsync(Hagg, 0, (size_t)NE * H * sizeof(float));
        msum<<<(NA + 127) / 128, 256>>>(Pq, Qq, mb1, adj_dst, adj_src, Hagg, NA);

        gk_upd<<<gE, 512, D_SMEM_BYTES>>>(
            ch, cl, Hagg, Pq, Qq, mb1,
            wh + OFF_U1T(l), wl + OFF_U1T(l), wh + OFF_WC(l), wl + OFF_WC(l),
            bc + l * H, deg, hh, hl, NE, gNE);

        gk_plain<<<gE, 512, SMEM_BYTES>>>(
            hh, hl, wh + OFF_UW2(l), wl + OFF_UW2(l),
            ub2, nh, nl, NE, gNE);

        u16* t1 = ch; ch = nh; nh = t1;
        u16* t2 = cl; cl = nl; nl = t2;
    }

    gk_dual<<<gE, 512, D_SMEM_BYTES>>>(
        ch, cl, wh + OFF_P1T, wl + OFF_P1T,
        wh + OFF_P1B, wl + OFF_P1B, Pq, Qq, NE, gNE);
    int logit_off = (out_size >= 2 * NC) ? NC : -1;
    gk_pair<<<gC, 512, SMEM_BYTES>>>(
        Pq, Qq, cand_i, cand_j, wh + OFF_P2, wl + OFF_P2,
        pred_b1, pred_b2, pred_W3, pred_b3,
        (float*)d_out, NC, gNC, logit_off);
}